// round 13
// baseline (speedup 1.0000x reference)
#include <cuda_runtime.h>
#include <cuda_bf16.h>
#include <cstdint>
#include <math.h>

#define L_  12
#define NH_ 12
#define DH_ 64
#define H_  768
#define FF_ 3072
#define S_  1024
#define B_  4
#define BS_ (B_ * S_)   // 4096
#define WIN_ 256
#define QKVS 2304       // fused qkv row stride

typedef __nv_bfloat16 bf16;

// ---------------- scratch (no allocations allowed) ----------------
__device__ bf16 g_wqkv_hi[L_ * QKVS * H_];
__device__ bf16 g_wqkv_lo[L_ * QKVS * H_];
__device__ bf16 g_wot_hi [L_ * H_ * H_];
__device__ bf16 g_wot_lo [L_ * H_ * H_];
__device__ bf16 g_w1t_hi [L_ * FF_ * H_];
__device__ bf16 g_w1t_lo [L_ * FF_ * H_];
__device__ bf16 g_w2t_hi [L_ * H_ * FF_];
__device__ bf16 g_w2t_lo [L_ * H_ * FF_];
__device__ float g_bqkv  [L_ * QKVS];
__device__ float g_zerob [H_];      // zero-initialized; bias for K-split 1

__device__ float g_h    [BS_ * H_];
__device__ bf16  g_h_hi [BS_ * H_];
__device__ bf16  g_h_lo [BS_ * H_];
__device__ bf16  g_qkvh [BS_ * QKVS];
__device__ bf16  g_qkvl [BS_ * QKVS];
__device__ bf16  g_a_hi [BS_ * H_];
__device__ bf16  g_a_lo [BS_ * H_];
__device__ bf16  g_f_hi [BS_ * FF_];
__device__ bf16  g_f_lo [BS_ * FF_];
__device__ float g_r1   [BS_ * H_];
__device__ float g_r2   [BS_ * H_];
__device__ float g_sc   [BS_];
__device__ float g_pr   [BS_];
__device__ float g_poolp[8 * B_ * H_];

__device__ __forceinline__ void split_bf16(float x, bf16& hi, bf16& lo) {
    hi = __float2bfloat16_rn(x);
    lo = __float2bfloat16_rn(x - __bfloat162float(hi));
}

// ---------------- low-level helpers ----------------
__device__ __forceinline__ void cp_async16(uint32_t smem_addr, const void* gptr) {
    asm volatile("cp.async.cg.shared.global [%0], [%1], 16;\n"
                 :: "r"(smem_addr), "l"(gptr));
}
__device__ __forceinline__ void cp_async_commit() {
    asm volatile("cp.async.commit_group;\n");
}
__device__ __forceinline__ void cp_async_wait0() {
    asm volatile("cp.async.wait_group 0;\n");
}
__device__ __forceinline__ void ldsm_x4(uint32_t& r0, uint32_t& r1, uint32_t& r2,
                                        uint32_t& r3, uint32_t a) {
    asm volatile("ldmatrix.sync.aligned.m8n8.x4.shared.b16 {%0,%1,%2,%3}, [%4];"
                 : "=r"(r0), "=r"(r1), "=r"(r2), "=r"(r3) : "r"(a));
}
__device__ __forceinline__ void ldsm_x4_t(uint32_t& r0, uint32_t& r1, uint32_t& r2,
                                          uint32_t& r3, uint32_t a) {
    asm volatile("ldmatrix.sync.aligned.m8n8.x4.trans.shared.b16 {%0,%1,%2,%3}, [%4];"
                 : "=r"(r0), "=r"(r1), "=r"(r2), "=r"(r3) : "r"(a));
}
__device__ __forceinline__ void mma_bf16(
    float* acc, uint32_t a0, uint32_t a1, uint32_t a2, uint32_t a3,
    uint32_t b0, uint32_t b1)
{
    asm volatile(
        "mma.sync.aligned.m16n8k16.row.col.f32.bf16.bf16.f32 "
        "{%0,%1,%2,%3}, {%4,%5,%6,%7}, {%8,%9}, {%0,%1,%2,%3};\n"
        : "+f"(acc[0]), "+f"(acc[1]), "+f"(acc[2]), "+f"(acc[3])
        : "r"(a0), "r"(a1), "r"(a2), "r"(a3), "r"(b0), "r"(b1));
}
__device__ __forceinline__ void packsplit(float a, float b, uint32_t& ph, uint32_t& pl) {
    bf16 ah = __float2bfloat16_rn(a), bh = __float2bfloat16_rn(b);
    float al = a - __bfloat162float(ah), bl = b - __bfloat162float(bh);
    ph = ((uint32_t)__bfloat16_as_ushort(bh) << 16) | (uint32_t)__bfloat16_as_ushort(ah);
    pl = ((uint32_t)__bfloat16_as_ushort(__float2bfloat16_rn(bl)) << 16)
       |  (uint32_t)__bfloat16_as_ushort(__float2bfloat16_rn(al));
}

// ---------------- reduction helpers ----------------
__device__ __forceinline__ float block_reduce_sum(float v) {
    __shared__ float red[32];
    int lane = threadIdx.x & 31, wid = threadIdx.x >> 5;
    #pragma unroll
    for (int o = 16; o; o >>= 1) v += __shfl_xor_sync(0xffffffffu, v, o);
    if (lane == 0) red[wid] = v;
    __syncthreads();
    int nw = (blockDim.x + 31) >> 5;
    v = (threadIdx.x < nw) ? red[threadIdx.x] : 0.f;
    if (wid == 0) {
        #pragma unroll
        for (int o = 16; o; o >>= 1) v += __shfl_xor_sync(0xffffffffu, v, o);
    }
    if (threadIdx.x == 0) red[0] = v;
    __syncthreads();
    v = red[0];
    __syncthreads();
    return v;
}

__device__ __forceinline__ float2 block_reduce_sum2(float a, float b) {
    __shared__ float2 red[32];
    int lane = threadIdx.x & 31, wid = threadIdx.x >> 5;
    #pragma unroll
    for (int o = 16; o; o >>= 1) {
        a += __shfl_xor_sync(0xffffffffu, a, o);
        b += __shfl_xor_sync(0xffffffffu, b, o);
    }
    if (lane == 0) red[wid] = make_float2(a, b);
    __syncthreads();
    int nw = (blockDim.x + 31) >> 5;
    float2 t = (threadIdx.x < nw) ? red[threadIdx.x] : make_float2(0.f, 0.f);
    if (wid == 0) {
        #pragma unroll
        for (int o = 16; o; o >>= 1) {
            t.x += __shfl_xor_sync(0xffffffffu, t.x, o);
            t.y += __shfl_xor_sync(0xffffffffu, t.y, o);
        }
    }
    if (threadIdx.x == 0) red[0] = t;
    __syncthreads();
    t = red[0];
    __syncthreads();
    return t;
}

__device__ __forceinline__ float block_reduce_max(float v) {
    __shared__ float red[32];
    int lane = threadIdx.x & 31, wid = threadIdx.x >> 5;
    #pragma unroll
    for (int o = 16; o; o >>= 1) v = fmaxf(v, __shfl_xor_sync(0xffffffffu, v, o));
    if (lane == 0) red[wid] = v;
    __syncthreads();
    int nw = (blockDim.x + 31) >> 5;
    v = (threadIdx.x < nw) ? red[threadIdx.x] : -1e30f;
    if (wid == 0) {
        #pragma unroll
        for (int o = 16; o; o >>= 1) v = fmaxf(v, __shfl_xor_sync(0xffffffffu, v, o));
    }
    if (threadIdx.x == 0) red[0] = v;
    __syncthreads();
    v = red[0];
    __syncthreads();
    return v;
}

// ---------------- weight transpose + hi/lo split ----------------
__global__ __launch_bounds__(256) void wsplit_kernel(
    const float* __restrict__ src, bf16* __restrict__ dhi, bf16* __restrict__ dlo,
    int K, int N, size_t srcStride, size_t dstStride)
{
    __shared__ float t[32][33];
    int l = blockIdx.z;
    src += (size_t)l * srcStride;
    dhi += (size_t)l * dstStride;
    dlo += (size_t)l * dstStride;
    int tx = threadIdx.x & 31, ty = threadIdx.x >> 5;
    int n0 = blockIdx.x * 32, k0 = blockIdx.y * 32;
    #pragma unroll
    for (int i = 0; i < 4; i++)
        t[ty + i * 8][tx] = src[(size_t)(k0 + ty + i * 8) * N + n0 + tx];
    __syncthreads();
    #pragma unroll
    for (int i = 0; i < 4; i++) {
        int r = ty + i * 8;
        float x = t[tx][r];
        bf16 hi, lo; split_bf16(x, hi, lo);
        size_t o = (size_t)(n0 + r) * K + k0 + tx;
        dhi[o] = hi; dlo[o] = lo;
    }
}

__global__ __launch_bounds__(256) void wsplit_qkv_kernel(
    const float* __restrict__ Wq, const float* __restrict__ Wk,
    const float* __restrict__ Wv, bf16* __restrict__ dhi, bf16* __restrict__ dlo)
{
    __shared__ float t[32][33];
    int z = blockIdx.z;
    int l = z / 3, j = z % 3;
    const float* src = (j == 0 ? Wq : (j == 1 ? Wk : Wv)) + (size_t)l * H_ * H_;
    bf16* oh = dhi + (size_t)l * QKVS * H_ + (size_t)j * H_ * H_;
    bf16* ol = dlo + (size_t)l * QKVS * H_ + (size_t)j * H_ * H_;
    int tx = threadIdx.x & 31, ty = threadIdx.x >> 5;
    int n0 = blockIdx.x * 32, k0 = blockIdx.y * 32;
    #pragma unroll
    for (int i = 0; i < 4; i++)
        t[ty + i * 8][tx] = src[(size_t)(k0 + ty + i * 8) * H_ + n0 + tx];
    __syncthreads();
    #pragma unroll
    for (int i = 0; i < 4; i++) {
        int r = ty + i * 8;
        float x = t[tx][r];
        bf16 hi, lo; split_bf16(x, hi, lo);
        size_t o = (size_t)(n0 + r) * H_ + k0 + tx;
        oh[o] = hi; ol[o] = lo;
    }
}

// ---------------- embedding + LN (+ fused qkv-bias concat) ----------------
__global__ __launch_bounds__(256) void embed_ln_kernel(
    const float* __restrict__ WE, const float* __restrict__ PE,
    const float* __restrict__ g, const float* __restrict__ be,
    const int* __restrict__ ids,
    float* __restrict__ out, bf16* __restrict__ ohi, bf16* __restrict__ olo,
    const float* __restrict__ bq, const float* __restrict__ bk,
    const float* __restrict__ bv, float* __restrict__ bqkv)
{
    int t = blockIdx.x;
    int tid = threadIdx.x;
    if (t >= BS_) {
        int l = t - BS_;
        for (int n = tid; n < QKVS; n += 256) {
            float v;
            if (n < H_)          v = bq[l * H_ + n];
            else if (n < 2 * H_) v = bk[l * H_ + n - H_];
            else                 v = bv[l * H_ + n - 2 * H_];
            bqkv[l * QKVS + n] = v;
        }
        return;
    }
    int s = t & (S_ - 1);
    int id = ids[t];
    float v[3];
    float s1 = 0.f, s2 = 0.f;
    #pragma unroll
    for (int i = 0; i < 3; i++) {
        int c = tid + i * 256;
        v[i] = WE[(size_t)id * H_ + c] + PE[(size_t)s * H_ + c];
        s1 += v[i]; s2 += v[i] * v[i];
    }
    float2 red = block_reduce_sum2(s1, s2);
    float m = red.x * (1.f / H_);
    float var = red.y * (1.f / H_) - m * m;
    float rs = rsqrtf(var + 1e-5f);
    #pragma unroll
    for (int i = 0; i < 3; i++) {
        int c = tid + i * 256;
        float y = (v[i] - m) * rs * g[c] + be[c];
        size_t o = (size_t)t * H_ + c;
        out[o] = y;
        bf16 hi, lo; split_bf16(y, hi, lo);
        ohi[o] = hi; olo[o] = lo;
    }
}

// ---------------- residual add (two partials) + LN (in-place on h) --------
__global__ __launch_bounds__(256) void add_ln_kernel(
    float* __restrict__ h, const float* __restrict__ r1, const float* __restrict__ r2,
    const float* __restrict__ g, const float* __restrict__ be,
    bf16* __restrict__ ohi, bf16* __restrict__ olo)
{
    int t = blockIdx.x;
    int tid = threadIdx.x;
    float v[3];
    float s1 = 0.f, s2 = 0.f;
    #pragma unroll
    for (int i = 0; i < 3; i++) {
        int c = tid + i * 256;
        size_t o = (size_t)t * H_ + c;
        v[i] = h[o] + r1[o] + r2[o];
        s1 += v[i]; s2 += v[i] * v[i];
    }
    float2 red = block_reduce_sum2(s1, s2);
    float m = red.x * (1.f / H_);
    float var = red.y * (1.f / H_) - m * m;
    float rs = rsqrtf(var + 1e-5f);
    #pragma unroll
    for (int i = 0; i < 3; i++) {
        int c = tid + i * 256;
        float y = (v[i] - m) * rs * g[c] + be[c];
        size_t o = (size_t)t * H_ + c;
        h[o] = y;
        bf16 hi, lo; split_bf16(y, hi, lo);
        ohi[o] = hi; olo[o] = lo;
    }
}

// ================= bf16x3 tensor-core GEMM (ldmatrix, unroll x2) ==========
// A/B pointers may be pre-offset into K (split-K); ldA/ldB are full strides.
// mode 0: fp32 + bias. mode 1: GELU -> bf16 hi/lo. mode 2: qkv bf16 hi/lo
//         with 0.125 folded into cols < H_.
#define PSTR 20
#define STG  (128 * PSTR)
#define GSMEM (8 * STG * 4)

__global__ __launch_bounds__(256) void tgemm_kernel(
    const bf16* __restrict__ Ah, const bf16* __restrict__ Al,
    const bf16* __restrict__ Bh, const bf16* __restrict__ Bl,
    const float* __restrict__ bias,
    float* __restrict__ Cf, bf16* __restrict__ Ch, bf16* __restrict__ Cl,
    int M, int N, int K, int ldA, int ldB, int mode)
{
    extern __shared__ uint32_t smem_u[];

    const int tid  = threadIdx.x;
    const int warp = tid >> 5;
    const int lane = tid & 31;
    const int m0 = blockIdx.y * 128;
    const int n0 = blockIdx.x * 128;
    const int wm = (warp >> 1) * 32;
    const int wn = (warp & 1) * 64;
    const int grp = lane >> 2;
    const int tig = lane & 3;
    const uint32_t smbase = (uint32_t)__cvta_generic_to_shared(smem_u);

    const int aRow = wm + (lane & 7) + ((lane >> 3) & 1) * 8;
    const int aBlk = lane >> 4;
    const int bRow = wn + (lane & 7) + (lane >> 4) * 8;
    const int bBlk = (lane >> 3) & 1;

    float acc[2][8][4];
    #pragma unroll
    for (int mi = 0; mi < 2; mi++)
        #pragma unroll
        for (int ni = 0; ni < 8; ni++)
            #pragma unroll
            for (int c = 0; c < 4; c++) acc[mi][ni][c] = 0.f;

    const int KT = K >> 5;     // KT must be even

    #define LOAD_STAGE(S, k0)                                                          \
    {                                                                                  \
        _Pragma("unroll")                                                              \
        for (int r = 0; r < 2; r++) {                                                  \
            int idx = tid + r * 256;                                                   \
            int row = idx >> 2, c = idx & 3;                                           \
            uint32_t doff = ((S) * 4 * STG + row * PSTR + c * 4) * 4;                  \
            size_t aoff = (size_t)(m0 + row) * ldA + (k0) + c * 8;                     \
            size_t boff = (size_t)(n0 + row) * ldB + (k0) + c * 8;                     \
            cp_async16(smbase + doff,               Ah + aoff);                        \
            cp_async16(smbase + doff + STG * 4,     Al + aoff);                        \
            cp_async16(smbase + doff + 2 * STG * 4, Bh + boff);                        \
            cp_async16(smbase + doff + 3 * STG * 4, Bl + boff);                        \
        }                                                                              \
        cp_async_commit();                                                             \
    }

    #define COMPUTE_STAGE(S)                                                           \
    {                                                                                  \
        const uint32_t sb = smbase + (uint32_t)((S) * 4 * STG) * 4;                    \
        _Pragma("unroll")                                                              \
        for (int st = 0; st < 2; st++) {                                               \
            uint32_t ah_[2][4], al_[2][4];                                             \
            _Pragma("unroll")                                                          \
            for (int mi = 0; mi < 2; mi++) {                                           \
                uint32_t ad = sb + ((aRow + mi * 16) * PSTR) * 4                       \
                            + (st * 2 + aBlk) * 16;                                    \
                ldsm_x4(ah_[mi][0], ah_[mi][1], ah_[mi][2], ah_[mi][3], ad);           \
                ldsm_x4(al_[mi][0], al_[mi][1], al_[mi][2], al_[mi][3],                \
                        ad + STG * 4);                                                 \
            }                                                                          \
            uint32_t bh_[8][2], bl_[8][2];                                             \
            _Pragma("unroll")                                                          \
            for (int t = 0; t < 4; t++) {                                              \
                uint32_t ad = sb + 2 * STG * 4 + ((bRow + t * 16) * PSTR) * 4          \
                            + (st * 2 + bBlk) * 16;                                    \
                ldsm_x4(bh_[2*t][0], bh_[2*t][1], bh_[2*t+1][0], bh_[2*t+1][1], ad);   \
                ldsm_x4(bl_[2*t][0], bl_[2*t][1], bl_[2*t+1][0], bl_[2*t+1][1],        \
                        ad + STG * 4);                                                 \
            }                                                                          \
            _Pragma("unroll")                                                          \
            for (int mi = 0; mi < 2; mi++)                                             \
                _Pragma("unroll")                                                      \
                for (int ni = 0; ni < 8; ni++)                                         \
                    mma_bf16(acc[mi][ni], al_[mi][0], al_[mi][1], al_[mi][2],          \
                             al_[mi][3], bh_[ni][0], bh_[ni][1]);                      \
            _Pragma("unroll")                                                          \
            for (int mi = 0; mi < 2; mi++)                                             \
                _Pragma("unroll")                                                      \
                for (int ni = 0; ni < 8; ni++)                                         \
                    mma_bf16(acc[mi][ni], ah_[mi][0], ah_[mi][1], ah_[mi][2],          \
                             ah_[mi][3], bl_[ni][0], bl_[ni][1]);                      \
            _Pragma("unroll")                                                          \
            for (int mi = 0; mi < 2; mi++)                                             \
                _Pragma("unroll")                                                      \
                for (int ni = 0; ni < 8; ni++)                                         \
                    mma_bf16(acc[mi][ni], ah_[mi][0], ah_[mi][1], ah_[mi][2],          \
                             ah_[mi][3], bh_[ni][0], bh_[ni][1]);                      \
        }                                                                              \
    }

    LOAD_STAGE(0, 0)

    for (int kt = 0; kt < KT; kt += 2) {
        cp_async_wait0();
        __syncthreads();
        if (kt + 1 < KT) LOAD_STAGE(1, (kt + 1) << 5)
        COMPUTE_STAGE(0)

        cp_async_wait0();
        __syncthreads();
        if (kt + 2 < KT) LOAD_STAGE(0, (kt + 2) << 5)
        COMPUTE_STAGE(1)
    }

    // ---- epilogue ----
    #pragma unroll
    for (int mi = 0; mi < 2; mi++) {
        int row0 = m0 + wm + mi * 16 + grp;
        #pragma unroll
        for (int ni = 0; ni < 8; ni++) {
            int col = n0 + wn + ni * 8 + tig * 2;
            float b0 = bias[col], b1 = bias[col + 1];
            float v0 = acc[mi][ni][0] + b0;
            float v1 = acc[mi][ni][1] + b1;
            float v2 = acc[mi][ni][2] + b0;
            float v3 = acc[mi][ni][3] + b1;
            if (mode == 0) {
                *(float2*)(Cf + (size_t)row0 * N + col)       = make_float2(v0, v1);
                *(float2*)(Cf + (size_t)(row0 + 8) * N + col) = make_float2(v2, v3);
            } else {
                if (mode == 1) {
                    v0 = 0.5f * v0 * (1.0f + erff(v0 * 0.70710678118654752f));
                    v1 = 0.5f * v1 * (1.0f + erff(v1 * 0.70710678118654752f));
                    v2 = 0.5f * v2 * (1.0f + erff(v2 * 0.70710678118654752f));
                    v3 = 0.5f * v3 * (1.0f + erff(v3 * 0.70710678118654752f));
                } else {
                    float scq = (col < H_) ? 0.125f : 1.f;
                    v0 *= scq; v1 *= scq; v2 *= scq; v3 *= scq;
                }
                size_t o0 = (size_t)row0 * N + col;
                size_t o1 = (size_t)(row0 + 8) * N + col;
                uint32_t ph, pl;
                packsplit(v0, v1, ph, pl);
                *(uint32_t*)(Ch + o0) = ph; *(uint32_t*)(Cl + o0) = pl;
                packsplit(v2, v3, ph, pl);
                *(uint32_t*)(Ch + o1) = ph; *(uint32_t*)(Cl + o1) = pl;
            }
        }
    }
}

// ================= tensor-core local attention (mma.sync) =================
#define QSTR 36
#define ATT_SMEM ((2 * 128 * QSTR + 4 * 64 * QSTR + 64) * 4)

__global__ __launch_bounds__(256, 1) void attn_tc_kernel(
    const bf16* __restrict__ Qh, const bf16* __restrict__ Ql,
    const int* __restrict__ amask,
    bf16* __restrict__ Ohi, bf16* __restrict__ Olo)
{
    extern __shared__ uint32_t sm[];
    const int OQH = 0;
    const int OQL = OQH + 128 * QSTR;
    const int OKH = OQL + 128 * QSTR;
    const int OKL = OKH + 64 * QSTR;
    const int OVH = OKL + 64 * QSTR;
    const int OVL = OVH + 64 * QSTR;
    const int OMF = OVL + 64 * QSTR;
    float* mf = (float*)(sm + OMF);

    const int q0 = blockIdx.x * 128;
    const int hh = blockIdx.y;
    const int b  = blockIdx.z;
    const int tid = threadIdx.x, warp = tid >> 5, lane = tid & 31;
    const int grp = lane >> 2, tig = lane & 3;
    const uint32_t base = (uint32_t)__cvta_generic_to_shared(sm);
    const unsigned FULL = 0xffffffffu;

    for (int idx = tid; idx < 128 * 8; idx += 256) {
        int r = idx >> 3, q4 = idx & 7;
        size_t off = (size_t)(b * S_ + q0 + r) * QKVS + hh * DH_;
        ((uint4*)(sm + OQH + r * QSTR))[q4] = ((const uint4*)(Qh + off))[q4];
        ((uint4*)(sm + OQL + r * QSTR))[q4] = ((const uint4*)(Ql + off))[q4];
    }
    __syncthreads();

    uint32_t qfh[4][4], qfl[4][4];
    {
        int arow = warp * 16 + (lane & 7) + ((lane >> 3) & 1) * 8;
        int ablk = lane >> 4;
        #pragma unroll
        for (int st = 0; st < 4; st++) {
            uint32_t ad = base + (OQH + arow * QSTR) * 4 + (st * 2 + ablk) * 16;
            ldsm_x4(qfh[st][0], qfh[st][1], qfh[st][2], qfh[st][3], ad);
            ldsm_x4(qfl[st][0], qfl[st][1], qfl[st][2], qfl[st][3],
                    ad + (OQL - OQH) * 4);
        }
    }

    float o[8][4];
    #pragma unroll
    for (int ni = 0; ni < 8; ni++)
        #pragma unroll
        for (int c = 0; c < 4; c++) o[ni][c] = 0.f;
    float m0 = -1e30f, m1 = -1e30f, l0 = 0.f, l1 = 0.f;

    const int brow = (lane & 7) + (lane >> 4) * 8;
    const int bblk = (lane >> 3) & 1;
    const int vrow = (lane & 7) + ((lane >> 3) & 1) * 8;
    const int vblk = lane >> 4;
    const int qg0 = q0 + warp * 16 + grp;
    const int qg1 = qg0 + 8;

    for (int kt = 0; kt < 10; kt++) {
        const int ks = q0 - 256 + kt * 64;
        if (ks + 64 <= 0 || ks >= S_) continue;
        __syncthreads();
        const uint4 z4 = make_uint4(0u, 0u, 0u, 0u);
        for (int idx = tid; idx < 64 * 8; idx += 256) {
            int c = idx >> 3, q4 = idx & 7;
            int kg = ks + c;
            uint4 kh = z4, kl = z4, vh = z4, vl = z4;
            if (kg >= 0 && kg < S_) {
                size_t off = (size_t)(b * S_ + kg) * QKVS + hh * DH_;
                kh = ((const uint4*)(Qh + off + H_))[q4];
                kl = ((const uint4*)(Ql + off + H_))[q4];
                vh = ((const uint4*)(Qh + off + 2 * H_))[q4];
                vl = ((const uint4*)(Ql + off + 2 * H_))[q4];
            }
            ((uint4*)(sm + OKH + c * QSTR))[q4] = kh;
            ((uint4*)(sm + OKL + c * QSTR))[q4] = kl;
            ((uint4*)(sm + OVH + c * QSTR))[q4] = vh;
            ((uint4*)(sm + OVL + c * QSTR))[q4] = vl;
        }
        if (tid < 64) {
            int kg = ks + tid;
            mf[tid] = (kg >= 0 && kg < S_ && amask[b * S_ + kg] > 0) ? 0.f : -1e9f;
        }
        __syncthreads();

        float s[8][4];
        #pragma unroll
        for (int ni = 0; ni < 8; ni++)
            #pragma unroll
            for (int c = 0; c < 4; c++) s[ni][c] = 0.f;
        #pragma unroll
        for (int st = 0; st < 4; st++) {
            uint32_t kbh[8][2], kbl[8][2];
            #pragma unroll
            for (int t = 0; t < 4; t++) {
                uint32_t ad = base + (OKH + (t * 16 + brow) * QSTR) * 4
                            + (st * 2 + bblk) * 16;
                ldsm_x4(kbh[2*t][0], kbh[2*t][1], kbh[2*t+1][0], kbh[2*t+1][1], ad);
                ldsm_x4(kbl[2*t][0], kbl[2*t][1], kbl[2*t+1][0], kbl[2*t+1][1],
                        ad + (OKL - OKH) * 4);
            }
            #pragma unroll
            for (int ni = 0; ni < 8; ni++)
                mma_bf16(s[ni], qfl[st][0], qfl[st][1], qfl[st][2], qfl[st][3],
                         kbh[ni][0], kbh[ni][1]);
            #pragma unroll
            for (int ni = 0; ni < 8; ni++)
                mma_bf16(s[ni], qfh[st][0], qfh[st][1], qfh[st][2], qfh[st][3],
                         kbl[ni][0], kbl[ni][1]);
            #pragma unroll
            for (int ni = 0; ni < 8; ni++)
                mma_bf16(s[ni], qfh[st][0], qfh[st][1], qfh[st][2], qfh[st][3],
                         kbh[ni][0], kbh[ni][1]);
        }

        float tmax0 = -1e30f, tmax1 = -1e30f;
        #pragma unroll
        for (int ni = 0; ni < 8; ni++) {
            int kl0 = ni * 8 + 2 * tig;
            float mv0 = mf[kl0], mv1 = mf[kl0 + 1];
            int kg0 = ks + kl0;
            int d00 = kg0 - qg0, d01 = d00 + 1;
            int d10 = kg0 - qg1, d11 = d10 + 1;
            float x0 = (d00 >= -WIN_ && d00 <= WIN_) ? s[ni][0] + mv0 : -1e9f;
            float x1 = (d01 >= -WIN_ && d01 <= WIN_) ? s[ni][1] + mv1 : -1e9f;
            float x2 = (d10 >= -WIN_ && d10 <= WIN_) ? s[ni][2] + mv0 : -1e9f;
            float x3 = (d11 >= -WIN_ && d11 <= WIN_) ? s[ni][3] + mv1 : -1e9f;
            s[ni][0] = x0; s[ni][1] = x1; s[ni][2] = x2; s[ni][3] = x3;
            tmax0 = fmaxf(tmax0, fmaxf(x0, x1));
            tmax1 = fmaxf(tmax1, fmaxf(x2, x3));
        }
        tmax0 = fmaxf(tmax0, __shfl_xor_sync(FULL, tmax0, 1));
        tmax0 = fmaxf(tmax0, __shfl_xor_sync(FULL, tmax0, 2));
        tmax1 = fmaxf(tmax1, __shfl_xor_sync(FULL, tmax1, 1));
        tmax1 = fmaxf(tmax1, __shfl_xor_sync(FULL, tmax1, 2));
        float mn0 = fmaxf(m0, tmax0), mn1 = fmaxf(m1, tmax1);
        float sc0 = __expf(m0 - mn0), sc1 = __expf(m1 - mn1);
        float ps0 = 0.f, ps1 = 0.f;
        #pragma unroll
        for (int ni = 0; ni < 8; ni++) {
            s[ni][0] = __expf(s[ni][0] - mn0);
            s[ni][1] = __expf(s[ni][1] - mn0);
            s[ni][2] = __expf(s[ni][2] - mn1);
            s[ni][3] = __expf(s[ni][3] - mn1);
            ps0 += s[ni][0] + s[ni][1];
            ps1 += s[ni][2] + s[ni][3];
        }
        ps0 += __shfl_xor_sync(FULL, ps0, 1);
        ps0 += __shfl_xor_sync(FULL, ps0, 2);
        ps1 += __shfl_xor_sync(FULL, ps1, 1);
        ps1 += __shfl_xor_sync(FULL, ps1, 2);
        l0 = l0 * sc0 + ps0;
        l1 = l1 * sc1 + ps1;
        m0 = mn0; m1 = mn1;
        #pragma unroll
        for (int ni = 0; ni < 8; ni++) {
            o[ni][0] *= sc0; o[ni][1] *= sc0;
            o[ni][2] *= sc1; o[ni][3] *= sc1;
        }

        uint32_t pah[4][4], pal[4][4];
        #pragma unroll
        for (int j = 0; j < 4; j++) {
            packsplit(s[2*j][0],   s[2*j][1],   pah[j][0], pal[j][0]);
            packsplit(s[2*j][2],   s[2*j][3],   pah[j][1], pal[j][1]);
            packsplit(s[2*j+1][0], s[2*j+1][1], pah[j][2], pal[j][2]);
            packsplit(s[2*j+1][2], s[2*j+1][3], pah[j][3], pal[j][3]);
        }

        #pragma unroll
        for (int j = 0; j < 4; j++) {
            uint32_t vbh[8][2], vbl[8][2];
            #pragma unroll
            for (int t = 0; t < 4; t++) {
                uint32_t ad = base + (OVH + (j * 16 + vrow) * QSTR) * 4
                            + (2 * t + vblk) * 16;
                ldsm_x4_t(vbh[2*t][0], vbh[2*t][1], vbh[2*t+1][0], vbh[2*t+1][1], ad);
                ldsm_x4_t(vbl[2*t][0], vbl[2*t][1], vbl[2*t+1][0], vbl[2*t+1][1],
                          ad + (OVL - OVH) * 4);
            }
            #pragma unroll
            for (int ni = 0; ni < 8; ni++)
                mma_bf16(o[ni], pal[j][0], pal[j][1], pal[j][2], pal[j][3],
                         vbh[ni][0], vbh[ni][1]);
            #pragma unroll
            for (int ni = 0; ni < 8; ni++)
                mma_bf16(o[ni], pah[j][0], pah[j][1], pah[j][2], pah[j][3],
                         vbl[ni][0], vbl[ni][1]);
            #pragma unroll
            for (int ni = 0; ni < 8; ni++)
                mma_bf16(o[ni], pah[j][0], pah[j][1], pah[j][2], pah[j][3],
                         vbh[ni][0], vbh[ni][1]);
        }
    }

    float inv0 = 1.f / l0, inv1 = 1.f / l1;
    #pragma unroll
    for (int ni = 0; ni < 8; ni++) {
        int dcol = hh * DH_ + ni * 8 + 2 * tig;
        size_t o0 = (size_t)(b * S_ + qg0) * H_ + dcol;
        size_t o1 = (size_t)(b * S_ + qg1) * H_ + dcol;
        uint32_t ph, pl;
        packsplit(o[ni][0] * inv0, o[ni][1] * inv0, ph, pl);
        *(uint32_t*)(Ohi + o0) = ph;
        *(uint32_t*)(Olo + o0) = pl;
        packsplit(o[ni][2] * inv1, o[ni][3] * inv1, ph, pl);
        *(uint32_t*)(Ohi + o1) = ph;
        *(uint32_t*)(Olo + o1) = pl;
    }
}

// ---------------- pooling head ----------------
__global__ __launch_bounds__(256) void attn_score_kernel(
    const float* __restrict__ h, const float* __restrict__ aw, float* __restrict__ sc)
{
    int t = blockIdx.x;
    int tid = threadIdx.x;
    float acc = 0.f;
    #pragma unroll
    for (int i = 0; i < 3; i++) {
        int c = tid + i * 256;
        acc += h[(size_t)t * H_ + c] * aw[c];
    }
    float s = block_reduce_sum(acc);
    if (tid == 0) sc[t] = s;
}

__global__ __launch_bounds__(256) void softmax_s_kernel(
    const float* __restrict__ sc, float* __restrict__ pr)
{
    int b = blockIdx.x;
    int tid = threadIdx.x;
    float v[4];
    float mx = -1e30f;
    #pragma unroll
    for (int i = 0; i < 4; i++) {
        v[i] = sc[b * S_ + tid + i * 256];
        mx = fmaxf(mx, v[i]);
    }
    mx = block_reduce_max(mx);
    float e[4], ps = 0.f;
    #pragma unroll
    for (int i = 0; i < 4; i++) { e[i] = __expf(v[i] - mx); ps += e[i]; }
    float tot = block_reduce_sum(ps);
    float inv = 1.f / tot;
    #pragma unroll
    for (int i = 0; i < 4; i++) pr[b * S_ + tid + i * 256] = e[i] * inv;
}

__global__ __launch_bounds__(256) void pool_kernel(
    const float* __restrict__ h, const float* __restrict__ pr, float* __restrict__ poolp)
{
    int d = blockIdx.x * 256 + threadIdx.x;
    int b = blockIdx.y;
    int p = blockIdx.z;
    float acc = 0.f;
    int s0 = p * (S_ / 8);
    for (int s = s0; s < s0 + S_ / 8; s++) {
        acc += h[((size_t)(b * S_ + s)) * H_ + d] * pr[b * S_ + s];
    }
    poolp[((size_t)p * B_ + b) * H_ + d] = acc;
}

__global__ __launch_bounds__(256) void final_kernel(
    const float* __restrict__ poolp, const float* __restrict__ Wc,
    const float* __restrict__ bc, float* __restrict__ out)
{
    int b = blockIdx.x;
    int tid = threadIdx.x;
    float acc = 0.f;
    #pragma unroll
    for (int i = 0; i < 3; i++) {
        int c = tid + i * 256;
        float pv = 0.f;
        #pragma unroll
        for (int p = 0; p < 8; p++)
            pv += poolp[((size_t)p * B_ + b) * H_ + c];
        acc += pv * Wc[c];
    }
    float s = block_reduce_sum(acc);
    if (tid == 0) out[b] = s + bc[0];
}

// ---------------- host launcher ----------------
extern "C" void kernel_launch(void* const* d_in, const int* in_sizes, int n_in,
                              void* d_out, int out_size)
{
    (void)in_sizes; (void)n_in; (void)out_size;
    const float* WE   = (const float*)d_in[0];
    const float* PE   = (const float*)d_in[1];
    const float* Eg   = (const float*)d_in[2];
    const float* Eb   = (const float*)d_in[3];
    const float* Wq   = (const float*)d_in[4];
    const float* bq   = (const float*)d_in[5];
    const float* Wk   = (const float*)d_in[6];
    const float* bk   = (const float*)d_in[7];
    const float* Wv   = (const float*)d_in[8];
    const float* bv   = (const float*)d_in[9];
    const float* Wo   = (const float*)d_in[10];
    const float* bo   = (const float*)d_in[11];
    const float* g1   = (const float*)d_in[12];
    const float* beta1= (const float*)d_in[13];
    const float* W1   = (const float*)d_in[14];
    const float* b1   = (const float*)d_in[15];
    const float* W2   = (const float*)d_in[16];
    const float* b2   = (const float*)d_in[17];
    const float* g2   = (const float*)d_in[18];
    const float* beta2= (const float*)d_in[19];
    const float* aw   = (const float*)d_in[20];
    const float* Wc   = (const float*)d_in[21];
    const float* bc   = (const float*)d_in[22];
    const int*   ids  = (const int*)d_in[23];
    const int*   am   = (const int*)d_in[24];
    float* out = (float*)d_out;

    bf16 *wqkv_hi, *wqkv_lo, *wot_hi, *wot_lo, *w1t_hi, *w1t_lo, *w2t_hi, *w2t_lo;
    bf16 *h_hi, *h_lo, *a_hi, *a_lo, *f_hi, *f_lo, *qkvh, *qkvl;
    float *bqkv, *zerob, *h, *r1, *r2, *sc, *pr, *poolp;
    cudaGetSymbolAddress((void**)&wqkv_hi, g_wqkv_hi);
    cudaGetSymbolAddress((void**)&wqkv_lo, g_wqkv_lo);
    cudaGetSymbolAddress((void**)&wot_hi,  g_wot_hi);
    cudaGetSymbolAddress((void**)&wot_lo,  g_wot_lo);
    cudaGetSymbolAddress((void**)&w1t_hi,  g_w1t_hi);
    cudaGetSymbolAddress((void**)&w1t_lo,  g_w1t_lo);
    cudaGetSymbolAddress((void**)&w2t_hi,  g_w2t_hi);
    cudaGetSymbolAddress((void**)&w2t_lo,  g_w2t_lo);
    cudaGetSymbolAddress((void**)&bqkv,    g_bqkv);
    cudaGetSymbolAddress((void**)&zerob,   g_zerob);
    cudaGetSymbolAddress((void**)&h,       g_h);
    cudaGetSymbolAddress((void**)&h_hi,    g_h_hi);
    cudaGetSymbolAddress((void**)&h_lo,    g_h_lo);
    cudaGetSymbolAddress((void**)&qkvh,    g_qkvh);
    cudaGetSymbolAddress((void**)&qkvl,    g_qkvl);
    cudaGetSymbolAddress((void**)&a_hi,    g_a_hi);
    cudaGetSymbolAddress((void**)&a_lo,    g_a_lo);
    cudaGetSymbolAddress((void**)&f_hi,    g_f_hi);
    cudaGetSymbolAddress((void**)&f_lo,    g_f_lo);
    cudaGetSymbolAddress((void**)&r1,      g_r1);
    cudaGetSymbolAddress((void**)&r2,      g_r2);
    cudaGetSymbolAddress((void**)&sc,      g_sc);
    cudaGetSymbolAddress((void**)&pr,      g_pr);
    cudaGetSymbolAddress((void**)&poolp,   g_poolp);

    cudaFuncSetAttribute(tgemm_kernel,
                         cudaFuncAttributeMaxDynamicSharedMemorySize, GSMEM);
    cudaFuncSetAttribute(attn_tc_kernel,
                         cudaFuncAttributeMaxDynamicSharedMemorySize, ATT_SMEM);

    // ---- pre-pass (reordered: QKV GEMM is my launch idx 3 for ncu) ----
    dim3 wb(256);
    wsplit_qkv_kernel<<<dim3(H_ / 32, H_ / 32, 3 * L_), wb>>>(Wq, Wk, Wv,
                                                              wqkv_hi, wqkv_lo);
    embed_ln_kernel<<<BS_ + L_, 256>>>(WE, PE, Eg, Eb, ids, h, h_hi, h_lo,
                                       bq, bk, bv, bqkv);
    wsplit_kernel<<<dim3(H_ / 32, H_ / 32, L_), wb>>>(Wo, wot_hi, wot_lo, H_, H_,
        (size_t)H_ * H_, (size_t)H_ * H_);

    dim3 gQKV(QKVS / 128, BS_ / 128);
    dim3 gO(H_ / 128, BS_ / 128);
    dim3 gW1(FF_ / 128, BS_ / 128);
    dim3 gattn(S_ / 128, NH_, B_);

    // layer 0 QKV GEMM first (launch idx 3), remaining wsplits after it
    tgemm_kernel<<<gQKV, 256, GSMEM>>>(h_hi, h_lo,
        wqkv_hi, wqkv_lo, bqkv, nullptr, qkvh, qkvl,
        BS_, QKVS, H_, H_, H_, 2);
    wsplit_kernel<<<dim3(FF_ / 32, H_ / 32, L_), wb>>>(W1, w1t_hi, w1t_lo, H_, FF_,
        (size_t)H_ * FF_, (size_t)FF_ * H_);
    wsplit_kernel<<<dim3(H_ / 32, FF_ / 32, L_), wb>>>(W2, w2t_hi, w2t_lo, FF_, H_,
        (size_t)FF_ * H_, (size_t)H_ * FF_);

    for (int l = 0; l < L_; l++) {
        if (l > 0) {
            tgemm_kernel<<<gQKV, 256, GSMEM>>>(h_hi, h_lo,
                wqkv_hi + (size_t)l * QKVS * H_, wqkv_lo + (size_t)l * QKVS * H_,
                bqkv + l * QKVS, nullptr, qkvh, qkvl, BS_, QKVS, H_, H_, H_, 2);
        }

        attn_tc_kernel<<<gattn, 256, ATT_SMEM>>>(qkvh, qkvl, am, a_hi, a_lo);

        // attn-out projection, split-K=2 (K=768 -> 2x384)
        {
            const bf16* Bh = wot_hi + (size_t)l * H_ * H_;
            const bf16* Bl = wot_lo + (size_t)l * H_ * H_;
            tgemm_kernel<<<gO, 256, GSMEM>>>(a_hi, a_lo, Bh, Bl,
                bo + l * H_, r1, nullptr, nullptr, BS_, H_, 384, H_, H_, 0);
            tgemm_kernel<<<gO, 256, GSMEM>>>(a_hi + 384, a_lo + 384,
                Bh + 384, Bl + 384,
                zerob, r2, nullptr, nullptr, BS_, H_, 384, H_, H_, 0);
        }
        add_ln_kernel<<<BS_, 256>>>(h, r1, r2, g1 + l * H_, beta1 + l * H_,
                                    h_hi, h_lo);

        tgemm_kernel<<<gW1, 256, GSMEM>>>(h_hi, h_lo,
            w1t_hi + (size_t)l * FF_ * H_, w1t_lo + (size_t)l * FF_ * H_,
            b1 + l * FF_, nullptr, f_hi, f_lo, BS_, FF_, H_, H_, H_, 1);

        // FFN down projection, split-K=2 (K=3072 -> 2x1536)
        {
            const bf16* Bh = w2t_hi + (size_t)l * H_ * FF_;
            const bf16* Bl = w2t_lo + (size_t)l * H_ * FF_;
            tgemm_kernel<<<gO, 256, GSMEM>>>(f_hi, f_lo, Bh, Bl,
                b2 + l * H_, r1, nullptr, nullptr, BS_, H_, 1536, FF_, FF_, 0);
            tgemm_kernel<<<gO, 256, GSMEM>>>(f_hi + 1536, f_lo + 1536,
                Bh + 1536, Bl + 1536,
                zerob, r2, nullptr, nullptr, BS_, H_, 1536, FF_, FF_, 0);
        }
        add_ln_kernel<<<BS_, 256>>>(h, r1, r2, g2 + l * H_, beta2 + l * H_,
                                    h_hi, h_lo);
    }

    attn_score_kernel<<<BS_, 256>>>(h, aw, sc);
    softmax_s_kernel<<<B_, 256>>>(sc, pr);
    pool_kernel<<<dim3(H_ / 256, B_, 8), 256>>>(h, pr, poolp);
    final_kernel<<<B_, 256>>>(poolp, Wc, bc, out);
}

// round 14
// speedup vs baseline: 1.0091x; 1.0091x over previous
#include <cuda_runtime.h>
#include <cuda_bf16.h>
#include <cstdint>
#include <math.h>

#define L_  12
#define NH_ 12
#define DH_ 64
#define H_  768
#define FF_ 3072
#define S_  1024
#define B_  4
#define BS_ (B_ * S_)   // 4096
#define WIN_ 256
#define QKVS 2304       // fused qkv row stride

typedef __nv_bfloat16 bf16;

// ---------------- scratch (no allocations allowed) ----------------
__device__ bf16 g_wqkv_hi[L_ * QKVS * H_];
__device__ bf16 g_wqkv_lo[L_ * QKVS * H_];
__device__ bf16 g_wot_hi [L_ * H_ * H_];
__device__ bf16 g_wot_lo [L_ * H_ * H_];
__device__ bf16 g_w1t_hi [L_ * FF_ * H_];
__device__ bf16 g_w1t_lo [L_ * FF_ * H_];
__device__ bf16 g_w2t_hi [L_ * H_ * FF_];
__device__ bf16 g_w2t_lo [L_ * H_ * FF_];
__device__ float g_bqkv  [L_ * QKVS];

__device__ float g_h    [BS_ * H_];
__device__ bf16  g_h_hi [BS_ * H_];
__device__ bf16  g_h_lo [BS_ * H_];
__device__ bf16  g_qkvh [BS_ * QKVS];
__device__ bf16  g_qkvl [BS_ * QKVS];
__device__ bf16  g_a_hi [BS_ * H_];
__device__ bf16  g_a_lo [BS_ * H_];
__device__ bf16  g_f_hi [BS_ * FF_];
__device__ bf16  g_f_lo [BS_ * FF_];
__device__ float g_r    [BS_ * H_];
__device__ float g_sc   [BS_];
__device__ float g_pr   [BS_];
__device__ float g_poolp[8 * B_ * H_];

__device__ __forceinline__ void split_bf16(float x, bf16& hi, bf16& lo) {
    hi = __float2bfloat16_rn(x);
    lo = __float2bfloat16_rn(x - __bfloat162float(hi));
}

// ---------------- low-level helpers ----------------
__device__ __forceinline__ void cp_async16(uint32_t smem_addr, const void* gptr) {
    asm volatile("cp.async.cg.shared.global [%0], [%1], 16;\n"
                 :: "r"(smem_addr), "l"(gptr));
}
__device__ __forceinline__ void cp_async_commit() {
    asm volatile("cp.async.commit_group;\n");
}
__device__ __forceinline__ void cp_async_wait0() {
    asm volatile("cp.async.wait_group 0;\n");
}
__device__ __forceinline__ void ldsm_x4(uint32_t& r0, uint32_t& r1, uint32_t& r2,
                                        uint32_t& r3, uint32_t a) {
    asm volatile("ldmatrix.sync.aligned.m8n8.x4.shared.b16 {%0,%1,%2,%3}, [%4];"
                 : "=r"(r0), "=r"(r1), "=r"(r2), "=r"(r3) : "r"(a));
}
__device__ __forceinline__ void ldsm_x4_t(uint32_t& r0, uint32_t& r1, uint32_t& r2,
                                          uint32_t& r3, uint32_t a) {
    asm volatile("ldmatrix.sync.aligned.m8n8.x4.trans.shared.b16 {%0,%1,%2,%3}, [%4];"
                 : "=r"(r0), "=r"(r1), "=r"(r2), "=r"(r3) : "r"(a));
}
__device__ __forceinline__ void mma_bf16(
    float* acc, uint32_t a0, uint32_t a1, uint32_t a2, uint32_t a3,
    uint32_t b0, uint32_t b1)
{
    asm volatile(
        "mma.sync.aligned.m16n8k16.row.col.f32.bf16.bf16.f32 "
        "{%0,%1,%2,%3}, {%4,%5,%6,%7}, {%8,%9}, {%0,%1,%2,%3};\n"
        : "+f"(acc[0]), "+f"(acc[1]), "+f"(acc[2]), "+f"(acc[3])
        : "r"(a0), "r"(a1), "r"(a2), "r"(a3), "r"(b0), "r"(b1));
}
__device__ __forceinline__ void packsplit(float a, float b, uint32_t& ph, uint32_t& pl) {
    bf16 ah = __float2bfloat16_rn(a), bh = __float2bfloat16_rn(b);
    float al = a - __bfloat162float(ah), bl = b - __bfloat162float(bh);
    ph = ((uint32_t)__bfloat16_as_ushort(bh) << 16) | (uint32_t)__bfloat16_as_ushort(ah);
    pl = ((uint32_t)__bfloat16_as_ushort(__float2bfloat16_rn(bl)) << 16)
       |  (uint32_t)__bfloat16_as_ushort(__float2bfloat16_rn(al));
}

// ---------------- reduction helpers ----------------
__device__ __forceinline__ float block_reduce_sum(float v) {
    __shared__ float red[32];
    int lane = threadIdx.x & 31, wid = threadIdx.x >> 5;
    #pragma unroll
    for (int o = 16; o; o >>= 1) v += __shfl_xor_sync(0xffffffffu, v, o);
    if (lane == 0) red[wid] = v;
    __syncthreads();
    int nw = (blockDim.x + 31) >> 5;
    v = (threadIdx.x < nw) ? red[threadIdx.x] : 0.f;
    if (wid == 0) {
        #pragma unroll
        for (int o = 16; o; o >>= 1) v += __shfl_xor_sync(0xffffffffu, v, o);
    }
    if (threadIdx.x == 0) red[0] = v;
    __syncthreads();
    v = red[0];
    __syncthreads();
    return v;
}

__device__ __forceinline__ float2 block_reduce_sum2(float a, float b) {
    __shared__ float2 red[32];
    int lane = threadIdx.x & 31, wid = threadIdx.x >> 5;
    #pragma unroll
    for (int o = 16; o; o >>= 1) {
        a += __shfl_xor_sync(0xffffffffu, a, o);
        b += __shfl_xor_sync(0xffffffffu, b, o);
    }
    if (lane == 0) red[wid] = make_float2(a, b);
    __syncthreads();
    int nw = (blockDim.x + 31) >> 5;
    float2 t = (threadIdx.x < nw) ? red[threadIdx.x] : make_float2(0.f, 0.f);
    if (wid == 0) {
        #pragma unroll
        for (int o = 16; o; o >>= 1) {
            t.x += __shfl_xor_sync(0xffffffffu, t.x, o);
            t.y += __shfl_xor_sync(0xffffffffu, t.y, o);
        }
    }
    if (threadIdx.x == 0) red[0] = t;
    __syncthreads();
    t = red[0];
    __syncthreads();
    return t;
}

__device__ __forceinline__ float block_reduce_max(float v) {
    __shared__ float red[32];
    int lane = threadIdx.x & 31, wid = threadIdx.x >> 5;
    #pragma unroll
    for (int o = 16; o; o >>= 1) v = fmaxf(v, __shfl_xor_sync(0xffffffffu, v, o));
    if (lane == 0) red[wid] = v;
    __syncthreads();
    int nw = (blockDim.x + 31) >> 5;
    v = (threadIdx.x < nw) ? red[threadIdx.x] : -1e30f;
    if (wid == 0) {
        #pragma unroll
        for (int o = 16; o; o >>= 1) v = fmaxf(v, __shfl_xor_sync(0xffffffffu, v, o));
    }
    if (threadIdx.x == 0) red[0] = v;
    __syncthreads();
    v = red[0];
    __syncthreads();
    return v;
}

// ---------------- weight transpose + hi/lo split ----------------
__global__ __launch_bounds__(256) void wsplit_kernel(
    const float* __restrict__ src, bf16* __restrict__ dhi, bf16* __restrict__ dlo,
    int K, int N, size_t srcStride, size_t dstStride)
{
    __shared__ float t[32][33];
    int l = blockIdx.z;
    src += (size_t)l * srcStride;
    dhi += (size_t)l * dstStride;
    dlo += (size_t)l * dstStride;
    int tx = threadIdx.x & 31, ty = threadIdx.x >> 5;
    int n0 = blockIdx.x * 32, k0 = blockIdx.y * 32;
    #pragma unroll
    for (int i = 0; i < 4; i++)
        t[ty + i * 8][tx] = src[(size_t)(k0 + ty + i * 8) * N + n0 + tx];
    __syncthreads();
    #pragma unroll
    for (int i = 0; i < 4; i++) {
        int r = ty + i * 8;
        float x = t[tx][r];
        bf16 hi, lo; split_bf16(x, hi, lo);
        size_t o = (size_t)(n0 + r) * K + k0 + tx;
        dhi[o] = hi; dlo[o] = lo;
    }
}

__global__ __launch_bounds__(256) void wsplit_qkv_kernel(
    const float* __restrict__ Wq, const float* __restrict__ Wk,
    const float* __restrict__ Wv, bf16* __restrict__ dhi, bf16* __restrict__ dlo)
{
    __shared__ float t[32][33];
    int z = blockIdx.z;
    int l = z / 3, j = z % 3;
    const float* src = (j == 0 ? Wq : (j == 1 ? Wk : Wv)) + (size_t)l * H_ * H_;
    bf16* oh = dhi + (size_t)l * QKVS * H_ + (size_t)j * H_ * H_;
    bf16* ol = dlo + (size_t)l * QKVS * H_ + (size_t)j * H_ * H_;
    int tx = threadIdx.x & 31, ty = threadIdx.x >> 5;
    int n0 = blockIdx.x * 32, k0 = blockIdx.y * 32;
    #pragma unroll
    for (int i = 0; i < 4; i++)
        t[ty + i * 8][tx] = src[(size_t)(k0 + ty + i * 8) * H_ + n0 + tx];
    __syncthreads();
    #pragma unroll
    for (int i = 0; i < 4; i++) {
        int r = ty + i * 8;
        float x = t[tx][r];
        bf16 hi, lo; split_bf16(x, hi, lo);
        size_t o = (size_t)(n0 + r) * H_ + k0 + tx;
        oh[o] = hi; ol[o] = lo;
    }
}

// ---------------- embedding + LN (+ fused qkv-bias concat) ----------------
__global__ __launch_bounds__(256) void embed_ln_kernel(
    const float* __restrict__ WE, const float* __restrict__ PE,
    const float* __restrict__ g, const float* __restrict__ be,
    const int* __restrict__ ids,
    float* __restrict__ out, bf16* __restrict__ ohi, bf16* __restrict__ olo,
    const float* __restrict__ bq, const float* __restrict__ bk,
    const float* __restrict__ bv, float* __restrict__ bqkv)
{
    int t = blockIdx.x;
    int tid = threadIdx.x;
    if (t >= BS_) {
        int l = t - BS_;
        for (int n = tid; n < QKVS; n += 256) {
            float v;
            if (n < H_)          v = bq[l * H_ + n];
            else if (n < 2 * H_) v = bk[l * H_ + n - H_];
            else                 v = bv[l * H_ + n - 2 * H_];
            bqkv[l * QKVS + n] = v;
        }
        return;
    }
    int s = t & (S_ - 1);
    int id = ids[t];
    float v[3];
    float s1 = 0.f, s2 = 0.f;
    #pragma unroll
    for (int i = 0; i < 3; i++) {
        int c = tid + i * 256;
        v[i] = WE[(size_t)id * H_ + c] + PE[(size_t)s * H_ + c];
        s1 += v[i]; s2 += v[i] * v[i];
    }
    float2 red = block_reduce_sum2(s1, s2);
    float m = red.x * (1.f / H_);
    float var = red.y * (1.f / H_) - m * m;
    float rs = rsqrtf(var + 1e-5f);
    #pragma unroll
    for (int i = 0; i < 3; i++) {
        int c = tid + i * 256;
        float y = (v[i] - m) * rs * g[c] + be[c];
        size_t o = (size_t)t * H_ + c;
        out[o] = y;
        bf16 hi, lo; split_bf16(y, hi, lo);
        ohi[o] = hi; olo[o] = lo;
    }
}

// ---------------- residual add + LN (in-place on h) ----------------
__global__ __launch_bounds__(256) void add_ln_kernel(
    float* __restrict__ h, const float* __restrict__ r,
    const float* __restrict__ g, const float* __restrict__ be,
    bf16* __restrict__ ohi, bf16* __restrict__ olo)
{
    int t = blockIdx.x;
    int tid = threadIdx.x;
    float v[3];
    float s1 = 0.f, s2 = 0.f;
    #pragma unroll
    for (int i = 0; i < 3; i++) {
        int c = tid + i * 256;
        size_t o = (size_t)t * H_ + c;
        v[i] = h[o] + r[o];
        s1 += v[i]; s2 += v[i] * v[i];
    }
    float2 red = block_reduce_sum2(s1, s2);
    float m = red.x * (1.f / H_);
    float var = red.y * (1.f / H_) - m * m;
    float rs = rsqrtf(var + 1e-5f);
    #pragma unroll
    for (int i = 0; i < 3; i++) {
        int c = tid + i * 256;
        float y = (v[i] - m) * rs * g[c] + be[c];
        size_t o = (size_t)t * H_ + c;
        h[o] = y;
        bf16 hi, lo; split_bf16(y, hi, lo);
        ohi[o] = hi; olo[o] = lo;
    }
}

// ================= bf16x3 tensor-core GEMM, 128x128 (narrow N) ============
#define PSTR 20
#define STG  (128 * PSTR)
#define GSMEM (8 * STG * 4)

__global__ __launch_bounds__(256) void tgemm_kernel(
    const bf16* __restrict__ Ah, const bf16* __restrict__ Al,
    const bf16* __restrict__ Bh, const bf16* __restrict__ Bl,
    const float* __restrict__ bias,
    float* __restrict__ Cf, bf16* __restrict__ Ch, bf16* __restrict__ Cl,
    int M, int N, int K, int mode)
{
    extern __shared__ uint32_t smem_u[];

    const int tid  = threadIdx.x;
    const int warp = tid >> 5;
    const int lane = tid & 31;
    const int m0 = blockIdx.y * 128;
    const int n0 = blockIdx.x * 128;
    const int wm = (warp >> 1) * 32;
    const int wn = (warp & 1) * 64;
    const int grp = lane >> 2;
    const int tig = lane & 3;
    const uint32_t smbase = (uint32_t)__cvta_generic_to_shared(smem_u);

    const int aRow = wm + (lane & 7) + ((lane >> 3) & 1) * 8;
    const int aBlk = lane >> 4;
    const int bRow = wn + (lane & 7) + (lane >> 4) * 8;
    const int bBlk = (lane >> 3) & 1;

    float acc[2][8][4];
    #pragma unroll
    for (int mi = 0; mi < 2; mi++)
        #pragma unroll
        for (int ni = 0; ni < 8; ni++)
            #pragma unroll
            for (int c = 0; c < 4; c++) acc[mi][ni][c] = 0.f;

    const int KT = K >> 5;     // even

    #define LOAD_STAGE(S, k0)                                                          \
    {                                                                                  \
        _Pragma("unroll")                                                              \
        for (int r = 0; r < 2; r++) {                                                  \
            int idx = tid + r * 256;                                                   \
            int row = idx >> 2, c = idx & 3;                                           \
            uint32_t doff = ((S) * 4 * STG + row * PSTR + c * 4) * 4;                  \
            size_t aoff = (size_t)(m0 + row) * K + (k0) + c * 8;                       \
            size_t boff = (size_t)(n0 + row) * K + (k0) + c * 8;                       \
            cp_async16(smbase + doff,               Ah + aoff);                        \
            cp_async16(smbase + doff + STG * 4,     Al + aoff);                        \
            cp_async16(smbase + doff + 2 * STG * 4, Bh + boff);                        \
            cp_async16(smbase + doff + 3 * STG * 4, Bl + boff);                        \
        }                                                                              \
        cp_async_commit();                                                             \
    }

    #define COMPUTE_STAGE(S)                                                           \
    {                                                                                  \
        const uint32_t sb = smbase + (uint32_t)((S) * 4 * STG) * 4;                    \
        _Pragma("unroll")                                                              \
        for (int st = 0; st < 2; st++) {                                               \
            uint32_t ah_[2][4], al_[2][4];                                             \
            _Pragma("unroll")                                                          \
            for (int mi = 0; mi < 2; mi++) {                                           \
                uint32_t ad = sb + ((aRow + mi * 16) * PSTR) * 4                       \
                            + (st * 2 + aBlk) * 16;                                    \
                ldsm_x4(ah_[mi][0], ah_[mi][1], ah_[mi][2], ah_[mi][3], ad);           \
                ldsm_x4(al_[mi][0], al_[mi][1], al_[mi][2], al_[mi][3],                \
                        ad + STG * 4);                                                 \
            }                                                                          \
            uint32_t bh_[8][2], bl_[8][2];                                             \
            _Pragma("unroll")                                                          \
            for (int t = 0; t < 4; t++) {                                              \
                uint32_t ad = sb + 2 * STG * 4 + ((bRow + t * 16) * PSTR) * 4          \
                            + (st * 2 + bBlk) * 16;                                    \
                ldsm_x4(bh_[2*t][0], bh_[2*t][1], bh_[2*t+1][0], bh_[2*t+1][1], ad);   \
                ldsm_x4(bl_[2*t][0], bl_[2*t][1], bl_[2*t+1][0], bl_[2*t+1][1],        \
                        ad + STG * 4);                                                 \
            }                                                                          \
            _Pragma("unroll")                                                          \
            for (int mi = 0; mi < 2; mi++)                                             \
                _Pragma("unroll")                                                      \
                for (int ni = 0; ni < 8; ni++)                                         \
                    mma_bf16(acc[mi][ni], al_[mi][0], al_[mi][1], al_[mi][2],          \
                             al_[mi][3], bh_[ni][0], bh_[ni][1]);                      \
            _Pragma("unroll")                                                          \
            for (int mi = 0; mi < 2; mi++)                                             \
                _Pragma("unroll")                                                      \
                for (int ni = 0; ni < 8; ni++)                                         \
                    mma_bf16(acc[mi][ni], ah_[mi][0], ah_[mi][1], ah_[mi][2],          \
                             ah_[mi][3], bl_[ni][0], bl_[ni][1]);                      \
            _Pragma("unroll")                                                          \
            for (int mi = 0; mi < 2; mi++)                                             \
                _Pragma("unroll")                                                      \
                for (int ni = 0; ni < 8; ni++)                                         \
                    mma_bf16(acc[mi][ni], ah_[mi][0], ah_[mi][1], ah_[mi][2],          \
                             ah_[mi][3], bh_[ni][0], bh_[ni][1]);                      \
        }                                                                              \
    }

    LOAD_STAGE(0, 0)

    for (int kt = 0; kt < KT; kt += 2) {
        cp_async_wait0();
        __syncthreads();
        if (kt + 1 < KT) LOAD_STAGE(1, (kt + 1) << 5)
        COMPUTE_STAGE(0)

        cp_async_wait0();
        __syncthreads();
        if (kt + 2 < KT) LOAD_STAGE(0, (kt + 2) << 5)
        COMPUTE_STAGE(1)
    }

    #pragma unroll
    for (int mi = 0; mi < 2; mi++) {
        int row0 = m0 + wm + mi * 16 + grp;
        #pragma unroll
        for (int ni = 0; ni < 8; ni++) {
            int col = n0 + wn + ni * 8 + tig * 2;
            float b0 = bias[col], b1 = bias[col + 1];
            float v0 = acc[mi][ni][0] + b0;
            float v1 = acc[mi][ni][1] + b1;
            float v2 = acc[mi][ni][2] + b0;
            float v3 = acc[mi][ni][3] + b1;
            if (mode == 0) {
                *(float2*)(Cf + (size_t)row0 * N + col)       = make_float2(v0, v1);
                *(float2*)(Cf + (size_t)(row0 + 8) * N + col) = make_float2(v2, v3);
            } else {
                if (mode == 1) {
                    v0 = 0.5f * v0 * (1.0f + erff(v0 * 0.70710678118654752f));
                    v1 = 0.5f * v1 * (1.0f + erff(v1 * 0.70710678118654752f));
                    v2 = 0.5f * v2 * (1.0f + erff(v2 * 0.70710678118654752f));
                    v3 = 0.5f * v3 * (1.0f + erff(v3 * 0.70710678118654752f));
                } else {
                    float scq = (col < H_) ? 0.125f : 1.f;
                    v0 *= scq; v1 *= scq; v2 *= scq; v3 *= scq;
                }
                size_t o0 = (size_t)row0 * N + col;
                size_t o1 = (size_t)(row0 + 8) * N + col;
                uint32_t ph, pl;
                packsplit(v0, v1, ph, pl);
                *(uint32_t*)(Ch + o0) = ph; *(uint32_t*)(Cl + o0) = pl;
                packsplit(v2, v3, ph, pl);
                *(uint32_t*)(Ch + o1) = ph; *(uint32_t*)(Cl + o1) = pl;
            }
        }
    }
}

// ================= bf16x3 tensor-core GEMM, 256x128 / 512 threads =========
// For wide-N GEMMs (QKV, FFN-up). 16 warps: wm in {0..224}, wn in {0,64}.
#define STGA (256 * PSTR)                  // A tile uint32
#define STGB (128 * PSTR)                  // B tile uint32
#define STG2 (2 * STGA + 2 * STGB)         // stage uint32
#define GSMEM2 (2 * STG2 * 4)

__global__ __launch_bounds__(512) void tgemm256_kernel(
    const bf16* __restrict__ Ah, const bf16* __restrict__ Al,
    const bf16* __restrict__ Bh, const bf16* __restrict__ Bl,
    const float* __restrict__ bias,
    bf16* __restrict__ Ch, bf16* __restrict__ Cl,
    int M, int N, int K, int mode)   // mode 1: GELU, mode 2: qkv
{
    extern __shared__ uint32_t smem_u[];

    const int tid  = threadIdx.x;
    const int warp = tid >> 5;
    const int lane = tid & 31;
    const int m0 = blockIdx.y * 256;
    const int n0 = blockIdx.x * 128;
    const int wm = (warp >> 1) * 32;       // 0..224
    const int wn = (warp & 1) * 64;
    const int grp = lane >> 2;
    const int tig = lane & 3;
    const uint32_t smbase = (uint32_t)__cvta_generic_to_shared(smem_u);

    const int aRow = wm + (lane & 7) + ((lane >> 3) & 1) * 8;
    const int aBlk = lane >> 4;
    const int bRow = wn + (lane & 7) + (lane >> 4) * 8;
    const int bBlk = (lane >> 3) & 1;

    float acc[2][8][4];
    #pragma unroll
    for (int mi = 0; mi < 2; mi++)
        #pragma unroll
        for (int ni = 0; ni < 8; ni++)
            #pragma unroll
            for (int c = 0; c < 4; c++) acc[mi][ni][c] = 0.f;

    const int KT = K >> 5;     // even (24)

    // stage layout: Ah(STGA) | Al(STGA) | Bh(STGB) | Bl(STGB)
    #define LOAD_STAGE2(S, k0)                                                         \
    {                                                                                  \
        _Pragma("unroll")                                                              \
        for (int r = 0; r < 2; r++) {                                                  \
            int idx = tid + r * 512;                                                   \
            int row = idx >> 2, c = idx & 3;                                           \
            uint32_t doff = ((S) * STG2 + row * PSTR + c * 4) * 4;                     \
            size_t aoff = (size_t)(m0 + row) * K + (k0) + c * 8;                       \
            cp_async16(smbase + doff,            Ah + aoff);                           \
            cp_async16(smbase + doff + STGA * 4, Al + aoff);                           \
        }                                                                              \
        {                                                                              \
            int row = tid >> 2, c = tid & 3;                                           \
            uint32_t doff = ((S) * STG2 + 2 * STGA + row * PSTR + c * 4) * 4;          \
            size_t boff = (size_t)(n0 + row) * K + (k0) + c * 8;                       \
            cp_async16(smbase + doff,            Bh + boff);                           \
            cp_async16(smbase + doff + STGB * 4, Bl + boff);                           \
        }                                                                              \
        cp_async_commit();                                                             \
    }

    #define COMPUTE_STAGE2(S)                                                          \
    {                                                                                  \
        const uint32_t sb = smbase + (uint32_t)((S) * STG2) * 4;                       \
        _Pragma("unroll")                                                              \
        for (int st = 0; st < 2; st++) {                                               \
            uint32_t ah_[2][4], al_[2][4];                                             \
            _Pragma("unroll")                                                          \
            for (int mi = 0; mi < 2; mi++) {                                           \
                uint32_t ad = sb + ((aRow + mi * 16) * PSTR) * 4                       \
                            + (st * 2 + aBlk) * 16;                                    \
                ldsm_x4(ah_[mi][0], ah_[mi][1], ah_[mi][2], ah_[mi][3], ad);           \
                ldsm_x4(al_[mi][0], al_[mi][1], al_[mi][2], al_[mi][3],                \
                        ad + STGA * 4);                                                \
            }                                                                          \
            uint32_t bh_[8][2], bl_[8][2];                                             \
            _Pragma("unroll")                                                          \
            for (int t = 0; t < 4; t++) {                                              \
                uint32_t ad = sb + 2 * STGA * 4 + ((bRow + t * 16) * PSTR) * 4         \
                            + (st * 2 + bBlk) * 16;                                    \
                ldsm_x4(bh_[2*t][0], bh_[2*t][1], bh_[2*t+1][0], bh_[2*t+1][1], ad);   \
                ldsm_x4(bl_[2*t][0], bl_[2*t][1], bl_[2*t+1][0], bl_[2*t+1][1],        \
                        ad + STGB * 4);                                                \
            }                                                                          \
            _Pragma("unroll")                                                          \
            for (int mi = 0; mi < 2; mi++)                                             \
                _Pragma("unroll")                                                      \
                for (int ni = 0; ni < 8; ni++)                                         \
                    mma_bf16(acc[mi][ni], al_[mi][0], al_[mi][1], al_[mi][2],          \
                             al_[mi][3], bh_[ni][0], bh_[ni][1]);                      \
            _Pragma("unroll")                                                          \
            for (int mi = 0; mi < 2; mi++)                                             \
                _Pragma("unroll")                                                      \
                for (int ni = 0; ni < 8; ni++)                                         \
                    mma_bf16(acc[mi][ni], ah_[mi][0], ah_[mi][1], ah_[mi][2],          \
                             ah_[mi][3], bl_[ni][0], bl_[ni][1]);                      \
            _Pragma("unroll")                                                          \
            for (int mi = 0; mi < 2; mi++)                                             \
                _Pragma("unroll")                                                      \
                for (int ni = 0; ni < 8; ni++)                                         \
                    mma_bf16(acc[mi][ni], ah_[mi][0], ah_[mi][1], ah_[mi][2],          \
                             ah_[mi][3], bh_[ni][0], bh_[ni][1]);                      \
        }                                                                              \
    }

    LOAD_STAGE2(0, 0)

    for (int kt = 0; kt < KT; kt += 2) {
        cp_async_wait0();
        __syncthreads();
        if (kt + 1 < KT) LOAD_STAGE2(1, (kt + 1) << 5)
        COMPUTE_STAGE2(0)

        cp_async_wait0();
        __syncthreads();
        if (kt + 2 < KT) LOAD_STAGE2(0, (kt + 2) << 5)
        COMPUTE_STAGE2(1)
    }

    #pragma unroll
    for (int mi = 0; mi < 2; mi++) {
        int row0 = m0 + wm + mi * 16 + grp;
        #pragma unroll
        for (int ni = 0; ni < 8; ni++) {
            int col = n0 + wn + ni * 8 + tig * 2;
            float b0 = bias[col], b1 = bias[col + 1];
            float v0 = acc[mi][ni][0] + b0;
            float v1 = acc[mi][ni][1] + b1;
            float v2 = acc[mi][ni][2] + b0;
            float v3 = acc[mi][ni][3] + b1;
            if (mode == 1) {
                v0 = 0.5f * v0 * (1.0f + erff(v0 * 0.70710678118654752f));
                v1 = 0.5f * v1 * (1.0f + erff(v1 * 0.70710678118654752f));
                v2 = 0.5f * v2 * (1.0f + erff(v2 * 0.70710678118654752f));
                v3 = 0.5f * v3 * (1.0f + erff(v3 * 0.70710678118654752f));
            } else {
                float scq = (col < H_) ? 0.125f : 1.f;
                v0 *= scq; v1 *= scq; v2 *= scq; v3 *= scq;
            }
            size_t o0 = (size_t)row0 * N + col;
            size_t o1 = (size_t)(row0 + 8) * N + col;
            uint32_t ph, pl;
            packsplit(v0, v1, ph, pl);
            *(uint32_t*)(Ch + o0) = ph; *(uint32_t*)(Cl + o0) = pl;
            packsplit(v2, v3, ph, pl);
            *(uint32_t*)(Ch + o1) = ph; *(uint32_t*)(Cl + o1) = pl;
        }
    }
}

// ================= tensor-core local attention (mma.sync) =================
#define QSTR 36
#define ATT_SMEM ((2 * 128 * QSTR + 4 * 64 * QSTR + 64) * 4)

__global__ __launch_bounds__(256, 1) void attn_tc_kernel(
    const bf16* __restrict__ Qh, const bf16* __restrict__ Ql,
    const int* __restrict__ amask,
    bf16* __restrict__ Ohi, bf16* __restrict__ Olo)
{
    extern __shared__ uint32_t sm[];
    const int OQH = 0;
    const int OQL = OQH + 128 * QSTR;
    const int OKH = OQL + 128 * QSTR;
    const int OKL = OKH + 64 * QSTR;
    const int OVH = OKL + 64 * QSTR;
    const int OVL = OVH + 64 * QSTR;
    const int OMF = OVL + 64 * QSTR;
    float* mf = (float*)(sm + OMF);

    const int q0 = blockIdx.x * 128;
    const int hh = blockIdx.y;
    const int b  = blockIdx.z;
    const int tid = threadIdx.x, warp = tid >> 5, lane = tid & 31;
    const int grp = lane >> 2, tig = lane & 3;
    const uint32_t base = (uint32_t)__cvta_generic_to_shared(sm);
    const unsigned FULL = 0xffffffffu;

    for (int idx = tid; idx < 128 * 8; idx += 256) {
        int r = idx >> 3, q4 = idx & 7;
        size_t off = (size_t)(b * S_ + q0 + r) * QKVS + hh * DH_;
        ((uint4*)(sm + OQH + r * QSTR))[q4] = ((const uint4*)(Qh + off))[q4];
        ((uint4*)(sm + OQL + r * QSTR))[q4] = ((const uint4*)(Ql + off))[q4];
    }
    __syncthreads();

    uint32_t qfh[4][4], qfl[4][4];
    {
        int arow = warp * 16 + (lane & 7) + ((lane >> 3) & 1) * 8;
        int ablk = lane >> 4;
        #pragma unroll
        for (int st = 0; st < 4; st++) {
            uint32_t ad = base + (OQH + arow * QSTR) * 4 + (st * 2 + ablk) * 16;
            ldsm_x4(qfh[st][0], qfh[st][1], qfh[st][2], qfh[st][3], ad);
            ldsm_x4(qfl[st][0], qfl[st][1], qfl[st][2], qfl[st][3],
                    ad + (OQL - OQH) * 4);
        }
    }

    float o[8][4];
    #pragma unroll
    for (int ni = 0; ni < 8; ni++)
        #pragma unroll
        for (int c = 0; c < 4; c++) o[ni][c] = 0.f;
    float m0 = -1e30f, m1 = -1e30f, l0 = 0.f, l1 = 0.f;

    const int brow = (lane & 7) + (lane >> 4) * 8;
    const int bblk = (lane >> 3) & 1;
    const int vrow = (lane & 7) + ((lane >> 3) & 1) * 8;
    const int vblk = lane >> 4;
    const int qg0 = q0 + warp * 16 + grp;
    const int qg1 = qg0 + 8;

    for (int kt = 0; kt < 10; kt++) {
        const int ks = q0 - 256 + kt * 64;
        if (ks + 64 <= 0 || ks >= S_) continue;
        __syncthreads();
        const uint4 z4 = make_uint4(0u, 0u, 0u, 0u);
        for (int idx = tid; idx < 64 * 8; idx += 256) {
            int c = idx >> 3, q4 = idx & 7;
            int kg = ks + c;
            uint4 kh = z4, kl = z4, vh = z4, vl = z4;
            if (kg >= 0 && kg < S_) {
                size_t off = (size_t)(b * S_ + kg) * QKVS + hh * DH_;
                kh = ((const uint4*)(Qh + off + H_))[q4];
                kl = ((const uint4*)(Ql + off + H_))[q4];
                vh = ((const uint4*)(Qh + off + 2 * H_))[q4];
                vl = ((const uint4*)(Ql + off + 2 * H_))[q4];
            }
            ((uint4*)(sm + OKH + c * QSTR))[q4] = kh;
            ((uint4*)(sm + OKL + c * QSTR))[q4] = kl;
            ((uint4*)(sm + OVH + c * QSTR))[q4] = vh;
            ((uint4*)(sm + OVL + c * QSTR))[q4] = vl;
        }
        if (tid < 64) {
            int kg = ks + tid;
            mf[tid] = (kg >= 0 && kg < S_ && amask[b * S_ + kg] > 0) ? 0.f : -1e9f;
        }
        __syncthreads();

        float s[8][4];
        #pragma unroll
        for (int ni = 0; ni < 8; ni++)
            #pragma unroll
            for (int c = 0; c < 4; c++) s[ni][c] = 0.f;
        #pragma unroll
        for (int st = 0; st < 4; st++) {
            uint32_t kbh[8][2], kbl[8][2];
            #pragma unroll
            for (int t = 0; t < 4; t++) {
                uint32_t ad = base + (OKH + (t * 16 + brow) * QSTR) * 4
                            + (st * 2 + bblk) * 16;
                ldsm_x4(kbh[2*t][0], kbh[2*t][1], kbh[2*t+1][0], kbh[2*t+1][1], ad);
                ldsm_x4(kbl[2*t][0], kbl[2*t][1], kbl[2*t+1][0], kbl[2*t+1][1],
                        ad + (OKL - OKH) * 4);
            }
            #pragma unroll
            for (int ni = 0; ni < 8; ni++)
                mma_bf16(s[ni], qfl[st][0], qfl[st][1], qfl[st][2], qfl[st][3],
                         kbh[ni][0], kbh[ni][1]);
            #pragma unroll
            for (int ni = 0; ni < 8; ni++)
                mma_bf16(s[ni], qfh[st][0], qfh[st][1], qfh[st][2], qfh[st][3],
                         kbl[ni][0], kbl[ni][1]);
            #pragma unroll
            for (int ni = 0; ni < 8; ni++)
                mma_bf16(s[ni], qfh[st][0], qfh[st][1], qfh[st][2], qfh[st][3],
                         kbh[ni][0], kbh[ni][1]);
        }

        float tmax0 = -1e30f, tmax1 = -1e30f;
        #pragma unroll
        for (int ni = 0; ni < 8; ni++) {
            int kl0 = ni * 8 + 2 * tig;
            float mv0 = mf[kl0], mv1 = mf[kl0 + 1];
            int kg0 = ks + kl0;
            int d00 = kg0 - qg0, d01 = d00 + 1;
            int d10 = kg0 - qg1, d11 = d10 + 1;
            float x0 = (d00 >= -WIN_ && d00 <= WIN_) ? s[ni][0] + mv0 : -1e9f;
            float x1 = (d01 >= -WIN_ && d01 <= WIN_) ? s[ni][1] + mv1 : -1e9f;
            float x2 = (d10 >= -WIN_ && d10 <= WIN_) ? s[ni][2] + mv0 : -1e9f;
            float x3 = (d11 >= -WIN_ && d11 <= WIN_) ? s[ni][3] + mv1 : -1e9f;
            s[ni][0] = x0; s[ni][1] = x1; s[ni][2] = x2; s[ni][3] = x3;
            tmax0 = fmaxf(tmax0, fmaxf(x0, x1));
            tmax1 = fmaxf(tmax1, fmaxf(x2, x3));
        }
        tmax0 = fmaxf(tmax0, __shfl_xor_sync(FULL, tmax0, 1));
        tmax0 = fmaxf(tmax0, __shfl_xor_sync(FULL, tmax0, 2));
        tmax1 = fmaxf(tmax1, __shfl_xor_sync(FULL, tmax1, 1));
        tmax1 = fmaxf(tmax1, __shfl_xor_sync(FULL, tmax1, 2));
        float mn0 = fmaxf(m0, tmax0), mn1 = fmaxf(m1, tmax1);
        float sc0 = __expf(m0 - mn0), sc1 = __expf(m1 - mn1);
        float ps0 = 0.f, ps1 = 0.f;
        #pragma unroll
        for (int ni = 0; ni < 8; ni++) {
            s[ni][0] = __expf(s[ni][0] - mn0);
            s[ni][1] = __expf(s[ni][1] - mn0);
            s[ni][2] = __expf(s[ni][2] - mn1);
            s[ni][3] = __expf(s[ni][3] - mn1);
            ps0 += s[ni][0] + s[ni][1];
            ps1 += s[ni][2] + s[ni][3];
        }
        ps0 += __shfl_xor_sync(FULL, ps0, 1);
        ps0 += __shfl_xor_sync(FULL, ps0, 2);
        ps1 += __shfl_xor_sync(FULL, ps1, 1);
        ps1 += __shfl_xor_sync(FULL, ps1, 2);
        l0 = l0 * sc0 + ps0;
        l1 = l1 * sc1 + ps1;
        m0 = mn0; m1 = mn1;
        #pragma unroll
        for (int ni = 0; ni < 8; ni++) {
            o[ni][0] *= sc0; o[ni][1] *= sc0;
            o[ni][2] *= sc1; o[ni][3] *= sc1;
        }

        uint32_t pah[4][4], pal[4][4];
        #pragma unroll
        for (int j = 0; j < 4; j++) {
            packsplit(s[2*j][0],   s[2*j][1],   pah[j][0], pal[j][0]);
            packsplit(s[2*j][2],   s[2*j][3],   pah[j][1], pal[j][1]);
            packsplit(s[2*j+1][0], s[2*j+1][1], pah[j][2], pal[j][2]);
            packsplit(s[2*j+1][2], s[2*j+1][3], pah[j][3], pal[j][3]);
        }

        #pragma unroll
        for (int j = 0; j < 4; j++) {
            uint32_t vbh[8][2], vbl[8][2];
            #pragma unroll
            for (int t = 0; t < 4; t++) {
                uint32_t ad = base + (OVH + (j * 16 + vrow) * QSTR) * 4
                            + (2 * t + vblk) * 16;
                ldsm_x4_t(vbh[2*t][0], vbh[2*t][1], vbh[2*t+1][0], vbh[2*t+1][1], ad);
                ldsm_x4_t(vbl[2*t][0], vbl[2*t][1], vbl[2*t+1][0], vbl[2*t+1][1],
                          ad + (OVL - OVH) * 4);
            }
            #pragma unroll
            for (int ni = 0; ni < 8; ni++)
                mma_bf16(o[ni], pal[j][0], pal[j][1], pal[j][2], pal[j][3],
                         vbh[ni][0], vbh[ni][1]);
            #pragma unroll
            for (int ni = 0; ni < 8; ni++)
                mma_bf16(o[ni], pah[j][0], pah[j][1], pah[j][2], pah[j][3],
                         vbl[ni][0], vbl[ni][1]);
            #pragma unroll
            for (int ni = 0; ni < 8; ni++)
                mma_bf16(o[ni], pah[j][0], pah[j][1], pah[j][2], pah[j][3],
                         vbh[ni][0], vbh[ni][1]);
        }
    }

    float inv0 = 1.f / l0, inv1 = 1.f / l1;
    #pragma unroll
    for (int ni = 0; ni < 8; ni++) {
        int dcol = hh * DH_ + ni * 8 + 2 * tig;
        size_t o0 = (size_t)(b * S_ + qg0) * H_ + dcol;
        size_t o1 = (size_t)(b * S_ + qg1) * H_ + dcol;
        uint32_t ph, pl;
        packsplit(o[ni][0] * inv0, o[ni][1] * inv0, ph, pl);
        *(uint32_t*)(Ohi + o0) = ph;
        *(uint32_t*)(Olo + o0) = pl;
        packsplit(o[ni][2] * inv1, o[ni][3] * inv1, ph, pl);
        *(uint32_t*)(Ohi + o1) = ph;
        *(uint32_t*)(Olo + o1) = pl;
    }
}

// ---------------- pooling head ----------------
__global__ __launch_bounds__(256) void attn_score_kernel(
    const float* __restrict__ h, const float* __restrict__ aw, float* __restrict__ sc)
{
    int t = blockIdx.x;
    int tid = threadIdx.x;
    float acc = 0.f;
    #pragma unroll
    for (int i = 0; i < 3; i++) {
        int c = tid + i * 256;
        acc += h[(size_t)t * H_ + c] * aw[c];
    }
    float s = block_reduce_sum(acc);
    if (tid == 0) sc[t] = s;
}

__global__ __launch_bounds__(256) void softmax_s_kernel(
    const float* __restrict__ sc, float* __restrict__ pr)
{
    int b = blockIdx.x;
    int tid = threadIdx.x;
    float v[4];
    float mx = -1e30f;
    #pragma unroll
    for (int i = 0; i < 4; i++) {
        v[i] = sc[b * S_ + tid + i * 256];
        mx = fmaxf(mx, v[i]);
    }
    mx = block_reduce_max(mx);
    float e[4], ps = 0.f;
    #pragma unroll
    for (int i = 0; i < 4; i++) { e[i] = __expf(v[i] - mx); ps += e[i]; }
    float tot = block_reduce_sum(ps);
    float inv = 1.f / tot;
    #pragma unroll
    for (int i = 0; i < 4; i++) pr[b * S_ + tid + i * 256] = e[i] * inv;
}

__global__ __launch_bounds__(256) void pool_kernel(
    const float* __restrict__ h, const float* __restrict__ pr, float* __restrict__ poolp)
{
    int d = blockIdx.x * 256 + threadIdx.x;
    int b = blockIdx.y;
    int p = blockIdx.z;
    float acc = 0.f;
    int s0 = p * (S_ / 8);
    for (int s = s0; s < s0 + S_ / 8; s++) {
        acc += h[((size_t)(b * S_ + s)) * H_ + d] * pr[b * S_ + s];
    }
    poolp[((size_t)p * B_ + b) * H_ + d] = acc;
}

__global__ __launch_bounds__(256) void final_kernel(
    const float* __restrict__ poolp, const float* __restrict__ Wc,
    const float* __restrict__ bc, float* __restrict__ out)
{
    int b = blockIdx.x;
    int tid = threadIdx.x;
    float acc = 0.f;
    #pragma unroll
    for (int i = 0; i < 3; i++) {
        int c = tid + i * 256;
        float pv = 0.f;
        #pragma unroll
        for (int p = 0; p < 8; p++)
            pv += poolp[((size_t)p * B_ + b) * H_ + c];
        acc += pv * Wc[c];
    }
    float s = block_reduce_sum(acc);
    if (tid == 0) out[b] = s + bc[0];
}

// ---------------- host launcher ----------------
extern "C" void kernel_launch(void* const* d_in, const int* in_sizes, int n_in,
                              void* d_out, int out_size)
{
    (void)in_sizes; (void)n_in; (void)out_size;
    const float* WE   = (const float*)d_in[0];
    const float* PE   = (const float*)d_in[1];
    const float* Eg   = (const float*)d_in[2];
    const float* Eb   = (const float*)d_in[3];
    const float* Wq   = (const float*)d_in[4];
    const float* bq   = (const float*)d_in[5];
    const float* Wk   = (const float*)d_in[6];
    const float* bk   = (const float*)d_in[7];
    const float* Wv   = (const float*)d_in[8];
    const float* bv   = (const float*)d_in[9];
    const float* Wo   = (const float*)d_in[10];
    const float* bo   = (const float*)d_in[11];
    const float* g1   = (const float*)d_in[12];
    const float* beta1= (const float*)d_in[13];
    const float* W1   = (const float*)d_in[14];
    const float* b1   = (const float*)d_in[15];
    const float* W2   = (const float*)d_in[16];
    const float* b2   = (const float*)d_in[17];
    const float* g2   = (const float*)d_in[18];
    const float* beta2= (const float*)d_in[19];
    const float* aw   = (const float*)d_in[20];
    const float* Wc   = (const float*)d_in[21];
    const float* bc   = (const float*)d_in[22];
    const int*   ids  = (const int*)d_in[23];
    const int*   am   = (const int*)d_in[24];
    float* out = (float*)d_out;

    bf16 *wqkv_hi, *wqkv_lo, *wot_hi, *wot_lo, *w1t_hi, *w1t_lo, *w2t_hi, *w2t_lo;
    bf16 *h_hi, *h_lo, *a_hi, *a_lo, *f_hi, *f_lo, *qkvh, *qkvl;
    float *bqkv, *h, *r, *sc, *pr, *poolp;
    cudaGetSymbolAddress((void**)&wqkv_hi, g_wqkv_hi);
    cudaGetSymbolAddress((void**)&wqkv_lo, g_wqkv_lo);
    cudaGetSymbolAddress((void**)&wot_hi,  g_wot_hi);
    cudaGetSymbolAddress((void**)&wot_lo,  g_wot_lo);
    cudaGetSymbolAddress((void**)&w1t_hi,  g_w1t_hi);
    cudaGetSymbolAddress((void**)&w1t_lo,  g_w1t_lo);
    cudaGetSymbolAddress((void**)&w2t_hi,  g_w2t_hi);
    cudaGetSymbolAddress((void**)&w2t_lo,  g_w2t_lo);
    cudaGetSymbolAddress((void**)&bqkv,    g_bqkv);
    cudaGetSymbolAddress((void**)&h,       g_h);
    cudaGetSymbolAddress((void**)&h_hi,    g_h_hi);
    cudaGetSymbolAddress((void**)&h_lo,    g_h_lo);
    cudaGetSymbolAddress((void**)&qkvh,    g_qkvh);
    cudaGetSymbolAddress((void**)&qkvl,    g_qkvl);
    cudaGetSymbolAddress((void**)&a_hi,    g_a_hi);
    cudaGetSymbolAddress((void**)&a_lo,    g_a_lo);
    cudaGetSymbolAddress((void**)&f_hi,    g_f_hi);
    cudaGetSymbolAddress((void**)&f_lo,    g_f_lo);
    cudaGetSymbolAddress((void**)&r,       g_r);
    cudaGetSymbolAddress((void**)&sc,      g_sc);
    cudaGetSymbolAddress((void**)&pr,      g_pr);
    cudaGetSymbolAddress((void**)&poolp,   g_poolp);

    cudaFuncSetAttribute(tgemm_kernel,
                         cudaFuncAttributeMaxDynamicSharedMemorySize, GSMEM);
    cudaFuncSetAttribute(tgemm256_kernel,
                         cudaFuncAttributeMaxDynamicSharedMemorySize, GSMEM2);
    cudaFuncSetAttribute(attn_tc_kernel,
                         cudaFuncAttributeMaxDynamicSharedMemorySize, ATT_SMEM);

    // ---- pre-pass (QKV GEMM is launch idx 3 for ncu) ----
    dim3 wb(256);
    wsplit_qkv_kernel<<<dim3(H_ / 32, H_ / 32, 3 * L_), wb>>>(Wq, Wk, Wv,
                                                              wqkv_hi, wqkv_lo);
    embed_ln_kernel<<<BS_ + L_, 256>>>(WE, PE, Eg, Eb, ids, h, h_hi, h_lo,
                                       bq, bk, bv, bqkv);
    wsplit_kernel<<<dim3(H_ / 32, H_ / 32, L_), wb>>>(Wo, wot_hi, wot_lo, H_, H_,
        (size_t)H_ * H_, (size_t)H_ * H_);

    dim3 gQKV(QKVS / 128, BS_ / 256);   // (18, 16) x 512 thr
    dim3 gO(H_ / 128, BS_ / 128);       // (6, 32)  x 256 thr
    dim3 gW1(FF_ / 128, BS_ / 256);     // (24, 16) x 512 thr
    dim3 gattn(S_ / 128, NH_, B_);

    // layer 0 QKV GEMM first (launch idx 3), remaining wsplits after it
    tgemm256_kernel<<<gQKV, 512, GSMEM2>>>(h_hi, h_lo,
        wqkv_hi, wqkv_lo, bqkv, qkvh, qkvl, BS_, QKVS, H_, 2);
    wsplit_kernel<<<dim3(FF_ / 32, H_ / 32, L_), wb>>>(W1, w1t_hi, w1t_lo, H_, FF_,
        (size_t)H_ * FF_, (size_t)FF_ * H_);
    wsplit_kernel<<<dim3(H_ / 32, FF_ / 32, L_), wb>>>(W2, w2t_hi, w2t_lo, FF_, H_,
        (size_t)FF_ * H_, (size_t)H_ * FF_);

    for (int l = 0; l < L_; l++) {
        if (l > 0) {
            tgemm256_kernel<<<gQKV, 512, GSMEM2>>>(h_hi, h_lo,
                wqkv_hi + (size_t)l * QKVS * H_, wqkv_lo + (size_t)l * QKVS * H_,
                bqkv + l * QKVS, qkvh, qkvl, BS_, QKVS, H_, 2);
        }

        attn_tc_kernel<<<gattn, 256, ATT_SMEM>>>(qkvh, qkvl, am, a_hi, a_lo);

        tgemm_kernel<<<gO, 256, GSMEM>>>(a_hi, a_lo,
            wot_hi + (size_t)l * H_ * H_, wot_lo + (size_t)l * H_ * H_,
            bo + l * H_, r, nullptr, nullptr, BS_, H_, H_, 0);
        add_ln_kernel<<<BS_, 256>>>(h, r, g1 + l * H_, beta1 + l * H_, h_hi, h_lo);

        tgemm256_kernel<<<gW1, 512, GSMEM2>>>(h_hi, h_lo,
            w1t_hi + (size_t)l * FF_ * H_, w1t_lo + (size_t)l * FF_ * H_,
            b1 + l * FF_, f_hi, f_lo, BS_, FF_, H_, 1);

        tgemm_kernel<<<gO, 256, GSMEM>>>(f_hi, f_lo,
            w2t_hi + (size_t)l * H_ * FF_, w2t_lo + (size_t)l * H_ * FF_,
            b2 + l * H_, r, nullptr, nullptr, BS_, H_, FF_, 0);
        add_ln_kernel<<<BS_, 256>>>(h, r, g2 + l * H_, beta2 + l * H_, h_hi, h_lo);
    }

    attn_score_kernel<<<BS_, 256>>>(h, aw, sc);
    softmax_s_kernel<<<B_, 256>>>(sc, pr);
    pool_kernel<<<dim3(H_ / 256, B_, 8), 256>>>(h, pr, poolp);
    final_kernel<<<B_, 256>>>(poolp, Wc, bc, out);
}

// round 15
// speedup vs baseline: 1.0270x; 1.0178x over previous
#include <cuda_runtime.h>
#include <cuda_bf16.h>
#include <cstdint>
#include <math.h>

#define L_  12
#define NH_ 12
#define DH_ 64
#define H_  768
#define FF_ 3072
#define S_  1024
#define B_  4
#define BS_ (B_ * S_)   // 4096
#define WIN_ 256
#define QKVS 2304       // fused qkv row stride

typedef __nv_bfloat16 bf16;

// ---------------- scratch (no allocations allowed) ----------------
__device__ bf16 g_wqkv_hi[L_ * QKVS * H_];
__device__ bf16 g_wqkv_lo[L_ * QKVS * H_];
__device__ bf16 g_wot_hi [L_ * H_ * H_];
__device__ bf16 g_wot_lo [L_ * H_ * H_];
__device__ bf16 g_w1t_hi [L_ * FF_ * H_];
__device__ bf16 g_w1t_lo [L_ * FF_ * H_];
__device__ bf16 g_w2t_hi [L_ * H_ * FF_];
__device__ bf16 g_w2t_lo [L_ * H_ * FF_];
__device__ float g_bqkv  [L_ * QKVS];

__device__ float g_h    [BS_ * H_];
__device__ bf16  g_h_hi [BS_ * H_];
__device__ bf16  g_h_lo [BS_ * H_];
__device__ bf16  g_qkvh [BS_ * QKVS];
__device__ bf16  g_qkvl [BS_ * QKVS];
__device__ bf16  g_a_hi [BS_ * H_];
__device__ bf16  g_a_lo [BS_ * H_];
__device__ bf16  g_f_hi [BS_ * FF_];
__device__ bf16  g_f_lo [BS_ * FF_];
__device__ float g_r    [BS_ * H_];
__device__ float g_sc   [BS_];
__device__ float g_pr   [BS_];
__device__ float g_poolp[8 * B_ * H_];

__device__ __forceinline__ void split_bf16(float x, bf16& hi, bf16& lo) {
    hi = __float2bfloat16_rn(x);
    lo = __float2bfloat16_rn(x - __bfloat162float(hi));
}

// ---------------- low-level helpers ----------------
__device__ __forceinline__ void cp_async16(uint32_t smem_addr, const void* gptr) {
    asm volatile("cp.async.cg.shared.global [%0], [%1], 16;\n"
                 :: "r"(smem_addr), "l"(gptr));
}
__device__ __forceinline__ void cp_async_commit() {
    asm volatile("cp.async.commit_group;\n");
}
__device__ __forceinline__ void cp_async_wait0() {
    asm volatile("cp.async.wait_group 0;\n");
}
__device__ __forceinline__ void ldsm_x4(uint32_t& r0, uint32_t& r1, uint32_t& r2,
                                        uint32_t& r3, uint32_t a) {
    asm volatile("ldmatrix.sync.aligned.m8n8.x4.shared.b16 {%0,%1,%2,%3}, [%4];"
                 : "=r"(r0), "=r"(r1), "=r"(r2), "=r"(r3) : "r"(a));
}
__device__ __forceinline__ void ldsm_x4_t(uint32_t& r0, uint32_t& r1, uint32_t& r2,
                                          uint32_t& r3, uint32_t a) {
    asm volatile("ldmatrix.sync.aligned.m8n8.x4.trans.shared.b16 {%0,%1,%2,%3}, [%4];"
                 : "=r"(r0), "=r"(r1), "=r"(r2), "=r"(r3) : "r"(a));
}
__device__ __forceinline__ void mma_bf16(
    float* acc, uint32_t a0, uint32_t a1, uint32_t a2, uint32_t a3,
    uint32_t b0, uint32_t b1)
{
    asm volatile(
        "mma.sync.aligned.m16n8k16.row.col.f32.bf16.bf16.f32 "
        "{%0,%1,%2,%3}, {%4,%5,%6,%7}, {%8,%9}, {%0,%1,%2,%3};\n"
        : "+f"(acc[0]), "+f"(acc[1]), "+f"(acc[2]), "+f"(acc[3])
        : "r"(a0), "r"(a1), "r"(a2), "r"(a3), "r"(b0), "r"(b1));
}
__device__ __forceinline__ void packsplit(float a, float b, uint32_t& ph, uint32_t& pl) {
    bf16 ah = __float2bfloat16_rn(a), bh = __float2bfloat16_rn(b);
    float al = a - __bfloat162float(ah), bl = b - __bfloat162float(bh);
    ph = ((uint32_t)__bfloat16_as_ushort(bh) << 16) | (uint32_t)__bfloat16_as_ushort(ah);
    pl = ((uint32_t)__bfloat16_as_ushort(__float2bfloat16_rn(bl)) << 16)
       |  (uint32_t)__bfloat16_as_ushort(__float2bfloat16_rn(al));
}

// ---------------- reduction helpers ----------------
__device__ __forceinline__ float block_reduce_sum(float v) {
    __shared__ float red[32];
    int lane = threadIdx.x & 31, wid = threadIdx.x >> 5;
    #pragma unroll
    for (int o = 16; o; o >>= 1) v += __shfl_xor_sync(0xffffffffu, v, o);
    if (lane == 0) red[wid] = v;
    __syncthreads();
    int nw = (blockDim.x + 31) >> 5;
    v = (threadIdx.x < nw) ? red[threadIdx.x] : 0.f;
    if (wid == 0) {
        #pragma unroll
        for (int o = 16; o; o >>= 1) v += __shfl_xor_sync(0xffffffffu, v, o);
    }
    if (threadIdx.x == 0) red[0] = v;
    __syncthreads();
    v = red[0];
    __syncthreads();
    return v;
}

__device__ __forceinline__ float2 block_reduce_sum2(float a, float b) {
    __shared__ float2 red[32];
    int lane = threadIdx.x & 31, wid = threadIdx.x >> 5;
    #pragma unroll
    for (int o = 16; o; o >>= 1) {
        a += __shfl_xor_sync(0xffffffffu, a, o);
        b += __shfl_xor_sync(0xffffffffu, b, o);
    }
    if (lane == 0) red[wid] = make_float2(a, b);
    __syncthreads();
    int nw = (blockDim.x + 31) >> 5;
    float2 t = (threadIdx.x < nw) ? red[threadIdx.x] : make_float2(0.f, 0.f);
    if (wid == 0) {
        #pragma unroll
        for (int o = 16; o; o >>= 1) {
            t.x += __shfl_xor_sync(0xffffffffu, t.x, o);
            t.y += __shfl_xor_sync(0xffffffffu, t.y, o);
        }
    }
    if (threadIdx.x == 0) red[0] = t;
    __syncthreads();
    t = red[0];
    __syncthreads();
    return t;
}

__device__ __forceinline__ float block_reduce_max(float v) {
    __shared__ float red[32];
    int lane = threadIdx.x & 31, wid = threadIdx.x >> 5;
    #pragma unroll
    for (int o = 16; o; o >>= 1) v = fmaxf(v, __shfl_xor_sync(0xffffffffu, v, o));
    if (lane == 0) red[wid] = v;
    __syncthreads();
    int nw = (blockDim.x + 31) >> 5;
    v = (threadIdx.x < nw) ? red[threadIdx.x] : -1e30f;
    if (wid == 0) {
        #pragma unroll
        for (int o = 16; o; o >>= 1) v = fmaxf(v, __shfl_xor_sync(0xffffffffu, v, o));
    }
    if (threadIdx.x == 0) red[0] = v;
    __syncthreads();
    v = red[0];
    __syncthreads();
    return v;
}

// ---------------- weight transpose + hi/lo split ----------------
__global__ __launch_bounds__(256) void wsplit_kernel(
    const float* __restrict__ src, bf16* __restrict__ dhi, bf16* __restrict__ dlo,
    int K, int N, size_t srcStride, size_t dstStride)
{
    __shared__ float t[32][33];
    int l = blockIdx.z;
    src += (size_t)l * srcStride;
    dhi += (size_t)l * dstStride;
    dlo += (size_t)l * dstStride;
    int tx = threadIdx.x & 31, ty = threadIdx.x >> 5;
    int n0 = blockIdx.x * 32, k0 = blockIdx.y * 32;
    #pragma unroll
    for (int i = 0; i < 4; i++)
        t[ty + i * 8][tx] = src[(size_t)(k0 + ty + i * 8) * N + n0 + tx];
    __syncthreads();
    #pragma unroll
    for (int i = 0; i < 4; i++) {
        int r = ty + i * 8;
        float x = t[tx][r];
        bf16 hi, lo; split_bf16(x, hi, lo);
        size_t o = (size_t)(n0 + r) * K + k0 + tx;
        dhi[o] = hi; dlo[o] = lo;
    }
}

__global__ __launch_bounds__(256) void wsplit_qkv_kernel(
    const float* __restrict__ Wq, const float* __restrict__ Wk,
    const float* __restrict__ Wv, bf16* __restrict__ dhi, bf16* __restrict__ dlo)
{
    __shared__ float t[32][33];
    int z = blockIdx.z;
    int l = z / 3, j = z % 3;
    const float* src = (j == 0 ? Wq : (j == 1 ? Wk : Wv)) + (size_t)l * H_ * H_;
    bf16* oh = dhi + (size_t)l * QKVS * H_ + (size_t)j * H_ * H_;
    bf16* ol = dlo + (size_t)l * QKVS * H_ + (size_t)j * H_ * H_;
    int tx = threadIdx.x & 31, ty = threadIdx.x >> 5;
    int n0 = blockIdx.x * 32, k0 = blockIdx.y * 32;
    #pragma unroll
    for (int i = 0; i < 4; i++)
        t[ty + i * 8][tx] = src[(size_t)(k0 + ty + i * 8) * H_ + n0 + tx];
    __syncthreads();
    #pragma unroll
    for (int i = 0; i < 4; i++) {
        int r = ty + i * 8;
        float x = t[tx][r];
        bf16 hi, lo; split_bf16(x, hi, lo);
        size_t o = (size_t)(n0 + r) * H_ + k0 + tx;
        oh[o] = hi; ol[o] = lo;
    }
}

// ---------------- embedding + LN (+ fused qkv-bias concat) ----------------
__global__ __launch_bounds__(256) void embed_ln_kernel(
    const float* __restrict__ WE, const float* __restrict__ PE,
    const float* __restrict__ g, const float* __restrict__ be,
    const int* __restrict__ ids,
    float* __restrict__ out, bf16* __restrict__ ohi, bf16* __restrict__ olo,
    const float* __restrict__ bq, const float* __restrict__ bk,
    const float* __restrict__ bv, float* __restrict__ bqkv)
{
    int t = blockIdx.x;
    int tid = threadIdx.x;
    if (t >= BS_) {
        int l = t - BS_;
        for (int n = tid; n < QKVS; n += 256) {
            float v;
            if (n < H_)          v = bq[l * H_ + n];
            else if (n < 2 * H_) v = bk[l * H_ + n - H_];
            else                 v = bv[l * H_ + n - 2 * H_];
            bqkv[l * QKVS + n] = v;
        }
        return;
    }
    int s = t & (S_ - 1);
    int id = ids[t];
    float v[3];
    float s1 = 0.f, s2 = 0.f;
    #pragma unroll
    for (int i = 0; i < 3; i++) {
        int c = tid + i * 256;
        v[i] = WE[(size_t)id * H_ + c] + PE[(size_t)s * H_ + c];
        s1 += v[i]; s2 += v[i] * v[i];
    }
    float2 red = block_reduce_sum2(s1, s2);
    float m = red.x * (1.f / H_);
    float var = red.y * (1.f / H_) - m * m;
    float rs = rsqrtf(var + 1e-5f);
    #pragma unroll
    for (int i = 0; i < 3; i++) {
        int c = tid + i * 256;
        float y = (v[i] - m) * rs * g[c] + be[c];
        size_t o = (size_t)t * H_ + c;
        out[o] = y;
        bf16 hi, lo; split_bf16(y, hi, lo);
        ohi[o] = hi; olo[o] = lo;
    }
}

// ---------------- residual add + LN (in-place on h) ----------------
__global__ __launch_bounds__(256) void add_ln_kernel(
    float* __restrict__ h, const float* __restrict__ r,
    const float* __restrict__ g, const float* __restrict__ be,
    bf16* __restrict__ ohi, bf16* __restrict__ olo)
{
    int t = blockIdx.x;
    int tid = threadIdx.x;
    float v[3];
    float s1 = 0.f, s2 = 0.f;
    #pragma unroll
    for (int i = 0; i < 3; i++) {
        int c = tid + i * 256;
        size_t o = (size_t)t * H_ + c;
        v[i] = h[o] + r[o];
        s1 += v[i]; s2 += v[i] * v[i];
    }
    float2 red = block_reduce_sum2(s1, s2);
    float m = red.x * (1.f / H_);
    float var = red.y * (1.f / H_) - m * m;
    float rs = rsqrtf(var + 1e-5f);
    #pragma unroll
    for (int i = 0; i < 3; i++) {
        int c = tid + i * 256;
        float y = (v[i] - m) * rs * g[c] + be[c];
        size_t o = (size_t)t * H_ + c;
        h[o] = y;
        bf16 hi, lo; split_bf16(y, hi, lo);
        ohi[o] = hi; olo[o] = lo;
    }
}

// ================= bf16x3 tensor-core GEMM (BK=64, unroll x2) =============
// 128x128 tile, K-chunk 64 (128B rows), 2-stage cp.async, compile-time
// stage indices, ONE wait+sync per 192 MMAs/warp.
// mode 0: fp32 + bias. mode 1: GELU -> bf16 hi/lo. mode 2: qkv bf16 hi/lo
//         with 0.125 folded into cols < H_.
#define PSTR 36                 // uint32 per row (32 data + 4 pad)
#define STG  (128 * PSTR)       // uint32 per data tile (18KB)
#define GSMEM (8 * STG * 4)     // 2 stages x 4 tiles = 147456 B

__global__ __launch_bounds__(256) void tgemm_kernel(
    const bf16* __restrict__ Ah, const bf16* __restrict__ Al,
    const bf16* __restrict__ Bh, const bf16* __restrict__ Bl,
    const float* __restrict__ bias,
    float* __restrict__ Cf, bf16* __restrict__ Ch, bf16* __restrict__ Cl,
    int M, int N, int K, int mode)
{
    extern __shared__ uint32_t smem_u[];

    const int tid  = threadIdx.x;
    const int warp = tid >> 5;
    const int lane = tid & 31;
    const int m0 = blockIdx.y * 128;
    const int n0 = blockIdx.x * 128;
    const int wm = (warp >> 1) * 32;
    const int wn = (warp & 1) * 64;
    const int grp = lane >> 2;
    const int tig = lane & 3;
    const uint32_t smbase = (uint32_t)__cvta_generic_to_shared(smem_u);

    const int aRow = wm + (lane & 7) + ((lane >> 3) & 1) * 8;
    const int aBlk = lane >> 4;
    const int bRow = wn + (lane & 7) + (lane >> 4) * 8;
    const int bBlk = (lane >> 3) & 1;

    float acc[2][8][4];
    #pragma unroll
    for (int mi = 0; mi < 2; mi++)
        #pragma unroll
        for (int ni = 0; ni < 8; ni++)
            #pragma unroll
            for (int c = 0; c < 4; c++) acc[mi][ni][c] = 0.f;

    const int KT = K >> 6;     // BK = 64; KT = 12 or 48 (even)

    // stage S in {0,1}; tiles: Ah, Al(+STG), Bh(+2STG), Bl(+3STG)
    #define LOAD_STAGE(S, k0)                                                          \
    {                                                                                  \
        _Pragma("unroll")                                                              \
        for (int r = 0; r < 4; r++) {                                                  \
            int idx = tid + r * 256;                                                   \
            int row = idx >> 3, c = idx & 7;                                           \
            uint32_t doff = ((S) * 4 * STG + row * PSTR + c * 4) * 4;                  \
            size_t aoff = (size_t)(m0 + row) * K + (k0) + c * 8;                       \
            size_t boff = (size_t)(n0 + row) * K + (k0) + c * 8;                       \
            cp_async16(smbase + doff,               Ah + aoff);                        \
            cp_async16(smbase + doff + STG * 4,     Al + aoff);                        \
            cp_async16(smbase + doff + 2 * STG * 4, Bh + boff);                        \
            cp_async16(smbase + doff + 3 * STG * 4, Bl + boff);                        \
        }                                                                              \
        cp_async_commit();                                                             \
    }

    // compute on stage S: 4 k16 steps, term-major
    #define COMPUTE_STAGE(S)                                                           \
    {                                                                                  \
        const uint32_t sb = smbase + (uint32_t)((S) * 4 * STG) * 4;                    \
        _Pragma("unroll")                                                              \
        for (int st = 0; st < 4; st++) {                                               \
            uint32_t ah_[2][4], al_[2][4];                                             \
            _Pragma("unroll")                                                          \
            for (int mi = 0; mi < 2; mi++) {                                           \
                uint32_t ad = sb + ((aRow + mi * 16) * PSTR) * 4                       \
                            + (st * 2 + aBlk) * 16;                                    \
                ldsm_x4(ah_[mi][0], ah_[mi][1], ah_[mi][2], ah_[mi][3], ad);           \
                ldsm_x4(al_[mi][0], al_[mi][1], al_[mi][2], al_[mi][3],                \
                        ad + STG * 4);                                                 \
            }                                                                          \
            uint32_t bh_[8][2], bl_[8][2];                                             \
            _Pragma("unroll")                                                          \
            for (int t = 0; t < 4; t++) {                                              \
                uint32_t ad = sb + 2 * STG * 4 + ((bRow + t * 16) * PSTR) * 4          \
                            + (st * 2 + bBlk) * 16;                                    \
                ldsm_x4(bh_[2*t][0], bh_[2*t][1], bh_[2*t+1][0], bh_[2*t+1][1], ad);   \
                ldsm_x4(bl_[2*t][0], bl_[2*t][1], bl_[2*t+1][0], bl_[2*t+1][1],        \
                        ad + STG * 4);                                                 \
            }                                                                          \
            _Pragma("unroll")                                                          \
            for (int mi = 0; mi < 2; mi++)                                             \
                _Pragma("unroll")                                                      \
                for (int ni = 0; ni < 8; ni++)                                         \
                    mma_bf16(acc[mi][ni], al_[mi][0], al_[mi][1], al_[mi][2],          \
                             al_[mi][3], bh_[ni][0], bh_[ni][1]);                      \
            _Pragma("unroll")                                                          \
            for (int mi = 0; mi < 2; mi++)                                             \
                _Pragma("unroll")                                                      \
                for (int ni = 0; ni < 8; ni++)                                         \
                    mma_bf16(acc[mi][ni], ah_[mi][0], ah_[mi][1], ah_[mi][2],          \
                             ah_[mi][3], bl_[ni][0], bl_[ni][1]);                      \
            _Pragma("unroll")                                                          \
            for (int mi = 0; mi < 2; mi++)                                             \
                _Pragma("unroll")                                                      \
                for (int ni = 0; ni < 8; ni++)                                         \
                    mma_bf16(acc[mi][ni], ah_[mi][0], ah_[mi][1], ah_[mi][2],          \
                             ah_[mi][3], bh_[ni][0], bh_[ni][1]);                      \
        }                                                                              \
    }

    LOAD_STAGE(0, 0)

    for (int kt = 0; kt < KT; kt += 2) {
        cp_async_wait0();
        __syncthreads();
        if (kt + 1 < KT) LOAD_STAGE(1, (kt + 1) << 6)
        COMPUTE_STAGE(0)

        cp_async_wait0();
        __syncthreads();
        if (kt + 2 < KT) LOAD_STAGE(0, (kt + 2) << 6)
        COMPUTE_STAGE(1)
    }

    // ---- epilogue ----
    #pragma unroll
    for (int mi = 0; mi < 2; mi++) {
        int row0 = m0 + wm + mi * 16 + grp;
        #pragma unroll
        for (int ni = 0; ni < 8; ni++) {
            int col = n0 + wn + ni * 8 + tig * 2;
            float b0 = bias[col], b1 = bias[col + 1];
            float v0 = acc[mi][ni][0] + b0;
            float v1 = acc[mi][ni][1] + b1;
            float v2 = acc[mi][ni][2] + b0;
            float v3 = acc[mi][ni][3] + b1;
            if (mode == 0) {
                *(float2*)(Cf + (size_t)row0 * N + col)       = make_float2(v0, v1);
                *(float2*)(Cf + (size_t)(row0 + 8) * N + col) = make_float2(v2, v3);
            } else {
                if (mode == 1) {
                    v0 = 0.5f * v0 * (1.0f + erff(v0 * 0.70710678118654752f));
                    v1 = 0.5f * v1 * (1.0f + erff(v1 * 0.70710678118654752f));
                    v2 = 0.5f * v2 * (1.0f + erff(v2 * 0.70710678118654752f));
                    v3 = 0.5f * v3 * (1.0f + erff(v3 * 0.70710678118654752f));
                } else {
                    float scq = (col < H_) ? 0.125f : 1.f;
                    v0 *= scq; v1 *= scq; v2 *= scq; v3 *= scq;
                }
                size_t o0 = (size_t)row0 * N + col;
                size_t o1 = (size_t)(row0 + 8) * N + col;
                uint32_t ph, pl;
                packsplit(v0, v1, ph, pl);
                *(uint32_t*)(Ch + o0) = ph; *(uint32_t*)(Cl + o0) = pl;
                packsplit(v2, v3, ph, pl);
                *(uint32_t*)(Ch + o1) = ph; *(uint32_t*)(Cl + o1) = pl;
            }
        }
    }
}

// ================= tensor-core local attention (mma.sync, R10 version) =====
#define QSTR 36
#define ATT_SMEM ((2 * 128 * QSTR + 4 * 64 * QSTR + 64) * 4)

__global__ __launch_bounds__(256, 1) void attn_tc_kernel(
    const bf16* __restrict__ Qh, const bf16* __restrict__ Ql,
    const int* __restrict__ amask,
    bf16* __restrict__ Ohi, bf16* __restrict__ Olo)
{
    extern __shared__ uint32_t sm[];
    const int OQH = 0;
    const int OQL = OQH + 128 * QSTR;
    const int OKH = OQL + 128 * QSTR;
    const int OKL = OKH + 64 * QSTR;
    const int OVH = OKL + 64 * QSTR;
    const int OVL = OVH + 64 * QSTR;
    const int OMF = OVL + 64 * QSTR;
    float* mf = (float*)(sm + OMF);

    const int q0 = blockIdx.x * 128;
    const int hh = blockIdx.y;
    const int b  = blockIdx.z;
    const int tid = threadIdx.x, warp = tid >> 5, lane = tid & 31;
    const int grp = lane >> 2, tig = lane & 3;
    const uint32_t base = (uint32_t)__cvta_generic_to_shared(sm);
    const unsigned FULL = 0xffffffffu;

    for (int idx = tid; idx < 128 * 8; idx += 256) {
        int r = idx >> 3, q4 = idx & 7;
        size_t off = (size_t)(b * S_ + q0 + r) * QKVS + hh * DH_;
        ((uint4*)(sm + OQH + r * QSTR))[q4] = ((const uint4*)(Qh + off))[q4];
        ((uint4*)(sm + OQL + r * QSTR))[q4] = ((const uint4*)(Ql + off))[q4];
    }
    __syncthreads();

    uint32_t qfh[4][4], qfl[4][4];
    {
        int arow = warp * 16 + (lane & 7) + ((lane >> 3) & 1) * 8;
        int ablk = lane >> 4;
        #pragma unroll
        for (int st = 0; st < 4; st++) {
            uint32_t ad = base + (OQH + arow * QSTR) * 4 + (st * 2 + ablk) * 16;
            ldsm_x4(qfh[st][0], qfh[st][1], qfh[st][2], qfh[st][3], ad);
            ldsm_x4(qfl[st][0], qfl[st][1], qfl[st][2], qfl[st][3],
                    ad + (OQL - OQH) * 4);
        }
    }

    float o[8][4];
    #pragma unroll
    for (int ni = 0; ni < 8; ni++)
        #pragma unroll
        for (int c = 0; c < 4; c++) o[ni][c] = 0.f;
    float m0 = -1e30f, m1 = -1e30f, l0 = 0.f, l1 = 0.f;

    const int brow = (lane & 7) + (lane >> 4) * 8;
    const int bblk = (lane >> 3) & 1;
    const int vrow = (lane & 7) + ((lane >> 3) & 1) * 8;
    const int vblk = lane >> 4;
    const int qg0 = q0 + warp * 16 + grp;
    const int qg1 = qg0 + 8;

    for (int kt = 0; kt < 10; kt++) {
        const int ks = q0 - 256 + kt * 64;
        if (ks + 64 <= 0 || ks >= S_) continue;
        __syncthreads();
        const uint4 z4 = make_uint4(0u, 0u, 0u, 0u);
        for (int idx = tid; idx < 64 * 8; idx += 256) {
            int c = idx >> 3, q4 = idx & 7;
            int kg = ks + c;
            uint4 kh = z4, kl = z4, vh = z4, vl = z4;
            if (kg >= 0 && kg < S_) {
                size_t off = (size_t)(b * S_ + kg) * QKVS + hh * DH_;
                kh = ((const uint4*)(Qh + off + H_))[q4];
                kl = ((const uint4*)(Ql + off + H_))[q4];
                vh = ((const uint4*)(Qh + off + 2 * H_))[q4];
                vl = ((const uint4*)(Ql + off + 2 * H_))[q4];
            }
            ((uint4*)(sm + OKH + c * QSTR))[q4] = kh;
            ((uint4*)(sm + OKL + c * QSTR))[q4] = kl;
            ((uint4*)(sm + OVH + c * QSTR))[q4] = vh;
            ((uint4*)(sm + OVL + c * QSTR))[q4] = vl;
        }
        if (tid < 64) {
            int kg = ks + tid;
            mf[tid] = (kg >= 0 && kg < S_ && amask[b * S_ + kg] > 0) ? 0.f : -1e9f;
        }
        __syncthreads();

        float s[8][4];
        #pragma unroll
        for (int ni = 0; ni < 8; ni++)
            #pragma unroll
            for (int c = 0; c < 4; c++) s[ni][c] = 0.f;
        #pragma unroll
        for (int st = 0; st < 4; st++) {
            uint32_t kbh[8][2], kbl[8][2];
            #pragma unroll
            for (int t = 0; t < 4; t++) {
                uint32_t ad = base + (OKH + (t * 16 + brow) * QSTR) * 4
                            + (st * 2 + bblk) * 16;
                ldsm_x4(kbh[2*t][0], kbh[2*t][1], kbh[2*t+1][0], kbh[2*t+1][1], ad);
                ldsm_x4(kbl[2*t][0], kbl[2*t][1], kbl[2*t+1][0], kbl[2*t+1][1],
                        ad + (OKL - OKH) * 4);
            }
            #pragma unroll
            for (int ni = 0; ni < 8; ni++)
                mma_bf16(s[ni], qfl[st][0], qfl[st][1], qfl[st][2], qfl[st][3],
                         kbh[ni][0], kbh[ni][1]);
            #pragma unroll
            for (int ni = 0; ni < 8; ni++)
                mma_bf16(s[ni], qfh[st][0], qfh[st][1], qfh[st][2], qfh[st][3],
                         kbl[ni][0], kbl[ni][1]);
            #pragma unroll
            for (int ni = 0; ni < 8; ni++)
                mma_bf16(s[ni], qfh[st][0], qfh[st][1], qfh[st][2], qfh[st][3],
                         kbh[ni][0], kbh[ni][1]);
        }

        float tmax0 = -1e30f, tmax1 = -1e30f;
        #pragma unroll
        for (int ni = 0; ni < 8; ni++) {
            int kl0 = ni * 8 + 2 * tig;
            float mv0 = mf[kl0], mv1 = mf[kl0 + 1];
            int kg0 = ks + kl0;
            int d00 = kg0 - qg0, d01 = d00 + 1;
            int d10 = kg0 - qg1, d11 = d10 + 1;
            float x0 = (d00 >= -WIN_ && d00 <= WIN_) ? s[ni][0] + mv0 : -1e9f;
            float x1 = (d01 >= -WIN_ && d01 <= WIN_) ? s[ni][1] + mv1 : -1e9f;
            float x2 = (d10 >= -WIN_ && d10 <= WIN_) ? s[ni][2] + mv0 : -1e9f;
            float x3 = (d11 >= -WIN_ && d11 <= WIN_) ? s[ni][3] + mv1 : -1e9f;
            s[ni][0] = x0; s[ni][1] = x1; s[ni][2] = x2; s[ni][3] = x3;
            tmax0 = fmaxf(tmax0, fmaxf(x0, x1));
            tmax1 = fmaxf(tmax1, fmaxf(x2, x3));
        }
        tmax0 = fmaxf(tmax0, __shfl_xor_sync(FULL, tmax0, 1));
        tmax0 = fmaxf(tmax0, __shfl_xor_sync(FULL, tmax0, 2));
        tmax1 = fmaxf(tmax1, __shfl_xor_sync(FULL, tmax1, 1));
        tmax1 = fmaxf(tmax1, __shfl_xor_sync(FULL, tmax1, 2));
        float mn0 = fmaxf(m0, tmax0), mn1 = fmaxf(m1, tmax1);
        float sc0 = __expf(m0 - mn0), sc1 = __expf(m1 - mn1);
        float ps0 = 0.f, ps1 = 0.f;
        #pragma unroll
        for (int ni = 0; ni < 8; ni++) {
            s[ni][0] = __expf(s[ni][0] - mn0);
            s[ni][1] = __expf(s[ni][1] - mn0);
            s[ni][2] = __expf(s[ni][2] - mn1);
            s[ni][3] = __expf(s[ni][3] - mn1);
            ps0 += s[ni][0] + s[ni][1];
            ps1 += s[ni][2] + s[ni][3];
        }
        ps0 += __shfl_xor_sync(FULL, ps0, 1);
        ps0 += __shfl_xor_sync(FULL, ps0, 2);
        ps1 += __shfl_xor_sync(FULL, ps1, 1);
        ps1 += __shfl_xor_sync(FULL, ps1, 2);
        l0 = l0 * sc0 + ps0;
        l1 = l1 * sc1 + ps1;
        m0 = mn0; m1 = mn1;
        #pragma unroll
        for (int ni = 0; ni < 8; ni++) {
            o[ni][0] *= sc0; o[ni][1] *= sc0;
            o[ni][2] *= sc1; o[ni][3] *= sc1;
        }

        uint32_t pah[4][4], pal[4][4];
        #pragma unroll
        for (int j = 0; j < 4; j++) {
            packsplit(s[2*j][0],   s[2*j][1],   pah[j][0], pal[j][0]);
            packsplit(s[2*j][2],   s[2*j][3],   pah[j][1], pal[j][1]);
            packsplit(s[2*j+1][0], s[2*j+1][1], pah[j][2], pal[j][2]);
            packsplit(s[2*j+1][2], s[2*j+1][3], pah[j][3], pal[j][3]);
        }

        #pragma unroll
        for (int j = 0; j < 4; j++) {
            uint32_t vbh[8][2], vbl[8][2];
            #pragma unroll
            for (int t = 0; t < 4; t++) {
                uint32_t ad = base + (OVH + (j * 16 + vrow) * QSTR) * 4
                            + (2 * t + vblk) * 16;
                ldsm_x4_t(vbh[2*t][0], vbh[2*t][1], vbh[2*t+1][0], vbh[2*t+1][1], ad);
                ldsm_x4_t(vbl[2*t][0], vbl[2*t][1], vbl[2*t+1][0], vbl[2*t+1][1],
                          ad + (OVL - OVH) * 4);
            }
            #pragma unroll
            for (int ni = 0; ni < 8; ni++)
                mma_bf16(o[ni], pal[j][0], pal[j][1], pal[j][2], pal[j][3],
                         vbh[ni][0], vbh[ni][1]);
            #pragma unroll
            for (int ni = 0; ni < 8; ni++)
                mma_bf16(o[ni], pah[j][0], pah[j][1], pah[j][2], pah[j][3],
                         vbl[ni][0], vbl[ni][1]);
            #pragma unroll
            for (int ni = 0; ni < 8; ni++)
                mma_bf16(o[ni], pah[j][0], pah[j][1], pah[j][2], pah[j][3],
                         vbh[ni][0], vbh[ni][1]);
        }
    }

    float inv0 = 1.f / l0, inv1 = 1.f / l1;
    #pragma unroll
    for (int ni = 0; ni < 8; ni++) {
        int dcol = hh * DH_ + ni * 8 + 2 * tig;
        size_t o0 = (size_t)(b * S_ + qg0) * H_ + dcol;
        size_t o1 = (size_t)(b * S_ + qg1) * H_ + dcol;
        uint32_t ph, pl;
        packsplit(o[ni][0] * inv0, o[ni][1] * inv0, ph, pl);
        *(uint32_t*)(Ohi + o0) = ph;
        *(uint32_t*)(Olo + o0) = pl;
        packsplit(o[ni][2] * inv1, o[ni][3] * inv1, ph, pl);
        *(uint32_t*)(Ohi + o1) = ph;
        *(uint32_t*)(Olo + o1) = pl;
    }
}

// ---------------- pooling head ----------------
__global__ __launch_bounds__(256) void attn_score_kernel(
    const float* __restrict__ h, const float* __restrict__ aw, float* __restrict__ sc)
{
    int t = blockIdx.x;
    int tid = threadIdx.x;
    float acc = 0.f;
    #pragma unroll
    for (int i = 0; i < 3; i++) {
        int c = tid + i * 256;
        acc += h[(size_t)t * H_ + c] * aw[c];
    }
    float s = block_reduce_sum(acc);
    if (tid == 0) sc[t] = s;
}

__global__ __launch_bounds__(256) void softmax_s_kernel(
    const float* __restrict__ sc, float* __restrict__ pr)
{
    int b = blockIdx.x;
    int tid = threadIdx.x;
    float v[4];
    float mx = -1e30f;
    #pragma unroll
    for (int i = 0; i < 4; i++) {
        v[i] = sc[b * S_ + tid + i * 256];
        mx = fmaxf(mx, v[i]);
    }
    mx = block_reduce_max(mx);
    float e[4], ps = 0.f;
    #pragma unroll
    for (int i = 0; i < 4; i++) { e[i] = __expf(v[i] - mx); ps += e[i]; }
    float tot = block_reduce_sum(ps);
    float inv = 1.f / tot;
    #pragma unroll
    for (int i = 0; i < 4; i++) pr[b * S_ + tid + i * 256] = e[i] * inv;
}

__global__ __launch_bounds__(256) void pool_kernel(
    const float* __restrict__ h, const float* __restrict__ pr, float* __restrict__ poolp)
{
    int d = blockIdx.x * 256 + threadIdx.x;
    int b = blockIdx.y;
    int p = blockIdx.z;
    float acc = 0.f;
    int s0 = p * (S_ / 8);
    for (int s = s0; s < s0 + S_ / 8; s++) {
        acc += h[((size_t)(b * S_ + s)) * H_ + d] * pr[b * S_ + s];
    }
    poolp[((size_t)p * B_ + b) * H_ + d] = acc;
}

__global__ __launch_bounds__(256) void final_kernel(
    const float* __restrict__ poolp, const float* __restrict__ Wc,
    const float* __restrict__ bc, float* __restrict__ out)
{
    int b = blockIdx.x;
    int tid = threadIdx.x;
    float acc = 0.f;
    #pragma unroll
    for (int i = 0; i < 3; i++) {
        int c = tid + i * 256;
        float pv = 0.f;
        #pragma unroll
        for (int p = 0; p < 8; p++)
            pv += poolp[((size_t)p * B_ + b) * H_ + c];
        acc += pv * Wc[c];
    }
    float s = block_reduce_sum(acc);
    if (tid == 0) out[b] = s + bc[0];
}

// ---------------- host launcher ----------------
extern "C" void kernel_launch(void* const* d_in, const int* in_sizes, int n_in,
                              void* d_out, int out_size)
{
    (void)in_sizes; (void)n_in; (void)out_size;
    const float* WE   = (const float*)d_in[0];
    const float* PE   = (const float*)d_in[1];
    const float* Eg   = (const float*)d_in[2];
    const float* Eb   = (const float*)d_in[3];
    const float* Wq   = (const float*)d_in[4];
    const float* bq   = (const float*)d_in[5];
    const float* Wk   = (const float*)d_in[6];
    const float* bk   = (const float*)d_in[7];
    const float* Wv   = (const float*)d_in[8];
    const float* bv   = (const float*)d_in[9];
    const float* Wo   = (const float*)d_in[10];
    const float* bo   = (const float*)d_in[11];
    const float* g1   = (const float*)d_in[12];
    const float* beta1= (const float*)d_in[13];
    const float* W1   = (const float*)d_in[14];
    const float* b1   = (const float*)d_in[15];
    const float* W2   = (const float*)d_in[16];
    const float* b2   = (const float*)d_in[17];
    const float* g2   = (const float*)d_in[18];
    const float* beta2= (const float*)d_in[19];
    const float* aw   = (const float*)d_in[20];
    const float* Wc   = (const float*)d_in[21];
    const float* bc   = (const float*)d_in[22];
    const int*   ids  = (const int*)d_in[23];
    const int*   am   = (const int*)d_in[24];
    float* out = (float*)d_out;

    bf16 *wqkv_hi, *wqkv_lo, *wot_hi, *wot_lo, *w1t_hi, *w1t_lo, *w2t_hi, *w2t_lo;
    bf16 *h_hi, *h_lo, *a_hi, *a_lo, *f_hi, *f_lo, *qkvh, *qkvl;
    float *bqkv, *h, *r, *sc, *pr, *poolp;
    cudaGetSymbolAddress((void**)&wqkv_hi, g_wqkv_hi);
    cudaGetSymbolAddress((void**)&wqkv_lo, g_wqkv_lo);
    cudaGetSymbolAddress((void**)&wot_hi,  g_wot_hi);
    cudaGetSymbolAddress((void**)&wot_lo,  g_wot_lo);
    cudaGetSymbolAddress((void**)&w1t_hi,  g_w1t_hi);
    cudaGetSymbolAddress((void**)&w1t_lo,  g_w1t_lo);
    cudaGetSymbolAddress((void**)&w2t_hi,  g_w2t_hi);
    cudaGetSymbolAddress((void**)&w2t_lo,  g_w2t_lo);
    cudaGetSymbolAddress((void**)&bqkv,    g_bqkv);
    cudaGetSymbolAddress((void**)&h,       g_h);
    cudaGetSymbolAddress((void**)&h_hi,    g_h_hi);
    cudaGetSymbolAddress((void**)&h_lo,    g_h_lo);
    cudaGetSymbolAddress((void**)&qkvh,    g_qkvh);
    cudaGetSymbolAddress((void**)&qkvl,    g_qkvl);
    cudaGetSymbolAddress((void**)&a_hi,    g_a_hi);
    cudaGetSymbolAddress((void**)&a_lo,    g_a_lo);
    cudaGetSymbolAddress((void**)&f_hi,    g_f_hi);
    cudaGetSymbolAddress((void**)&f_lo,    g_f_lo);
    cudaGetSymbolAddress((void**)&r,       g_r);
    cudaGetSymbolAddress((void**)&sc,      g_sc);
    cudaGetSymbolAddress((void**)&pr,      g_pr);
    cudaGetSymbolAddress((void**)&poolp,   g_poolp);

    cudaFuncSetAttribute(tgemm_kernel,
                         cudaFuncAttributeMaxDynamicSharedMemorySize, GSMEM);
    cudaFuncSetAttribute(attn_tc_kernel,
                         cudaFuncAttributeMaxDynamicSharedMemorySize, ATT_SMEM);

    // ---- pre-pass (QKV GEMM at launch idx 3 for ncu) ----
    dim3 wb(256);
    wsplit_qkv_kernel<<<dim3(H_ / 32, H_ / 32, 3 * L_), wb>>>(Wq, Wk, Wv,
                                                              wqkv_hi, wqkv_lo);
    embed_ln_kernel<<<BS_ + L_, 256>>>(WE, PE, Eg, Eb, ids, h, h_hi, h_lo,
                                       bq, bk, bv, bqkv);
    wsplit_kernel<<<dim3(H_ / 32, H_ / 32, L_), wb>>>(Wo, wot_hi, wot_lo, H_, H_,
        (size_t)H_ * H_, (size_t)H_ * H_);

    dim3 gQKV(QKVS / 128, BS_ / 128);   // (18, 32)
    dim3 gO(H_ / 128, BS_ / 128);       // (6, 32)
    dim3 gW1(FF_ / 128, BS_ / 128);     // (24, 32)
    dim3 gattn(S_ / 128, NH_, B_);

    // layer 0 QKV GEMM first (launch idx 3), remaining wsplits after it
    tgemm_kernel<<<gQKV, 256, GSMEM>>>(h_hi, h_lo,
        wqkv_hi, wqkv_lo, bqkv, nullptr, qkvh, qkvl, BS_, QKVS, H_, 2);
    wsplit_kernel<<<dim3(FF_ / 32, H_ / 32, L_), wb>>>(W1, w1t_hi, w1t_lo, H_, FF_,
        (size_t)H_ * FF_, (size_t)FF_ * H_);
    wsplit_kernel<<<dim3(H_ / 32, FF_ / 32, L_), wb>>>(W2, w2t_hi, w2t_lo, FF_, H_,
        (size_t)FF_ * H_, (size_t)H_ * FF_);

    for (int l = 0; l < L_; l++) {
        if (l > 0) {
            tgemm_kernel<<<gQKV, 256, GSMEM>>>(h_hi, h_lo,
                wqkv_hi + (size_t)l * QKVS * H_, wqkv_lo + (size_t)l * QKVS * H_,
                bqkv + l * QKVS, nullptr, qkvh, qkvl, BS_, QKVS, H_, 2);
        }

        attn_tc_kernel<<<gattn, 256, ATT_SMEM>>>(qkvh, qkvl, am, a_hi, a_lo);

        tgemm_kernel<<<gO, 256, GSMEM>>>(a_hi, a_lo,
            wot_hi + (size_t)l * H_ * H_, wot_lo + (size_t)l * H_ * H_,
            bo + l * H_, r, nullptr, nullptr, BS_, H_, H_, 0);
        add_ln_kernel<<<BS_, 256>>>(h, r, g1 + l * H_, beta1 + l * H_, h_hi, h_lo);

        tgemm_kernel<<<gW1, 256, GSMEM>>>(h_hi, h_lo,
            w1t_hi + (size_t)l * FF_ * H_, w1t_lo + (size_t)l * FF_ * H_,
            b1 + l * FF_, nullptr, f_hi, f_lo, BS_, FF_, H_, 1);

        tgemm_kernel<<<gO, 256, GSMEM>>>(f_hi, f_lo,
            w2t_hi + (size_t)l * H_ * FF_, w2t_lo + (size_t)l * H_ * FF_,
            b2 + l * H_, r, nullptr, nullptr, BS_, H_, FF_, 0);
        add_ln_kernel<<<BS_, 256>>>(h, r, g2 + l * H_, beta2 + l * H_, h_hi, h_lo);
    }

    attn_score_kernel<<<BS_, 256>>>(h, aw, sc);
    softmax_s_kernel<<<B_, 256>>>(sc, pr);
    pool_kernel<<<dim3(H_ / 256, B_, 8), 256>>>(h, pr, poolp);
    final_kernel<<<B_, 256>>>(poolp, Wc, bc, out);
}

// round 16
// speedup vs baseline: 1.1189x; 1.0894x over previous
#include <cuda_runtime.h>
#include <cuda_bf16.h>
#include <cstdint>
#include <math.h>

#define L_  12
#define NH_ 12
#define DH_ 64
#define H_  768
#define FF_ 3072
#define S_  1024
#define B_  4
#define BS_ (B_ * S_)   // 4096
#define WIN_ 256
#define QKVS 2304       // fused qkv row stride

typedef __nv_bfloat16 bf16;

// ---------------- scratch (no allocations allowed) ----------------
__device__ bf16 g_wqkv_hi[L_ * QKVS * H_];
__device__ bf16 g_wqkv_lo[L_ * QKVS * H_];
__device__ bf16 g_wot_hi [L_ * H_ * H_];
__device__ bf16 g_wot_lo [L_ * H_ * H_];
__device__ bf16 g_w1t_hi [L_ * FF_ * H_];
__device__ bf16 g_w1t_lo [L_ * FF_ * H_];
__device__ bf16 g_w2t_hi [L_ * H_ * FF_];
__device__ bf16 g_w2t_lo [L_ * H_ * FF_];
__device__ float g_bqkv  [L_ * QKVS];

__device__ float g_h    [BS_ * H_];
__device__ bf16  g_h_hi [BS_ * H_];
__device__ bf16  g_h_lo [BS_ * H_];
__device__ bf16  g_qkvh [BS_ * QKVS];
__device__ bf16  g_qkvl [BS_ * QKVS];
__device__ bf16  g_a_hi [BS_ * H_];
__device__ bf16  g_a_lo [BS_ * H_];
__device__ bf16  g_f_hi [BS_ * FF_];
__device__ bf16  g_f_lo [BS_ * FF_];
__device__ float g_r    [BS_ * H_];
__device__ float g_sc   [BS_];
__device__ float g_pr   [BS_];
__device__ float g_poolp[8 * B_ * H_];

__device__ __forceinline__ void split_bf16(float x, bf16& hi, bf16& lo) {
    hi = __float2bfloat16_rn(x);
    lo = __float2bfloat16_rn(x - __bfloat162float(hi));
}

// ---------------- low-level helpers ----------------
__device__ __forceinline__ void cp_async16(uint32_t smem_addr, const void* gptr) {
    asm volatile("cp.async.cg.shared.global [%0], [%1], 16;\n"
                 :: "r"(smem_addr), "l"(gptr));
}
__device__ __forceinline__ void cp_async_commit() {
    asm volatile("cp.async.commit_group;\n");
}
__device__ __forceinline__ void cp_async_wait0() {
    asm volatile("cp.async.wait_group 0;\n");
}
__device__ __forceinline__ void ldsm_x4(uint32_t& r0, uint32_t& r1, uint32_t& r2,
                                        uint32_t& r3, uint32_t a) {
    asm volatile("ldmatrix.sync.aligned.m8n8.x4.shared.b16 {%0,%1,%2,%3}, [%4];"
                 : "=r"(r0), "=r"(r1), "=r"(r2), "=r"(r3) : "r"(a));
}
__device__ __forceinline__ void ldsm_x4_t(uint32_t& r0, uint32_t& r1, uint32_t& r2,
                                          uint32_t& r3, uint32_t a) {
    asm volatile("ldmatrix.sync.aligned.m8n8.x4.trans.shared.b16 {%0,%1,%2,%3}, [%4];"
                 : "=r"(r0), "=r"(r1), "=r"(r2), "=r"(r3) : "r"(a));
}
__device__ __forceinline__ void mma_bf16(
    float* acc, uint32_t a0, uint32_t a1, uint32_t a2, uint32_t a3,
    uint32_t b0, uint32_t b1)
{
    asm volatile(
        "mma.sync.aligned.m16n8k16.row.col.f32.bf16.bf16.f32 "
        "{%0,%1,%2,%3}, {%4,%5,%6,%7}, {%8,%9}, {%0,%1,%2,%3};\n"
        : "+f"(acc[0]), "+f"(acc[1]), "+f"(acc[2]), "+f"(acc[3])
        : "r"(a0), "r"(a1), "r"(a2), "r"(a3), "r"(b0), "r"(b1));
}
__device__ __forceinline__ void packsplit(float a, float b, uint32_t& ph, uint32_t& pl) {
    bf16 ah = __float2bfloat16_rn(a), bh = __float2bfloat16_rn(b);
    float al = a - __bfloat162float(ah), bl = b - __bfloat162float(bh);
    ph = ((uint32_t)__bfloat16_as_ushort(bh) << 16) | (uint32_t)__bfloat16_as_ushort(ah);
    pl = ((uint32_t)__bfloat16_as_ushort(__float2bfloat16_rn(bl)) << 16)
       |  (uint32_t)__bfloat16_as_ushort(__float2bfloat16_rn(al));
}

// ---------------- reduction helpers ----------------
__device__ __forceinline__ float block_reduce_sum(float v) {
    __shared__ float red[32];
    int lane = threadIdx.x & 31, wid = threadIdx.x >> 5;
    #pragma unroll
    for (int o = 16; o; o >>= 1) v += __shfl_xor_sync(0xffffffffu, v, o);
    if (lane == 0) red[wid] = v;
    __syncthreads();
    int nw = (blockDim.x + 31) >> 5;
    v = (threadIdx.x < nw) ? red[threadIdx.x] : 0.f;
    if (wid == 0) {
        #pragma unroll
        for (int o = 16; o; o >>= 1) v += __shfl_xor_sync(0xffffffffu, v, o);
    }
    if (threadIdx.x == 0) red[0] = v;
    __syncthreads();
    v = red[0];
    __syncthreads();
    return v;
}

__device__ __forceinline__ float2 block_reduce_sum2(float a, float b) {
    __shared__ float2 red[32];
    int lane = threadIdx.x & 31, wid = threadIdx.x >> 5;
    #pragma unroll
    for (int o = 16; o; o >>= 1) {
        a += __shfl_xor_sync(0xffffffffu, a, o);
        b += __shfl_xor_sync(0xffffffffu, b, o);
    }
    if (lane == 0) red[wid] = make_float2(a, b);
    __syncthreads();
    int nw = (blockDim.x + 31) >> 5;
    float2 t = (threadIdx.x < nw) ? red[threadIdx.x] : make_float2(0.f, 0.f);
    if (wid == 0) {
        #pragma unroll
        for (int o = 16; o; o >>= 1) {
            t.x += __shfl_xor_sync(0xffffffffu, t.x, o);
            t.y += __shfl_xor_sync(0xffffffffu, t.y, o);
        }
    }
    if (threadIdx.x == 0) red[0] = t;
    __syncthreads();
    t = red[0];
    __syncthreads();
    return t;
}

__device__ __forceinline__ float block_reduce_max(float v) {
    __shared__ float red[32];
    int lane = threadIdx.x & 31, wid = threadIdx.x >> 5;
    #pragma unroll
    for (int o = 16; o; o >>= 1) v = fmaxf(v, __shfl_xor_sync(0xffffffffu, v, o));
    if (lane == 0) red[wid] = v;
    __syncthreads();
    int nw = (blockDim.x + 31) >> 5;
    v = (threadIdx.x < nw) ? red[threadIdx.x] : -1e30f;
    if (wid == 0) {
        #pragma unroll
        for (int o = 16; o; o >>= 1) v = fmaxf(v, __shfl_xor_sync(0xffffffffu, v, o));
    }
    if (threadIdx.x == 0) red[0] = v;
    __syncthreads();
    v = red[0];
    __syncthreads();
    return v;
}

// ---------------- weight transpose + hi/lo split ----------------
__global__ __launch_bounds__(256) void wsplit_kernel(
    const float* __restrict__ src, bf16* __restrict__ dhi, bf16* __restrict__ dlo,
    int K, int N, size_t srcStride, size_t dstStride)
{
    __shared__ float t[32][33];
    int l = blockIdx.z;
    src += (size_t)l * srcStride;
    dhi += (size_t)l * dstStride;
    dlo += (size_t)l * dstStride;
    int tx = threadIdx.x & 31, ty = threadIdx.x >> 5;
    int n0 = blockIdx.x * 32, k0 = blockIdx.y * 32;
    #pragma unroll
    for (int i = 0; i < 4; i++)
        t[ty + i * 8][tx] = src[(size_t)(k0 + ty + i * 8) * N + n0 + tx];
    __syncthreads();
    #pragma unroll
    for (int i = 0; i < 4; i++) {
        int r = ty + i * 8;
        float x = t[tx][r];
        bf16 hi, lo; split_bf16(x, hi, lo);
        size_t o = (size_t)(n0 + r) * K + k0 + tx;
        dhi[o] = hi; dlo[o] = lo;
    }
}

__global__ __launch_bounds__(256) void wsplit_qkv_kernel(
    const float* __restrict__ Wq, const float* __restrict__ Wk,
    const float* __restrict__ Wv, bf16* __restrict__ dhi, bf16* __restrict__ dlo)
{
    __shared__ float t[32][33];
    int z = blockIdx.z;
    int l = z / 3, j = z % 3;
    const float* src = (j == 0 ? Wq : (j == 1 ? Wk : Wv)) + (size_t)l * H_ * H_;
    bf16* oh = dhi + (size_t)l * QKVS * H_ + (size_t)j * H_ * H_;
    bf16* ol = dlo + (size_t)l * QKVS * H_ + (size_t)j * H_ * H_;
    int tx = threadIdx.x & 31, ty = threadIdx.x >> 5;
    int n0 = blockIdx.x * 32, k0 = blockIdx.y * 32;
    #pragma unroll
    for (int i = 0; i < 4; i++)
        t[ty + i * 8][tx] = src[(size_t)(k0 + ty + i * 8) * H_ + n0 + tx];
    __syncthreads();
    #pragma unroll
    for (int i = 0; i < 4; i++) {
        int r = ty + i * 8;
        float x = t[tx][r];
        bf16 hi, lo; split_bf16(x, hi, lo);
        size_t o = (size_t)(n0 + r) * H_ + k0 + tx;
        oh[o] = hi; ol[o] = lo;
    }
}

// ---------------- embedding + LN (+ fused qkv-bias concat) ----------------
__global__ __launch_bounds__(256) void embed_ln_kernel(
    const float* __restrict__ WE, const float* __restrict__ PE,
    const float* __restrict__ g, const float* __restrict__ be,
    const int* __restrict__ ids,
    float* __restrict__ out, bf16* __restrict__ ohi, bf16* __restrict__ olo,
    const float* __restrict__ bq, const float* __restrict__ bk,
    const float* __restrict__ bv, float* __restrict__ bqkv)
{
    int t = blockIdx.x;
    int tid = threadIdx.x;
    if (t >= BS_) {
        int l = t - BS_;
        for (int n = tid; n < QKVS; n += 256) {
            float v;
            if (n < H_)          v = bq[l * H_ + n];
            else if (n < 2 * H_) v = bk[l * H_ + n - H_];
            else                 v = bv[l * H_ + n - 2 * H_];
            bqkv[l * QKVS + n] = v;
        }
        return;
    }
    int s = t & (S_ - 1);
    int id = ids[t];
    float v[3];
    float s1 = 0.f, s2 = 0.f;
    #pragma unroll
    for (int i = 0; i < 3; i++) {
        int c = tid + i * 256;
        v[i] = WE[(size_t)id * H_ + c] + PE[(size_t)s * H_ + c];
        s1 += v[i]; s2 += v[i] * v[i];
    }
    float2 red = block_reduce_sum2(s1, s2);
    float m = red.x * (1.f / H_);
    float var = red.y * (1.f / H_) - m * m;
    float rs = rsqrtf(var + 1e-5f);
    #pragma unroll
    for (int i = 0; i < 3; i++) {
        int c = tid + i * 256;
        float y = (v[i] - m) * rs * g[c] + be[c];
        size_t o = (size_t)t * H_ + c;
        out[o] = y;
        bf16 hi, lo; split_bf16(y, hi, lo);
        ohi[o] = hi; olo[o] = lo;
    }
}

// ---------------- residual add + LN (in-place on h) ----------------
__global__ __launch_bounds__(256) void add_ln_kernel(
    float* __restrict__ h, const float* __restrict__ r,
    const float* __restrict__ g, const float* __restrict__ be,
    bf16* __restrict__ ohi, bf16* __restrict__ olo)
{
    int t = blockIdx.x;
    int tid = threadIdx.x;
    float v[3];
    float s1 = 0.f, s2 = 0.f;
    #pragma unroll
    for (int i = 0; i < 3; i++) {
        int c = tid + i * 256;
        size_t o = (size_t)t * H_ + c;
        v[i] = h[o] + r[o];
        s1 += v[i]; s2 += v[i] * v[i];
    }
    float2 red = block_reduce_sum2(s1, s2);
    float m = red.x * (1.f / H_);
    float var = red.y * (1.f / H_) - m * m;
    float rs = rsqrtf(var + 1e-5f);
    #pragma unroll
    for (int i = 0; i < 3; i++) {
        int c = tid + i * 256;
        float y = (v[i] - m) * rs * g[c] + be[c];
        size_t o = (size_t)t * H_ + c;
        h[o] = y;
        bf16 hi, lo; split_bf16(y, hi, lo);
        ohi[o] = hi; olo[o] = lo;
    }
}

// ================= bf16x3 tensor-core GEMM (BK=64, 128x128) ===============
#define PSTR 36                 // uint32 per row (32 data + 4 pad)
#define STG  (128 * PSTR)       // uint32 per data tile (18KB)
#define GSMEM (8 * STG * 4)     // 2 stages x 4 tiles = 147456 B

__global__ __launch_bounds__(256) void tgemm_kernel(
    const bf16* __restrict__ Ah, const bf16* __restrict__ Al,
    const bf16* __restrict__ Bh, const bf16* __restrict__ Bl,
    const float* __restrict__ bias,
    float* __restrict__ Cf, bf16* __restrict__ Ch, bf16* __restrict__ Cl,
    int M, int N, int K, int mode)
{
    extern __shared__ uint32_t smem_u[];

    const int tid  = threadIdx.x;
    const int warp = tid >> 5;
    const int lane = tid & 31;
    const int m0 = blockIdx.y * 128;
    const int n0 = blockIdx.x * 128;
    const int wm = (warp >> 1) * 32;
    const int wn = (warp & 1) * 64;
    const int grp = lane >> 2;
    const int tig = lane & 3;
    const uint32_t smbase = (uint32_t)__cvta_generic_to_shared(smem_u);

    const int aRow = wm + (lane & 7) + ((lane >> 3) & 1) * 8;
    const int aBlk = lane >> 4;
    const int bRow = wn + (lane & 7) + (lane >> 4) * 8;
    const int bBlk = (lane >> 3) & 1;

    float acc[2][8][4];
    #pragma unroll
    for (int mi = 0; mi < 2; mi++)
        #pragma unroll
        for (int ni = 0; ni < 8; ni++)
            #pragma unroll
            for (int c = 0; c < 4; c++) acc[mi][ni][c] = 0.f;

    const int KT = K >> 6;     // BK = 64; KT = 12 or 48 (even)

    #define LOAD_STAGE(S, k0)                                                          \
    {                                                                                  \
        _Pragma("unroll")                                                              \
        for (int r = 0; r < 4; r++) {                                                  \
            int idx = tid + r * 256;                                                   \
            int row = idx >> 3, c = idx & 7;                                           \
            uint32_t doff = ((S) * 4 * STG + row * PSTR + c * 4) * 4;                  \
            size_t aoff = (size_t)(m0 + row) * K + (k0) + c * 8;                       \
            size_t boff = (size_t)(n0 + row) * K + (k0) + c * 8;                       \
            cp_async16(smbase + doff,               Ah + aoff);                        \
            cp_async16(smbase + doff + STG * 4,     Al + aoff);                        \
            cp_async16(smbase + doff + 2 * STG * 4, Bh + boff);                        \
            cp_async16(smbase + doff + 3 * STG * 4, Bl + boff);                        \
        }                                                                              \
        cp_async_commit();                                                             \
    }

    #define COMPUTE_STAGE(S)                                                           \
    {                                                                                  \
        const uint32_t sb = smbase + (uint32_t)((S) * 4 * STG) * 4;                    \
        _Pragma("unroll")                                                              \
        for (int st = 0; st < 4; st++) {                                               \
            uint32_t ah_[2][4], al_[2][4];                                             \
            _Pragma("unroll")                                                          \
            for (int mi = 0; mi < 2; mi++) {                                           \
                uint32_t ad = sb + ((aRow + mi * 16) * PSTR) * 4                       \
                            + (st * 2 + aBlk) * 16;                                    \
                ldsm_x4(ah_[mi][0], ah_[mi][1], ah_[mi][2], ah_[mi][3], ad);           \
                ldsm_x4(al_[mi][0], al_[mi][1], al_[mi][2], al_[mi][3],                \
                        ad + STG * 4);                                                 \
            }                                                                          \
            uint32_t bh_[8][2], bl_[8][2];                                             \
            _Pragma("unroll")                                                          \
            for (int t = 0; t < 4; t++) {                                              \
                uint32_t ad = sb + 2 * STG * 4 + ((bRow + t * 16) * PSTR) * 4          \
                            + (st * 2 + bBlk) * 16;                                    \
                ldsm_x4(bh_[2*t][0], bh_[2*t][1], bh_[2*t+1][0], bh_[2*t+1][1], ad);   \
                ldsm_x4(bl_[2*t][0], bl_[2*t][1], bl_[2*t+1][0], bl_[2*t+1][1],        \
                        ad + STG * 4);                                                 \
            }                                                                          \
            _Pragma("unroll")                                                          \
            for (int mi = 0; mi < 2; mi++)                                             \
                _Pragma("unroll")                                                      \
                for (int ni = 0; ni < 8; ni++)                                         \
                    mma_bf16(acc[mi][ni], al_[mi][0], al_[mi][1], al_[mi][2],          \
                             al_[mi][3], bh_[ni][0], bh_[ni][1]);                      \
            _Pragma("unroll")                                                          \
            for (int mi = 0; mi < 2; mi++)                                             \
                _Pragma("unroll")                                                      \
                for (int ni = 0; ni < 8; ni++)                                         \
                    mma_bf16(acc[mi][ni], ah_[mi][0], ah_[mi][1], ah_[mi][2],          \
                             ah_[mi][3], bl_[ni][0], bl_[ni][1]);                      \
            _Pragma("unroll")                                                          \
            for (int mi = 0; mi < 2; mi++)                                             \
                _Pragma("unroll")                                                      \
                for (int ni = 0; ni < 8; ni++)                                         \
                    mma_bf16(acc[mi][ni], ah_[mi][0], ah_[mi][1], ah_[mi][2],          \
                             ah_[mi][3], bh_[ni][0], bh_[ni][1]);                      \
        }                                                                              \
    }

    LOAD_STAGE(0, 0)

    for (int kt = 0; kt < KT; kt += 2) {
        cp_async_wait0();
        __syncthreads();
        if (kt + 1 < KT) LOAD_STAGE(1, (kt + 1) << 6)
        COMPUTE_STAGE(0)

        cp_async_wait0();
        __syncthreads();
        if (kt + 2 < KT) LOAD_STAGE(0, (kt + 2) << 6)
        COMPUTE_STAGE(1)
    }

    // ---- epilogue ----
    #pragma unroll
    for (int mi = 0; mi < 2; mi++) {
        int row0 = m0 + wm + mi * 16 + grp;
        #pragma unroll
        for (int ni = 0; ni < 8; ni++) {
            int col = n0 + wn + ni * 8 + tig * 2;
            float b0 = bias[col], b1 = bias[col + 1];
            float v0 = acc[mi][ni][0] + b0;
            float v1 = acc[mi][ni][1] + b1;
            float v2 = acc[mi][ni][2] + b0;
            float v3 = acc[mi][ni][3] + b1;
            if (mode == 0) {
                *(float2*)(Cf + (size_t)row0 * N + col)       = make_float2(v0, v1);
                *(float2*)(Cf + (size_t)(row0 + 8) * N + col) = make_float2(v2, v3);
            } else {
                if (mode == 1) {
                    v0 = 0.5f * v0 * (1.0f + erff(v0 * 0.70710678118654752f));
                    v1 = 0.5f * v1 * (1.0f + erff(v1 * 0.70710678118654752f));
                    v2 = 0.5f * v2 * (1.0f + erff(v2 * 0.70710678118654752f));
                    v3 = 0.5f * v3 * (1.0f + erff(v3 * 0.70710678118654752f));
                } else {
                    float scq = (col < H_) ? 0.125f : 1.f;
                    v0 *= scq; v1 *= scq; v2 *= scq; v3 *= scq;
                }
                size_t o0 = (size_t)row0 * N + col;
                size_t o1 = (size_t)(row0 + 8) * N + col;
                uint32_t ph, pl;
                packsplit(v0, v1, ph, pl);
                *(uint32_t*)(Ch + o0) = ph; *(uint32_t*)(Cl + o0) = pl;
                packsplit(v2, v3, ph, pl);
                *(uint32_t*)(Ch + o1) = ph; *(uint32_t*)(Cl + o1) = pl;
            }
        }
    }
}

// ================= bf16x3 GEMM, 64x128 tile (narrow-N wave smoothing) =====
// 8 warps as 2(m) x 4(n); warp tile 32x32. fp32-out only (mode 0 GEMMs).
#define STGA64 (64 * PSTR)
#define STGB64 (128 * PSTR)
#define STG64  (2 * STGA64 + 2 * STGB64)
#define GSMEM64 (2 * STG64 * 4)   // 110592 B

__global__ __launch_bounds__(256) void tgemm64_kernel(
    const bf16* __restrict__ Ah, const bf16* __restrict__ Al,
    const bf16* __restrict__ Bh, const bf16* __restrict__ Bl,
    const float* __restrict__ bias, float* __restrict__ Cf,
    int M, int N, int K)
{
    extern __shared__ uint32_t smem_u[];

    const int tid  = threadIdx.x;
    const int warp = tid >> 5;
    const int lane = tid & 31;
    const int m0 = blockIdx.y * 64;
    const int n0 = blockIdx.x * 128;
    const int wm = (warp >> 2) * 32;       // 0 or 32
    const int wn = (warp & 3) * 32;        // 0,32,64,96
    const int grp = lane >> 2;
    const int tig = lane & 3;
    const uint32_t smbase = (uint32_t)__cvta_generic_to_shared(smem_u);

    const int aRow = wm + (lane & 7) + ((lane >> 3) & 1) * 8;
    const int aBlk = lane >> 4;
    const int bRow = wn + (lane & 7) + (lane >> 4) * 8;
    const int bBlk = (lane >> 3) & 1;

    float acc[2][4][4];
    #pragma unroll
    for (int mi = 0; mi < 2; mi++)
        #pragma unroll
        for (int ni = 0; ni < 4; ni++)
            #pragma unroll
            for (int c = 0; c < 4; c++) acc[mi][ni][c] = 0.f;

    const int KT = K >> 6;     // even (12 or 48)

    // stage: Ah(STGA64) | Al(STGA64) | Bh(STGB64) | Bl(STGB64)
    #define LOAD_STAGE64(S, k0)                                                        \
    {                                                                                  \
        _Pragma("unroll")                                                              \
        for (int r = 0; r < 2; r++) {                                                  \
            int idx = tid + r * 256;                                                   \
            int row = idx >> 3, c = idx & 7;                                           \
            uint32_t doff = ((S) * STG64 + row * PSTR + c * 4) * 4;                    \
            size_t aoff = (size_t)(m0 + row) * K + (k0) + c * 8;                       \
            cp_async16(smbase + doff,              Ah + aoff);                         \
            cp_async16(smbase + doff + STGA64 * 4, Al + aoff);                         \
        }                                                                              \
        _Pragma("unroll")                                                              \
        for (int r = 0; r < 4; r++) {                                                  \
            int idx = tid + r * 256;                                                   \
            int row = idx >> 3, c = idx & 7;                                           \
            uint32_t doff = ((S) * STG64 + 2 * STGA64 + row * PSTR + c * 4) * 4;       \
            size_t boff = (size_t)(n0 + row) * K + (k0) + c * 8;                       \
            cp_async16(smbase + doff,              Bh + boff);                         \
            cp_async16(smbase + doff + STGB64 * 4, Bl + boff);                         \
        }                                                                              \
        cp_async_commit();                                                             \
    }

    #define COMPUTE_STAGE64(S)                                                         \
    {                                                                                  \
        const uint32_t sb = smbase + (uint32_t)((S) * STG64) * 4;                      \
        _Pragma("unroll")                                                              \
        for (int st = 0; st < 4; st++) {                                               \
            uint32_t ah_[2][4], al_[2][4];                                             \
            _Pragma("unroll")                                                          \
            for (int mi = 0; mi < 2; mi++) {                                           \
                uint32_t ad = sb + ((aRow + mi * 16) * PSTR) * 4                       \
                            + (st * 2 + aBlk) * 16;                                    \
                ldsm_x4(ah_[mi][0], ah_[mi][1], ah_[mi][2], ah_[mi][3], ad);           \
                ldsm_x4(al_[mi][0], al_[mi][1], al_[mi][2], al_[mi][3],                \
                        ad + STGA64 * 4);                                              \
            }                                                                          \
            uint32_t bh_[4][2], bl_[4][2];                                             \
            _Pragma("unroll")                                                          \
            for (int t = 0; t < 2; t++) {                                              \
                uint32_t ad = sb + 2 * STGA64 * 4 + ((bRow + t * 16) * PSTR) * 4       \
                            + (st * 2 + bBlk) * 16;                                    \
                ldsm_x4(bh_[2*t][0], bh_[2*t][1], bh_[2*t+1][0], bh_[2*t+1][1], ad);   \
                ldsm_x4(bl_[2*t][0], bl_[2*t][1], bl_[2*t+1][0], bl_[2*t+1][1],        \
                        ad + STGB64 * 4);                                              \
            }                                                                          \
            _Pragma("unroll")                                                          \
            for (int mi = 0; mi < 2; mi++)                                             \
                _Pragma("unroll")                                                      \
                for (int ni = 0; ni < 4; ni++)                                         \
                    mma_bf16(acc[mi][ni], al_[mi][0], al_[mi][1], al_[mi][2],          \
                             al_[mi][3], bh_[ni][0], bh_[ni][1]);                      \
            _Pragma("unroll")                                                          \
            for (int mi = 0; mi < 2; mi++)                                             \
                _Pragma("unroll")                                                      \
                for (int ni = 0; ni < 4; ni++)                                         \
                    mma_bf16(acc[mi][ni], ah_[mi][0], ah_[mi][1], ah_[mi][2],          \
                             ah_[mi][3], bl_[ni][0], bl_[ni][1]);                      \
            _Pragma("unroll")                                                          \
            for (int mi = 0; mi < 2; mi++)                                             \
                _Pragma("unroll")                                                      \
                for (int ni = 0; ni < 4; ni++)                                         \
                    mma_bf16(acc[mi][ni], ah_[mi][0], ah_[mi][1], ah_[mi][2],          \
                             ah_[mi][3], bh_[ni][0], bh_[ni][1]);                      \
        }                                                                              \
    }

    LOAD_STAGE64(0, 0)

    for (int kt = 0; kt < KT; kt += 2) {
        cp_async_wait0();
        __syncthreads();
        if (kt + 1 < KT) LOAD_STAGE64(1, (kt + 1) << 6)
        COMPUTE_STAGE64(0)

        cp_async_wait0();
        __syncthreads();
        if (kt + 2 < KT) LOAD_STAGE64(0, (kt + 2) << 6)
        COMPUTE_STAGE64(1)
    }

    #pragma unroll
    for (int mi = 0; mi < 2; mi++) {
        int row0 = m0 + wm + mi * 16 + grp;
        #pragma unroll
        for (int ni = 0; ni < 4; ni++) {
            int col = n0 + wn + ni * 8 + tig * 2;
            float b0 = bias[col], b1 = bias[col + 1];
            *(float2*)(Cf + (size_t)row0 * N + col) =
                make_float2(acc[mi][ni][0] + b0, acc[mi][ni][1] + b1);
            *(float2*)(Cf + (size_t)(row0 + 8) * N + col) =
                make_float2(acc[mi][ni][2] + b0, acc[mi][ni][3] + b1);
        }
    }
}

// ================= tensor-core local attention (mma.sync) =================
#define QSTR 36
#define ATT_SMEM ((2 * 128 * QSTR + 4 * 64 * QSTR + 64) * 4)

__global__ __launch_bounds__(256, 1) void attn_tc_kernel(
    const bf16* __restrict__ Qh, const bf16* __restrict__ Ql,
    const int* __restrict__ amask,
    bf16* __restrict__ Ohi, bf16* __restrict__ Olo)
{
    extern __shared__ uint32_t sm[];
    const int OQH = 0;
    const int OQL = OQH + 128 * QSTR;
    const int OKH = OQL + 128 * QSTR;
    const int OKL = OKH + 64 * QSTR;
    const int OVH = OKL + 64 * QSTR;
    const int OVL = OVH + 64 * QSTR;
    const int OMF = OVL + 64 * QSTR;
    float* mf = (float*)(sm + OMF);

    const int q0 = blockIdx.x * 128;
    const int hh = blockIdx.y;
    const int b  = blockIdx.z;
    const int tid = threadIdx.x, warp = tid >> 5, lane = tid & 31;
    const int grp = lane >> 2, tig = lane & 3;
    const uint32_t base = (uint32_t)__cvta_generic_to_shared(sm);
    const unsigned FULL = 0xffffffffu;

    for (int idx = tid; idx < 128 * 8; idx += 256) {
        int r = idx >> 3, q4 = idx & 7;
        size_t off = (size_t)(b * S_ + q0 + r) * QKVS + hh * DH_;
        ((uint4*)(sm + OQH + r * QSTR))[q4] = ((const uint4*)(Qh + off))[q4];
        ((uint4*)(sm + OQL + r * QSTR))[q4] = ((const uint4*)(Ql + off))[q4];
    }
    __syncthreads();

    uint32_t qfh[4][4], qfl[4][4];
    {
        int arow = warp * 16 + (lane & 7) + ((lane >> 3) & 1) * 8;
        int ablk = lane >> 4;
        #pragma unroll
        for (int st = 0; st < 4; st++) {
            uint32_t ad = base + (OQH + arow * QSTR) * 4 + (st * 2 + ablk) * 16;
            ldsm_x4(qfh[st][0], qfh[st][1], qfh[st][2], qfh[st][3], ad);
            ldsm_x4(qfl[st][0], qfl[st][1], qfl[st][2], qfl[st][3],
                    ad + (OQL - OQH) * 4);
        }
    }

    float o[8][4];
    #pragma unroll
    for (int ni = 0; ni < 8; ni++)
        #pragma unroll
        for (int c = 0; c < 4; c++) o[ni][c] = 0.f;
    float m0 = -1e30f, m1 = -1e30f, l0 = 0.f, l1 = 0.f;

    const int brow = (lane & 7) + (lane >> 4) * 8;
    const int bblk = (lane >> 3) & 1;
    const int vrow = (lane & 7) + ((lane >> 3) & 1) * 8;
    const int vblk = lane >> 4;
    const int qg0 = q0 + warp * 16 + grp;
    const int qg1 = qg0 + 8;

    for (int kt = 0; kt < 10; kt++) {
        const int ks = q0 - 256 + kt * 64;
        if (ks + 64 <= 0 || ks >= S_) continue;
        __syncthreads();
        const uint4 z4 = make_uint4(0u, 0u, 0u, 0u);
        for (int idx = tid; idx < 64 * 8; idx += 256) {
            int c = idx >> 3, q4 = idx & 7;
            int kg = ks + c;
            uint4 kh = z4, kl = z4, vh = z4, vl = z4;
            if (kg >= 0 && kg < S_) {
                size_t off = (size_t)(b * S_ + kg) * QKVS + hh * DH_;
                kh = ((const uint4*)(Qh + off + H_))[q4];
                kl = ((const uint4*)(Ql + off + H_))[q4];
                vh = ((const uint4*)(Qh + off + 2 * H_))[q4];
                vl = ((const uint4*)(Ql + off + 2 * H_))[q4];
            }
            ((uint4*)(sm + OKH + c * QSTR))[q4] = kh;
            ((uint4*)(sm + OKL + c * QSTR))[q4] = kl;
            ((uint4*)(sm + OVH + c * QSTR))[q4] = vh;
            ((uint4*)(sm + OVL + c * QSTR))[q4] = vl;
        }
        if (tid < 64) {
            int kg = ks + tid;
            mf[tid] = (kg >= 0 && kg < S_ && amask[b * S_ + kg] > 0) ? 0.f : -1e9f;
        }
        __syncthreads();

        float s[8][4];
        #pragma unroll
        for (int ni = 0; ni < 8; ni++)
            #pragma unroll
            for (int c = 0; c < 4; c++) s[ni][c] = 0.f;
        #pragma unroll
        for (int st = 0; st < 4; st++) {
            uint32_t kbh[8][2], kbl[8][2];
            #pragma unroll
            for (int t = 0; t < 4; t++) {
                uint32_t ad = base + (OKH + (t * 16 + brow) * QSTR) * 4
                            + (st * 2 + bblk) * 16;
                ldsm_x4(kbh[2*t][0], kbh[2*t][1], kbh[2*t+1][0], kbh[2*t+1][1], ad);
                ldsm_x4(kbl[2*t][0], kbl[2*t][1], kbl[2*t+1][0], kbl[2*t+1][1],
                        ad + (OKL - OKH) * 4);
            }
            #pragma unroll
            for (int ni = 0; ni < 8; ni++)
                mma_bf16(s[ni], qfl[st][0], qfl[st][1], qfl[st][2], qfl[st][3],
                         kbh[ni][0], kbh[ni][1]);
            #pragma unroll
            for (int ni = 0; ni < 8; ni++)
                mma_bf16(s[ni], qfh[st][0], qfh[st][1], qfh[st][2], qfh[st][3],
                         kbl[ni][0], kbl[ni][1]);
            #pragma unroll
            for (int ni = 0; ni < 8; ni++)
                mma_bf16(s[ni], qfh[st][0], qfh[st][1], qfh[st][2], qfh[st][3],
                         kbh[ni][0], kbh[ni][1]);
        }

        float tmax0 = -1e30f, tmax1 = -1e30f;
        #pragma unroll
        for (int ni = 0; ni < 8; ni++) {
            int kl0 = ni * 8 + 2 * tig;
            float mv0 = mf[kl0], mv1 = mf[kl0 + 1];
            int kg0 = ks + kl0;
            int d00 = kg0 - qg0, d01 = d00 + 1;
            int d10 = kg0 - qg1, d11 = d10 + 1;
            float x0 = (d00 >= -WIN_ && d00 <= WIN_) ? s[ni][0] + mv0 : -1e9f;
            float x1 = (d01 >= -WIN_ && d01 <= WIN_) ? s[ni][1] + mv1 : -1e9f;
            float x2 = (d10 >= -WIN_ && d10 <= WIN_) ? s[ni][2] + mv0 : -1e9f;
            float x3 = (d11 >= -WIN_ && d11 <= WIN_) ? s[ni][3] + mv1 : -1e9f;
            s[ni][0] = x0; s[ni][1] = x1; s[ni][2] = x2; s[ni][3] = x3;
            tmax0 = fmaxf(tmax0, fmaxf(x0, x1));
            tmax1 = fmaxf(tmax1, fmaxf(x2, x3));
        }
        tmax0 = fmaxf(tmax0, __shfl_xor_sync(FULL, tmax0, 1));
        tmax0 = fmaxf(tmax0, __shfl_xor_sync(FULL, tmax0, 2));
        tmax1 = fmaxf(tmax1, __shfl_xor_sync(FULL, tmax1, 1));
        tmax1 = fmaxf(tmax1, __shfl_xor_sync(FULL, tmax1, 2));
        float mn0 = fmaxf(m0, tmax0), mn1 = fmaxf(m1, tmax1);
        float sc0 = __expf(m0 - mn0), sc1 = __expf(m1 - mn1);
        float ps0 = 0.f, ps1 = 0.f;
        #pragma unroll
        for (int ni = 0; ni < 8; ni++) {
            s[ni][0] = __expf(s[ni][0] - mn0);
            s[ni][1] = __expf(s[ni][1] - mn0);
            s[ni][2] = __expf(s[ni][2] - mn1);
            s[ni][3] = __expf(s[ni][3] - mn1);
            ps0 += s[ni][0] + s[ni][1];
            ps1 += s[ni][2] + s[ni][3];
        }
        ps0 += __shfl_xor_sync(FULL, ps0, 1);
        ps0 += __shfl_xor_sync(FULL, ps0, 2);
        ps1 += __shfl_xor_sync(FULL, ps1, 1);
        ps1 += __shfl_xor_sync(FULL, ps1, 2);
        l0 = l0 * sc0 + ps0;
        l1 = l1 * sc1 + ps1;
        m0 = mn0; m1 = mn1;
        #pragma unroll
        for (int ni = 0; ni < 8; ni++) {
            o[ni][0] *= sc0; o[ni][1] *= sc0;
            o[ni][2] *= sc1; o[ni][3] *= sc1;
        }

        uint32_t pah[4][4], pal[4][4];
        #pragma unroll
        for (int j = 0; j < 4; j++) {
            packsplit(s[2*j][0],   s[2*j][1],   pah[j][0], pal[j][0]);
            packsplit(s[2*j][2],   s[2*j][3],   pah[j][1], pal[j][1]);
            packsplit(s[2*j+1][0], s[2*j+1][1], pah[j][2], pal[j][2]);
            packsplit(s[2*j+1][2], s[2*j+1][3], pah[j][3], pal[j][3]);
        }

        #pragma unroll
        for (int j = 0; j < 4; j++) {
            uint32_t vbh[8][2], vbl[8][2];
            #pragma unroll
            for (int t = 0; t < 4; t++) {
                uint32_t ad = base + (OVH + (j * 16 + vrow) * QSTR) * 4
                            + (2 * t + vblk) * 16;
                ldsm_x4_t(vbh[2*t][0], vbh[2*t][1], vbh[2*t+1][0], vbh[2*t+1][1], ad);
                ldsm_x4_t(vbl[2*t][0], vbl[2*t][1], vbl[2*t+1][0], vbl[2*t+1][1],
                          ad + (OVL - OVH) * 4);
            }
            #pragma unroll
            for (int ni = 0; ni < 8; ni++)
                mma_bf16(o[ni], pal[j][0], pal[j][1], pal[j][2], pal[j][3],
                         vbh[ni][0], vbh[ni][1]);
            #pragma unroll
            for (int ni = 0; ni < 8; ni++)
                mma_bf16(o[ni], pah[j][0], pah[j][1], pah[j][2], pah[j][3],
                         vbl[ni][0], vbl[ni][1]);
            #pragma unroll
            for (int ni = 0; ni < 8; ni++)
                mma_bf16(o[ni], pah[j][0], pah[j][1], pah[j][2], pah[j][3],
                         vbh[ni][0], vbh[ni][1]);
        }
    }

    float inv0 = 1.f / l0, inv1 = 1.f / l1;
    #pragma unroll
    for (int ni = 0; ni < 8; ni++) {
        int dcol = hh * DH_ + ni * 8 + 2 * tig;
        size_t o0 = (size_t)(b * S_ + qg0) * H_ + dcol;
        size_t o1 = (size_t)(b * S_ + qg1) * H_ + dcol;
        uint32_t ph, pl;
        packsplit(o[ni][0] * inv0, o[ni][1] * inv0, ph, pl);
        *(uint32_t*)(Ohi + o0) = ph;
        *(uint32_t*)(Olo + o0) = pl;
        packsplit(o[ni][2] * inv1, o[ni][3] * inv1, ph, pl);
        *(uint32_t*)(Ohi + o1) = ph;
        *(uint32_t*)(Olo + o1) = pl;
    }
}

// ---------------- pooling head ----------------
__global__ __launch_bounds__(256) void attn_score_kernel(
    const float* __restrict__ h, const float* __restrict__ aw, float* __restrict__ sc)
{
    int t = blockIdx.x;
    int tid = threadIdx.x;
    float acc = 0.f;
    #pragma unroll
    for (int i = 0; i < 3; i++) {
        int c = tid + i * 256;
        acc += h[(size_t)t * H_ + c] * aw[c];
    }
    float s = block_reduce_sum(acc);
    if (tid == 0) sc[t] = s;
}

__global__ __launch_bounds__(256) void softmax_s_kernel(
    const float* __restrict__ sc, float* __restrict__ pr)
{
    int b = blockIdx.x;
    int tid = threadIdx.x;
    float v[4];
    float mx = -1e30f;
    #pragma unroll
    for (int i = 0; i < 4; i++) {
        v[i] = sc[b * S_ + tid + i * 256];
        mx = fmaxf(mx, v[i]);
    }
    mx = block_reduce_max(mx);
    float e[4], ps = 0.f;
    #pragma unroll
    for (int i = 0; i < 4; i++) { e[i] = __expf(v[i] - mx); ps += e[i]; }
    float tot = block_reduce_sum(ps);
    float inv = 1.f / tot;
    #pragma unroll
    for (int i = 0; i < 4; i++) pr[b * S_ + tid + i * 256] = e[i] * inv;
}

__global__ __launch_bounds__(256) void pool_kernel(
    const float* __restrict__ h, const float* __restrict__ pr, float* __restrict__ poolp)
{
    int d = blockIdx.x * 256 + threadIdx.x;
    int b = blockIdx.y;
    int p = blockIdx.z;
    float acc = 0.f;
    int s0 = p * (S_ / 8);
    for (int s = s0; s < s0 + S_ / 8; s++) {
        acc += h[((size_t)(b * S_ + s)) * H_ + d] * pr[b * S_ + s];
    }
    poolp[((size_t)p * B_ + b) * H_ + d] = acc;
}

__global__ __launch_bounds__(256) void final_kernel(
    const float* __restrict__ poolp, const float* __restrict__ Wc,
    const float* __restrict__ bc, float* __restrict__ out)
{
    int b = blockIdx.x;
    int tid = threadIdx.x;
    float acc = 0.f;
    #pragma unroll
    for (int i = 0; i < 3; i++) {
        int c = tid + i * 256;
        float pv = 0.f;
        #pragma unroll
        for (int p = 0; p < 8; p++)
            pv += poolp[((size_t)p * B_ + b) * H_ + c];
        acc += pv * Wc[c];
    }
    float s = block_reduce_sum(acc);
    if (tid == 0) out[b] = s + bc[0];
}

// ---------------- host launcher ----------------
extern "C" void kernel_launch(void* const* d_in, const int* in_sizes, int n_in,
                              void* d_out, int out_size)
{
    (void)in_sizes; (void)n_in; (void)out_size;
    const float* WE   = (const float*)d_in[0];
    const float* PE   = (const float*)d_in[1];
    const float* Eg   = (const float*)d_in[2];
    const float* Eb   = (const float*)d_in[3];
    const float* Wq   = (const float*)d_in[4];
    const float* bq   = (const float*)d_in[5];
    const float* Wk   = (const float*)d_in[6];
    const float* bk   = (const float*)d_in[7];
    const float* Wv   = (const float*)d_in[8];
    const float* bv   = (const float*)d_in[9];
    const float* Wo   = (const float*)d_in[10];
    const float* bo   = (const float*)d_in[11];
    const float* g1   = (const float*)d_in[12];
    const float* beta1= (const float*)d_in[13];
    const float* W1   = (const float*)d_in[14];
    const float* b1   = (const float*)d_in[15];
    const float* W2   = (const float*)d_in[16];
    const float* b2   = (const float*)d_in[17];
    const float* g2   = (const float*)d_in[18];
    const float* beta2= (const float*)d_in[19];
    const float* aw   = (const float*)d_in[20];
    const float* Wc   = (const float*)d_in[21];
    const float* bc   = (const float*)d_in[22];
    const int*   ids  = (const int*)d_in[23];
    const int*   am   = (const int*)d_in[24];
    float* out = (float*)d_out;

    bf16 *wqkv_hi, *wqkv_lo, *wot_hi, *wot_lo, *w1t_hi, *w1t_lo, *w2t_hi, *w2t_lo;
    bf16 *h_hi, *h_lo, *a_hi, *a_lo, *f_hi, *f_lo, *qkvh, *qkvl;
    float *bqkv, *h, *r, *sc, *pr, *poolp;
    cudaGetSymbolAddress((void**)&wqkv_hi, g_wqkv_hi);
    cudaGetSymbolAddress((void**)&wqkv_lo, g_wqkv_lo);
    cudaGetSymbolAddress((void**)&wot_hi,  g_wot_hi);
    cudaGetSymbolAddress((void**)&wot_lo,  g_wot_lo);
    cudaGetSymbolAddress((void**)&w1t_hi,  g_w1t_hi);
    cudaGetSymbolAddress((void**)&w1t_lo,  g_w1t_lo);
    cudaGetSymbolAddress((void**)&w2t_hi,  g_w2t_hi);
    cudaGetSymbolAddress((void**)&w2t_lo,  g_w2t_lo);
    cudaGetSymbolAddress((void**)&bqkv,    g_bqkv);
    cudaGetSymbolAddress((void**)&h,       g_h);
    cudaGetSymbolAddress((void**)&h_hi,    g_h_hi);
    cudaGetSymbolAddress((void**)&h_lo,    g_h_lo);
    cudaGetSymbolAddress((void**)&qkvh,    g_qkvh);
    cudaGetSymbolAddress((void**)&qkvl,    g_qkvl);
    cudaGetSymbolAddress((void**)&a_hi,    g_a_hi);
    cudaGetSymbolAddress((void**)&a_lo,    g_a_lo);
    cudaGetSymbolAddress((void**)&f_hi,    g_f_hi);
    cudaGetSymbolAddress((void**)&f_lo,    g_f_lo);
    cudaGetSymbolAddress((void**)&r,       g_r);
    cudaGetSymbolAddress((void**)&sc,      g_sc);
    cudaGetSymbolAddress((void**)&pr,      g_pr);
    cudaGetSymbolAddress((void**)&poolp,   g_poolp);

    cudaFuncSetAttribute(tgemm_kernel,
                         cudaFuncAttributeMaxDynamicSharedMemorySize, GSMEM);
    cudaFuncSetAttribute(tgemm64_kernel,
                         cudaFuncAttributeMaxDynamicSharedMemorySize, GSMEM64);
    cudaFuncSetAttribute(attn_tc_kernel,
                         cudaFuncAttributeMaxDynamicSharedMemorySize, ATT_SMEM);

    // ---- pre-pass (QKV GEMM at launch idx 3 for ncu) ----
    dim3 wb(256);
    wsplit_qkv_kernel<<<dim3(H_ / 32, H_ / 32, 3 * L_), wb>>>(Wq, Wk, Wv,
                                                              wqkv_hi, wqkv_lo);
    embed_ln_kernel<<<BS_ + L_, 256>>>(WE, PE, Eg, Eb, ids, h, h_hi, h_lo,
                                       bq, bk, bv, bqkv);
    wsplit_kernel<<<dim3(H_ / 32, H_ / 32, L_), wb>>>(Wo, wot_hi, wot_lo, H_, H_,
        (size_t)H_ * H_, (size_t)H_ * H_);

    dim3 gQKV(QKVS / 128, BS_ / 128);   // (18, 32) = 576 CTAs
    dim3 gO64(H_ / 128, BS_ / 64);      // (6, 64)  = 384 CTAs
    dim3 gW1(FF_ / 128, BS_ / 128);     // (24, 32) = 768 CTAs
    dim3 gattn(S_ / 128, NH_, B_);

    // layer 0 QKV GEMM first (launch idx 3), remaining wsplits after it
    tgemm_kernel<<<gQKV, 256, GSMEM>>>(h_hi, h_lo,
        wqkv_hi, wqkv_lo, bqkv, nullptr, qkvh, qkvl, BS_, QKVS, H_, 2);
    wsplit_kernel<<<dim3(FF_ / 32, H_ / 32, L_), wb>>>(W1, w1t_hi, w1t_lo, H_, FF_,
        (size_t)H_ * FF_, (size_t)FF_ * H_);
    wsplit_kernel<<<dim3(H_ / 32, FF_ / 32, L_), wb>>>(W2, w2t_hi, w2t_lo, FF_, H_,
        (size_t)FF_ * H_, (size_t)H_ * FF_);

    for (int l = 0; l < L_; l++) {
        if (l > 0) {
            tgemm_kernel<<<gQKV, 256, GSMEM>>>(h_hi, h_lo,
                wqkv_hi + (size_t)l * QKVS * H_, wqkv_lo + (size_t)l * QKVS * H_,
                bqkv + l * QKVS, nullptr, qkvh, qkvl, BS_, QKVS, H_, 2);
        }

        attn_tc_kernel<<<gattn, 256, ATT_SMEM>>>(qkvh, qkvl, am, a_hi, a_lo);

        tgemm64_kernel<<<gO64, 256, GSMEM64>>>(a_hi, a_lo,
            wot_hi + (size_t)l * H_ * H_, wot_lo + (size_t)l * H_ * H_,
            bo + l * H_, r, BS_, H_, H_);
        add_ln_kernel<<<BS_, 256>>>(h, r, g1 + l * H_, beta1 + l * H_, h_hi, h_lo);

        tgemm_kernel<<<gW1, 256, GSMEM>>>(h_hi, h_lo,
            w1t_hi + (size_t)l * FF_ * H_, w1t_lo + (size_t)l * FF_ * H_,
            b1 + l * FF_, nullptr, f_hi, f_lo, BS_, FF_, H_, 1);

        tgemm64_kernel<<<gO64, 256, GSMEM64>>>(f_hi, f_lo,
            w2t_hi + (size_t)l * H_ * FF_, w2t_lo + (size_t)l * H_ * FF_,
            b2 + l * H_, r, BS_, H_, FF_);
        add_ln_kernel<<<BS_, 256>>>(h, r, g2 + l * H_, beta2 + l * H_, h_hi, h_lo);
    }

    attn_score_kernel<<<BS_, 256>>>(h, aw, sc);
    softmax_s_kernel<<<B_, 256>>>(sc, pr);
    pool_kernel<<<dim3(H_ / 256, B_, 8), 256>>>(h, pr, poolp);
    final_kernel<<<B_, 256>>>(poolp, Wc, bc, out);
}

// round 17
// speedup vs baseline: 1.1479x; 1.0259x over previous
#include <cuda_runtime.h>
#include <cuda_bf16.h>
#include <cstdint>
#include <math.h>

#define L_  12
#define NH_ 12
#define DH_ 64
#define H_  768
#define FF_ 3072
#define S_  1024
#define B_  4
#define BS_ (B_ * S_)   // 4096
#define WIN_ 256
#define QKVS 2304       // fused qkv row stride

typedef __nv_bfloat16 bf16;

// ---------------- scratch (no allocations allowed) ----------------
__device__ bf16 g_wqkv_hi[L_ * QKVS * H_];
__device__ bf16 g_wqkv_lo[L_ * QKVS * H_];
__device__ bf16 g_wot_hi [L_ * H_ * H_];
__device__ bf16 g_wot_lo [L_ * H_ * H_];
__device__ bf16 g_w1t_hi [L_ * FF_ * H_];
__device__ bf16 g_w1t_lo [L_ * FF_ * H_];
__device__ bf16 g_w2t_hi [L_ * H_ * FF_];
__device__ bf16 g_w2t_lo [L_ * H_ * FF_];
__device__ float g_bqkv  [L_ * QKVS];

__device__ float g_h    [BS_ * H_];
__device__ bf16  g_h_hi [BS_ * H_];
__device__ bf16  g_h_lo [BS_ * H_];
__device__ bf16  g_qkvh [BS_ * QKVS];
__device__ bf16  g_qkvl [BS_ * QKVS];
__device__ bf16  g_a_hi [BS_ * H_];
__device__ bf16  g_a_lo [BS_ * H_];
__device__ bf16  g_f_hi [BS_ * FF_];
__device__ bf16  g_f_lo [BS_ * FF_];
__device__ float g_r    [BS_ * H_];
__device__ float g_sc   [BS_];
__device__ float g_pr   [BS_];
__device__ float g_poolp[8 * B_ * H_];

__device__ __forceinline__ void split_bf16(float x, bf16& hi, bf16& lo) {
    hi = __float2bfloat16_rn(x);
    lo = __float2bfloat16_rn(x - __bfloat162float(hi));
}

// ---------------- low-level helpers ----------------
__device__ __forceinline__ void cp_async16(uint32_t smem_addr, const void* gptr) {
    asm volatile("cp.async.cg.shared.global [%0], [%1], 16;\n"
                 :: "r"(smem_addr), "l"(gptr));
}
__device__ __forceinline__ void cp_async_commit() {
    asm volatile("cp.async.commit_group;\n");
}
__device__ __forceinline__ void cp_async_wait0() {
    asm volatile("cp.async.wait_group 0;\n");
}
__device__ __forceinline__ void ldsm_x4(uint32_t& r0, uint32_t& r1, uint32_t& r2,
                                        uint32_t& r3, uint32_t a) {
    asm volatile("ldmatrix.sync.aligned.m8n8.x4.shared.b16 {%0,%1,%2,%3}, [%4];"
                 : "=r"(r0), "=r"(r1), "=r"(r2), "=r"(r3) : "r"(a));
}
__device__ __forceinline__ void ldsm_x4_t(uint32_t& r0, uint32_t& r1, uint32_t& r2,
                                          uint32_t& r3, uint32_t a) {
    asm volatile("ldmatrix.sync.aligned.m8n8.x4.trans.shared.b16 {%0,%1,%2,%3}, [%4];"
                 : "=r"(r0), "=r"(r1), "=r"(r2), "=r"(r3) : "r"(a));
}
__device__ __forceinline__ void mma_bf16(
    float* acc, uint32_t a0, uint32_t a1, uint32_t a2, uint32_t a3,
    uint32_t b0, uint32_t b1)
{
    asm volatile(
        "mma.sync.aligned.m16n8k16.row.col.f32.bf16.bf16.f32 "
        "{%0,%1,%2,%3}, {%4,%5,%6,%7}, {%8,%9}, {%0,%1,%2,%3};\n"
        : "+f"(acc[0]), "+f"(acc[1]), "+f"(acc[2]), "+f"(acc[3])
        : "r"(a0), "r"(a1), "r"(a2), "r"(a3), "r"(b0), "r"(b1));
}
__device__ __forceinline__ void packsplit(float a, float b, uint32_t& ph, uint32_t& pl) {
    bf16 ah = __float2bfloat16_rn(a), bh = __float2bfloat16_rn(b);
    float al = a - __bfloat162float(ah), bl = b - __bfloat162float(bh);
    ph = ((uint32_t)__bfloat16_as_ushort(bh) << 16) | (uint32_t)__bfloat16_as_ushort(ah);
    pl = ((uint32_t)__bfloat16_as_ushort(__float2bfloat16_rn(bl)) << 16)
       |  (uint32_t)__bfloat16_as_ushort(__float2bfloat16_rn(al));
}

// ---------------- reduction helpers ----------------
__device__ __forceinline__ float block_reduce_sum(float v) {
    __shared__ float red[32];
    int lane = threadIdx.x & 31, wid = threadIdx.x >> 5;
    #pragma unroll
    for (int o = 16; o; o >>= 1) v += __shfl_xor_sync(0xffffffffu, v, o);
    if (lane == 0) red[wid] = v;
    __syncthreads();
    int nw = (blockDim.x + 31) >> 5;
    v = (threadIdx.x < nw) ? red[threadIdx.x] : 0.f;
    if (wid == 0) {
        #pragma unroll
        for (int o = 16; o; o >>= 1) v += __shfl_xor_sync(0xffffffffu, v, o);
    }
    if (threadIdx.x == 0) red[0] = v;
    __syncthreads();
    v = red[0];
    __syncthreads();
    return v;
}

__device__ __forceinline__ float2 block_reduce_sum2(float a, float b) {
    __shared__ float2 red[32];
    int lane = threadIdx.x & 31, wid = threadIdx.x >> 5;
    #pragma unroll
    for (int o = 16; o; o >>= 1) {
        a += __shfl_xor_sync(0xffffffffu, a, o);
        b += __shfl_xor_sync(0xffffffffu, b, o);
    }
    if (lane == 0) red[wid] = make_float2(a, b);
    __syncthreads();
    int nw = (blockDim.x + 31) >> 5;
    float2 t = (threadIdx.x < nw) ? red[threadIdx.x] : make_float2(0.f, 0.f);
    if (wid == 0) {
        #pragma unroll
        for (int o = 16; o; o >>= 1) {
            t.x += __shfl_xor_sync(0xffffffffu, t.x, o);
            t.y += __shfl_xor_sync(0xffffffffu, t.y, o);
        }
    }
    if (threadIdx.x == 0) red[0] = t;
    __syncthreads();
    t = red[0];
    __syncthreads();
    return t;
}

__device__ __forceinline__ float block_reduce_max(float v) {
    __shared__ float red[32];
    int lane = threadIdx.x & 31, wid = threadIdx.x >> 5;
    #pragma unroll
    for (int o = 16; o; o >>= 1) v = fmaxf(v, __shfl_xor_sync(0xffffffffu, v, o));
    if (lane == 0) red[wid] = v;
    __syncthreads();
    int nw = (blockDim.x + 31) >> 5;
    v = (threadIdx.x < nw) ? red[threadIdx.x] : -1e30f;
    if (wid == 0) {
        #pragma unroll
        for (int o = 16; o; o >>= 1) v = fmaxf(v, __shfl_xor_sync(0xffffffffu, v, o));
    }
    if (threadIdx.x == 0) red[0] = v;
    __syncthreads();
    v = red[0];
    __syncthreads();
    return v;
}

// ---------------- weight transpose + hi/lo split ----------------
__global__ __launch_bounds__(256) void wsplit_kernel(
    const float* __restrict__ src, bf16* __restrict__ dhi, bf16* __restrict__ dlo,
    int K, int N, size_t srcStride, size_t dstStride)
{
    __shared__ float t[32][33];
    int l = blockIdx.z;
    src += (size_t)l * srcStride;
    dhi += (size_t)l * dstStride;
    dlo += (size_t)l * dstStride;
    int tx = threadIdx.x & 31, ty = threadIdx.x >> 5;
    int n0 = blockIdx.x * 32, k0 = blockIdx.y * 32;
    #pragma unroll
    for (int i = 0; i < 4; i++)
        t[ty + i * 8][tx] = src[(size_t)(k0 + ty + i * 8) * N + n0 + tx];
    __syncthreads();
    #pragma unroll
    for (int i = 0; i < 4; i++) {
        int r = ty + i * 8;
        float x = t[tx][r];
        bf16 hi, lo; split_bf16(x, hi, lo);
        size_t o = (size_t)(n0 + r) * K + k0 + tx;
        dhi[o] = hi; dlo[o] = lo;
    }
}

__global__ __launch_bounds__(256) void wsplit_qkv_kernel(
    const float* __restrict__ Wq, const float* __restrict__ Wk,
    const float* __restrict__ Wv, bf16* __restrict__ dhi, bf16* __restrict__ dlo)
{
    __shared__ float t[32][33];
    int z = blockIdx.z;
    int l = z / 3, j = z % 3;
    const float* src = (j == 0 ? Wq : (j == 1 ? Wk : Wv)) + (size_t)l * H_ * H_;
    bf16* oh = dhi + (size_t)l * QKVS * H_ + (size_t)j * H_ * H_;
    bf16* ol = dlo + (size_t)l * QKVS * H_ + (size_t)j * H_ * H_;
    int tx = threadIdx.x & 31, ty = threadIdx.x >> 5;
    int n0 = blockIdx.x * 32, k0 = blockIdx.y * 32;
    #pragma unroll
    for (int i = 0; i < 4; i++)
        t[ty + i * 8][tx] = src[(size_t)(k0 + ty + i * 8) * H_ + n0 + tx];
    __syncthreads();
    #pragma unroll
    for (int i = 0; i < 4; i++) {
        int r = ty + i * 8;
        float x = t[tx][r];
        bf16 hi, lo; split_bf16(x, hi, lo);
        size_t o = (size_t)(n0 + r) * H_ + k0 + tx;
        oh[o] = hi; ol[o] = lo;
    }
}

// ---------------- embedding + LN (+ fused qkv-bias concat) ----------------
__global__ __launch_bounds__(256) void embed_ln_kernel(
    const float* __restrict__ WE, const float* __restrict__ PE,
    const float* __restrict__ g, const float* __restrict__ be,
    const int* __restrict__ ids,
    float* __restrict__ out, bf16* __restrict__ ohi, bf16* __restrict__ olo,
    const float* __restrict__ bq, const float* __restrict__ bk,
    const float* __restrict__ bv, float* __restrict__ bqkv)
{
    int t = blockIdx.x;
    int tid = threadIdx.x;
    if (t >= BS_) {
        int l = t - BS_;
        for (int n = tid; n < QKVS; n += 256) {
            float v;
            if (n < H_)          v = bq[l * H_ + n];
            else if (n < 2 * H_) v = bk[l * H_ + n - H_];
            else                 v = bv[l * H_ + n - 2 * H_];
            bqkv[l * QKVS + n] = v;
        }
        return;
    }
    int s = t & (S_ - 1);
    int id = ids[t];
    float v[3];
    float s1 = 0.f, s2 = 0.f;
    #pragma unroll
    for (int i = 0; i < 3; i++) {
        int c = tid + i * 256;
        v[i] = WE[(size_t)id * H_ + c] + PE[(size_t)s * H_ + c];
        s1 += v[i]; s2 += v[i] * v[i];
    }
    float2 red = block_reduce_sum2(s1, s2);
    float m = red.x * (1.f / H_);
    float var = red.y * (1.f / H_) - m * m;
    float rs = rsqrtf(var + 1e-5f);
    #pragma unroll
    for (int i = 0; i < 3; i++) {
        int c = tid + i * 256;
        float y = (v[i] - m) * rs * g[c] + be[c];
        size_t o = (size_t)t * H_ + c;
        out[o] = y;
        bf16 hi, lo; split_bf16(y, hi, lo);
        ohi[o] = hi; olo[o] = lo;
    }
}

// ---------------- residual add + LN (in-place on h) ----------------
__global__ __launch_bounds__(256) void add_ln_kernel(
    float* __restrict__ h, const float* __restrict__ r,
    const float* __restrict__ g, const float* __restrict__ be,
    bf16* __restrict__ ohi, bf16* __restrict__ olo)
{
    int t = blockIdx.x;
    int tid = threadIdx.x;
    float v[3];
    float s1 = 0.f, s2 = 0.f;
    #pragma unroll
    for (int i = 0; i < 3; i++) {
        int c = tid + i * 256;
        size_t o = (size_t)t * H_ + c;
        v[i] = h[o] + r[o];
        s1 += v[i]; s2 += v[i] * v[i];
    }
    float2 red = block_reduce_sum2(s1, s2);
    float m = red.x * (1.f / H_);
    float var = red.y * (1.f / H_) - m * m;
    float rs = rsqrtf(var + 1e-5f);
    #pragma unroll
    for (int i = 0; i < 3; i++) {
        int c = tid + i * 256;
        float y = (v[i] - m) * rs * g[c] + be[c];
        size_t o = (size_t)t * H_ + c;
        h[o] = y;
        bf16 hi, lo; split_bf16(y, hi, lo);
        ohi[o] = hi; olo[o] = lo;
    }
}

// ================= bf16x3 tensor-core GEMM (BK=64, 128x128) ===============
#define PSTR 36                 // uint32 per row (32 data + 4 pad)
#define STG  (128 * PSTR)       // uint32 per data tile (18KB)
#define GSMEM (8 * STG * 4)     // 2 stages x 4 tiles = 147456 B

__global__ __launch_bounds__(256) void tgemm_kernel(
    const bf16* __restrict__ Ah, const bf16* __restrict__ Al,
    const bf16* __restrict__ Bh, const bf16* __restrict__ Bl,
    const float* __restrict__ bias,
    float* __restrict__ Cf, bf16* __restrict__ Ch, bf16* __restrict__ Cl,
    int M, int N, int K, int mode)
{
    extern __shared__ uint32_t smem_u[];

    const int tid  = threadIdx.x;
    const int warp = tid >> 5;
    const int lane = tid & 31;
    const int m0 = blockIdx.y * 128;
    const int n0 = blockIdx.x * 128;
    const int wm = (warp >> 1) * 32;
    const int wn = (warp & 1) * 64;
    const int grp = lane >> 2;
    const int tig = lane & 3;
    const uint32_t smbase = (uint32_t)__cvta_generic_to_shared(smem_u);

    const int aRow = wm + (lane & 7) + ((lane >> 3) & 1) * 8;
    const int aBlk = lane >> 4;
    const int bRow = wn + (lane & 7) + (lane >> 4) * 8;
    const int bBlk = (lane >> 3) & 1;

    float acc[2][8][4];
    #pragma unroll
    for (int mi = 0; mi < 2; mi++)
        #pragma unroll
        for (int ni = 0; ni < 8; ni++)
            #pragma unroll
            for (int c = 0; c < 4; c++) acc[mi][ni][c] = 0.f;

    const int KT = K >> 6;     // BK = 64; KT = 12 or 48 (even)

    #define LOAD_STAGE(S, k0)                                                          \
    {                                                                                  \
        _Pragma("unroll")                                                              \
        for (int r = 0; r < 4; r++) {                                                  \
            int idx = tid + r * 256;                                                   \
            int row = idx >> 3, c = idx & 7;                                           \
            uint32_t doff = ((S) * 4 * STG + row * PSTR + c * 4) * 4;                  \
            size_t aoff = (size_t)(m0 + row) * K + (k0) + c * 8;                       \
            size_t boff = (size_t)(n0 + row) * K + (k0) + c * 8;                       \
            cp_async16(smbase + doff,               Ah + aoff);                        \
            cp_async16(smbase + doff + STG * 4,     Al + aoff);                        \
            cp_async16(smbase + doff + 2 * STG * 4, Bh + boff);                        \
            cp_async16(smbase + doff + 3 * STG * 4, Bl + boff);                        \
        }                                                                              \
        cp_async_commit();                                                             \
    }

    #define COMPUTE_STAGE(S)                                                           \
    {                                                                                  \
        const uint32_t sb = smbase + (uint32_t)((S) * 4 * STG) * 4;                    \
        _Pragma("unroll")                                                              \
        for (int st = 0; st < 4; st++) {                                               \
            uint32_t ah_[2][4], al_[2][4];                                             \
            _Pragma("unroll")                                                          \
            for (int mi = 0; mi < 2; mi++) {                                           \
                uint32_t ad = sb + ((aRow + mi * 16) * PSTR) * 4                       \
                            + (st * 2 + aBlk) * 16;                                    \
                ldsm_x4(ah_[mi][0], ah_[mi][1], ah_[mi][2], ah_[mi][3], ad);           \
                ldsm_x4(al_[mi][0], al_[mi][1], al_[mi][2], al_[mi][3],                \
                        ad + STG * 4);                                                 \
            }                                                                          \
            uint32_t bh_[8][2], bl_[8][2];                                             \
            _Pragma("unroll")                                                          \
            for (int t = 0; t < 4; t++) {                                              \
                uint32_t ad = sb + 2 * STG * 4 + ((bRow + t * 16) * PSTR) * 4          \
                            + (st * 2 + bBlk) * 16;                                    \
                ldsm_x4(bh_[2*t][0], bh_[2*t][1], bh_[2*t+1][0], bh_[2*t+1][1], ad);   \
                ldsm_x4(bl_[2*t][0], bl_[2*t][1], bl_[2*t+1][0], bl_[2*t+1][1],        \
                        ad + STG * 4);                                                 \
            }                                                                          \
            _Pragma("unroll")                                                          \
            for (int mi = 0; mi < 2; mi++)                                             \
                _Pragma("unroll")                                                      \
                for (int ni = 0; ni < 8; ni++)                                         \
                    mma_bf16(acc[mi][ni], al_[mi][0], al_[mi][1], al_[mi][2],          \
                             al_[mi][3], bh_[ni][0], bh_[ni][1]);                      \
            _Pragma("unroll")                                                          \
            for (int mi = 0; mi < 2; mi++)                                             \
                _Pragma("unroll")                                                      \
                for (int ni = 0; ni < 8; ni++)                                         \
                    mma_bf16(acc[mi][ni], ah_[mi][0], ah_[mi][1], ah_[mi][2],          \
                             ah_[mi][3], bl_[ni][0], bl_[ni][1]);                      \
            _Pragma("unroll")                                                          \
            for (int mi = 0; mi < 2; mi++)                                             \
                _Pragma("unroll")                                                      \
                for (int ni = 0; ni < 8; ni++)                                         \
                    mma_bf16(acc[mi][ni], ah_[mi][0], ah_[mi][1], ah_[mi][2],          \
                             ah_[mi][3], bh_[ni][0], bh_[ni][1]);                      \
        }                                                                              \
    }

    LOAD_STAGE(0, 0)

    for (int kt = 0; kt < KT; kt += 2) {
        cp_async_wait0();
        __syncthreads();
        if (kt + 1 < KT) LOAD_STAGE(1, (kt + 1) << 6)
        COMPUTE_STAGE(0)

        cp_async_wait0();
        __syncthreads();
        if (kt + 2 < KT) LOAD_STAGE(0, (kt + 2) << 6)
        COMPUTE_STAGE(1)
    }

    // ---- epilogue ----
    #pragma unroll
    for (int mi = 0; mi < 2; mi++) {
        int row0 = m0 + wm + mi * 16 + grp;
        #pragma unroll
        for (int ni = 0; ni < 8; ni++) {
            int col = n0 + wn + ni * 8 + tig * 2;
            float b0 = bias[col], b1 = bias[col + 1];
            float v0 = acc[mi][ni][0] + b0;
            float v1 = acc[mi][ni][1] + b1;
            float v2 = acc[mi][ni][2] + b0;
            float v3 = acc[mi][ni][3] + b1;
            if (mode == 0) {
                *(float2*)(Cf + (size_t)row0 * N + col)       = make_float2(v0, v1);
                *(float2*)(Cf + (size_t)(row0 + 8) * N + col) = make_float2(v2, v3);
            } else {
                if (mode == 1) {
                    v0 = 0.5f * v0 * (1.0f + erff(v0 * 0.70710678118654752f));
                    v1 = 0.5f * v1 * (1.0f + erff(v1 * 0.70710678118654752f));
                    v2 = 0.5f * v2 * (1.0f + erff(v2 * 0.70710678118654752f));
                    v3 = 0.5f * v3 * (1.0f + erff(v3 * 0.70710678118654752f));
                } else {
                    float scq = (col < H_) ? 0.125f : 1.f;
                    v0 *= scq; v1 *= scq; v2 *= scq; v3 *= scq;
                }
                size_t o0 = (size_t)row0 * N + col;
                size_t o1 = (size_t)(row0 + 8) * N + col;
                uint32_t ph, pl;
                packsplit(v0, v1, ph, pl);
                *(uint32_t*)(Ch + o0) = ph; *(uint32_t*)(Cl + o0) = pl;
                packsplit(v2, v3, ph, pl);
                *(uint32_t*)(Ch + o1) = ph; *(uint32_t*)(Cl + o1) = pl;
            }
        }
    }
}

// ================= bf16x3 GEMM, 64x128 tile (wave smoothing) ==============
// 8 warps as 2(m) x 4(n); warp tile 32x32.
// mode 0: fp32 + bias out. mode 1: GELU -> bf16 hi/lo out.
#define STGA64 (64 * PSTR)
#define STGB64 (128 * PSTR)
#define STG64  (2 * STGA64 + 2 * STGB64)
#define GSMEM64 (2 * STG64 * 4)   // 110592 B

__global__ __launch_bounds__(256) void tgemm64_kernel(
    const bf16* __restrict__ Ah, const bf16* __restrict__ Al,
    const bf16* __restrict__ Bh, const bf16* __restrict__ Bl,
    const float* __restrict__ bias,
    float* __restrict__ Cf, bf16* __restrict__ Ch, bf16* __restrict__ Cl,
    int M, int N, int K, int mode)
{
    extern __shared__ uint32_t smem_u[];

    const int tid  = threadIdx.x;
    const int warp = tid >> 5;
    const int lane = tid & 31;
    const int m0 = blockIdx.y * 64;
    const int n0 = blockIdx.x * 128;
    const int wm = (warp >> 2) * 32;       // 0 or 32
    const int wn = (warp & 3) * 32;        // 0,32,64,96
    const int grp = lane >> 2;
    const int tig = lane & 3;
    const uint32_t smbase = (uint32_t)__cvta_generic_to_shared(smem_u);

    const int aRow = wm + (lane & 7) + ((lane >> 3) & 1) * 8;
    const int aBlk = lane >> 4;
    const int bRow = wn + (lane & 7) + (lane >> 4) * 8;
    const int bBlk = (lane >> 3) & 1;

    float acc[2][4][4];
    #pragma unroll
    for (int mi = 0; mi < 2; mi++)
        #pragma unroll
        for (int ni = 0; ni < 4; ni++)
            #pragma unroll
            for (int c = 0; c < 4; c++) acc[mi][ni][c] = 0.f;

    const int KT = K >> 6;     // even (12 or 48)

    // stage: Ah(STGA64) | Al(STGA64) | Bh(STGB64) | Bl(STGB64)
    #define LOAD_STAGE64(S, k0)                                                        \
    {                                                                                  \
        _Pragma("unroll")                                                              \
        for (int r = 0; r < 2; r++) {                                                  \
            int idx = tid + r * 256;                                                   \
            int row = idx >> 3, c = idx & 7;                                           \
            uint32_t doff = ((S) * STG64 + row * PSTR + c * 4) * 4;                    \
            size_t aoff = (size_t)(m0 + row) * K + (k0) + c * 8;                       \
            cp_async16(smbase + doff,              Ah + aoff);                         \
            cp_async16(smbase + doff + STGA64 * 4, Al + aoff);                         \
        }                                                                              \
        _Pragma("unroll")                                                              \
        for (int r = 0; r < 4; r++) {                                                  \
            int idx = tid + r * 256;                                                   \
            int row = idx >> 3, c = idx & 7;                                           \
            uint32_t doff = ((S) * STG64 + 2 * STGA64 + row * PSTR + c * 4) * 4;       \
            size_t boff = (size_t)(n0 + row) * K + (k0) + c * 8;                       \
            cp_async16(smbase + doff,              Bh + boff);                         \
            cp_async16(smbase + doff + STGB64 * 4, Bl + boff);                         \
        }                                                                              \
        cp_async_commit();                                                             \
    }

    #define COMPUTE_STAGE64(S)                                                         \
    {                                                                                  \
        const uint32_t sb = smbase + (uint32_t)((S) * STG64) * 4;                      \
        _Pragma("unroll")                                                              \
        for (int st = 0; st < 4; st++) {                                               \
            uint32_t ah_[2][4], al_[2][4];                                             \
            _Pragma("unroll")                                                          \
            for (int mi = 0; mi < 2; mi++) {                                           \
                uint32_t ad = sb + ((aRow + mi * 16) * PSTR) * 4                       \
                            + (st * 2 + aBlk) * 16;                                    \
                ldsm_x4(ah_[mi][0], ah_[mi][1], ah_[mi][2], ah_[mi][3], ad);           \
                ldsm_x4(al_[mi][0], al_[mi][1], al_[mi][2], al_[mi][3],                \
                        ad + STGA64 * 4);                                              \
            }                                                                          \
            uint32_t bh_[4][2], bl_[4][2];                                             \
            _Pragma("unroll")                                                          \
            for (int t = 0; t < 2; t++) {                                              \
                uint32_t ad = sb + 2 * STGA64 * 4 + ((bRow + t * 16) * PSTR) * 4       \
                            + (st * 2 + bBlk) * 16;                                    \
                ldsm_x4(bh_[2*t][0], bh_[2*t][1], bh_[2*t+1][0], bh_[2*t+1][1], ad);   \
                ldsm_x4(bl_[2*t][0], bl_[2*t][1], bl_[2*t+1][0], bl_[2*t+1][1],        \
                        ad + STGB64 * 4);                                              \
            }                                                                          \
            _Pragma("unroll")                                                          \
            for (int mi = 0; mi < 2; mi++)                                             \
                _Pragma("unroll")                                                      \
                for (int ni = 0; ni < 4; ni++)                                         \
                    mma_bf16(acc[mi][ni], al_[mi][0], al_[mi][1], al_[mi][2],          \
                             al_[mi][3], bh_[ni][0], bh_[ni][1]);                      \
            _Pragma("unroll")                                                          \
            for (int mi = 0; mi < 2; mi++)                                             \
                _Pragma("unroll")                                                      \
                for (int ni = 0; ni < 4; ni++)                                         \
                    mma_bf16(acc[mi][ni], ah_[mi][0], ah_[mi][1], ah_[mi][2],          \
                             ah_[mi][3], bl_[ni][0], bl_[ni][1]);                      \
            _Pragma("unroll")                                                          \
            for (int mi = 0; mi < 2; mi++)                                             \
                _Pragma("unroll")                                                      \
                for (int ni = 0; ni < 4; ni++)                                         \
                    mma_bf16(acc[mi][ni], ah_[mi][0], ah_[mi][1], ah_[mi][2],          \
                             ah_[mi][3], bh_[ni][0], bh_[ni][1]);                      \
        }                                                                              \
    }

    LOAD_STAGE64(0, 0)

    for (int kt = 0; kt < KT; kt += 2) {
        cp_async_wait0();
        __syncthreads();
        if (kt + 1 < KT) LOAD_STAGE64(1, (kt + 1) << 6)
        COMPUTE_STAGE64(0)

        cp_async_wait0();
        __syncthreads();
        if (kt + 2 < KT) LOAD_STAGE64(0, (kt + 2) << 6)
        COMPUTE_STAGE64(1)
    }

    #pragma unroll
    for (int mi = 0; mi < 2; mi++) {
        int row0 = m0 + wm + mi * 16 + grp;
        #pragma unroll
        for (int ni = 0; ni < 4; ni++) {
            int col = n0 + wn + ni * 8 + tig * 2;
            float b0 = bias[col], b1 = bias[col + 1];
            float v0 = acc[mi][ni][0] + b0;
            float v1 = acc[mi][ni][1] + b1;
            float v2 = acc[mi][ni][2] + b0;
            float v3 = acc[mi][ni][3] + b1;
            if (mode == 0) {
                *(float2*)(Cf + (size_t)row0 * N + col)       = make_float2(v0, v1);
                *(float2*)(Cf + (size_t)(row0 + 8) * N + col) = make_float2(v2, v3);
            } else {
                v0 = 0.5f * v0 * (1.0f + erff(v0 * 0.70710678118654752f));
                v1 = 0.5f * v1 * (1.0f + erff(v1 * 0.70710678118654752f));
                v2 = 0.5f * v2 * (1.0f + erff(v2 * 0.70710678118654752f));
                v3 = 0.5f * v3 * (1.0f + erff(v3 * 0.70710678118654752f));
                size_t o0 = (size_t)row0 * N + col;
                size_t o1 = (size_t)(row0 + 8) * N + col;
                uint32_t ph, pl;
                packsplit(v0, v1, ph, pl);
                *(uint32_t*)(Ch + o0) = ph; *(uint32_t*)(Cl + o0) = pl;
                packsplit(v2, v3, ph, pl);
                *(uint32_t*)(Ch + o1) = ph; *(uint32_t*)(Cl + o1) = pl;
            }
        }
    }
}

// ================= tensor-core local attention (mma.sync) =================
#define QSTR 36
#define ATT_SMEM ((2 * 128 * QSTR + 4 * 64 * QSTR + 64) * 4)

__global__ __launch_bounds__(256, 1) void attn_tc_kernel(
    const bf16* __restrict__ Qh, const bf16* __restrict__ Ql,
    const int* __restrict__ amask,
    bf16* __restrict__ Ohi, bf16* __restrict__ Olo)
{
    extern __shared__ uint32_t sm[];
    const int OQH = 0;
    const int OQL = OQH + 128 * QSTR;
    const int OKH = OQL + 128 * QSTR;
    const int OKL = OKH + 64 * QSTR;
    const int OVH = OKL + 64 * QSTR;
    const int OVL = OVH + 64 * QSTR;
    const int OMF = OVL + 64 * QSTR;
    float* mf = (float*)(sm + OMF);

    const int q0 = blockIdx.x * 128;
    const int hh = blockIdx.y;
    const int b  = blockIdx.z;
    const int tid = threadIdx.x, warp = tid >> 5, lane = tid & 31;
    const int grp = lane >> 2, tig = lane & 3;
    const uint32_t base = (uint32_t)__cvta_generic_to_shared(sm);
    const unsigned FULL = 0xffffffffu;

    for (int idx = tid; idx < 128 * 8; idx += 256) {
        int r = idx >> 3, q4 = idx & 7;
        size_t off = (size_t)(b * S_ + q0 + r) * QKVS + hh * DH_;
        ((uint4*)(sm + OQH + r * QSTR))[q4] = ((const uint4*)(Qh + off))[q4];
        ((uint4*)(sm + OQL + r * QSTR))[q4] = ((const uint4*)(Ql + off))[q4];
    }
    __syncthreads();

    uint32_t qfh[4][4], qfl[4][4];
    {
        int arow = warp * 16 + (lane & 7) + ((lane >> 3) & 1) * 8;
        int ablk = lane >> 4;
        #pragma unroll
        for (int st = 0; st < 4; st++) {
            uint32_t ad = base + (OQH + arow * QSTR) * 4 + (st * 2 + ablk) * 16;
            ldsm_x4(qfh[st][0], qfh[st][1], qfh[st][2], qfh[st][3], ad);
            ldsm_x4(qfl[st][0], qfl[st][1], qfl[st][2], qfl[st][3],
                    ad + (OQL - OQH) * 4);
        }
    }

    float o[8][4];
    #pragma unroll
    for (int ni = 0; ni < 8; ni++)
        #pragma unroll
        for (int c = 0; c < 4; c++) o[ni][c] = 0.f;
    float m0 = -1e30f, m1 = -1e30f, l0 = 0.f, l1 = 0.f;

    const int brow = (lane & 7) + (lane >> 4) * 8;
    const int bblk = (lane >> 3) & 1;
    const int vrow = (lane & 7) + ((lane >> 3) & 1) * 8;
    const int vblk = lane >> 4;
    const int qg0 = q0 + warp * 16 + grp;
    const int qg1 = qg0 + 8;

    for (int kt = 0; kt < 10; kt++) {
        const int ks = q0 - 256 + kt * 64;
        if (ks + 64 <= 0 || ks >= S_) continue;
        __syncthreads();
        const uint4 z4 = make_uint4(0u, 0u, 0u, 0u);
        for (int idx = tid; idx < 64 * 8; idx += 256) {
            int c = idx >> 3, q4 = idx & 7;
            int kg = ks + c;
            uint4 kh = z4, kl = z4, vh = z4, vl = z4;
            if (kg >= 0 && kg < S_) {
                size_t off = (size_t)(b * S_ + kg) * QKVS + hh * DH_;
                kh = ((const uint4*)(Qh + off + H_))[q4];
                kl = ((const uint4*)(Ql + off + H_))[q4];
                vh = ((const uint4*)(Qh + off + 2 * H_))[q4];
                vl = ((const uint4*)(Ql + off + 2 * H_))[q4];
            }
            ((uint4*)(sm + OKH + c * QSTR))[q4] = kh;
            ((uint4*)(sm + OKL + c * QSTR))[q4] = kl;
            ((uint4*)(sm + OVH + c * QSTR))[q4] = vh;
            ((uint4*)(sm + OVL + c * QSTR))[q4] = vl;
        }
        if (tid < 64) {
            int kg = ks + tid;
            mf[tid] = (kg >= 0 && kg < S_ && amask[b * S_ + kg] > 0) ? 0.f : -1e9f;
        }
        __syncthreads();

        float s[8][4];
        #pragma unroll
        for (int ni = 0; ni < 8; ni++)
            #pragma unroll
            for (int c = 0; c < 4; c++) s[ni][c] = 0.f;
        #pragma unroll
        for (int st = 0; st < 4; st++) {
            uint32_t kbh[8][2], kbl[8][2];
            #pragma unroll
            for (int t = 0; t < 4; t++) {
                uint32_t ad = base + (OKH + (t * 16 + brow) * QSTR) * 4
                            + (st * 2 + bblk) * 16;
                ldsm_x4(kbh[2*t][0], kbh[2*t][1], kbh[2*t+1][0], kbh[2*t+1][1], ad);
                ldsm_x4(kbl[2*t][0], kbl[2*t][1], kbl[2*t+1][0], kbl[2*t+1][1],
                        ad + (OKL - OKH) * 4);
            }
            #pragma unroll
            for (int ni = 0; ni < 8; ni++)
                mma_bf16(s[ni], qfl[st][0], qfl[st][1], qfl[st][2], qfl[st][3],
                         kbh[ni][0], kbh[ni][1]);
            #pragma unroll
            for (int ni = 0; ni < 8; ni++)
                mma_bf16(s[ni], qfh[st][0], qfh[st][1], qfh[st][2], qfh[st][3],
                         kbl[ni][0], kbl[ni][1]);
            #pragma unroll
            for (int ni = 0; ni < 8; ni++)
                mma_bf16(s[ni], qfh[st][0], qfh[st][1], qfh[st][2], qfh[st][3],
                         kbh[ni][0], kbh[ni][1]);
        }

        float tmax0 = -1e30f, tmax1 = -1e30f;
        #pragma unroll
        for (int ni = 0; ni < 8; ni++) {
            int kl0 = ni * 8 + 2 * tig;
            float mv0 = mf[kl0], mv1 = mf[kl0 + 1];
            int kg0 = ks + kl0;
            int d00 = kg0 - qg0, d01 = d00 + 1;
            int d10 = kg0 - qg1, d11 = d10 + 1;
            float x0 = (d00 >= -WIN_ && d00 <= WIN_) ? s[ni][0] + mv0 : -1e9f;
            float x1 = (d01 >= -WIN_ && d01 <= WIN_) ? s[ni][1] + mv1 : -1e9f;
            float x2 = (d10 >= -WIN_ && d10 <= WIN_) ? s[ni][2] + mv0 : -1e9f;
            float x3 = (d11 >= -WIN_ && d11 <= WIN_) ? s[ni][3] + mv1 : -1e9f;
            s[ni][0] = x0; s[ni][1] = x1; s[ni][2] = x2; s[ni][3] = x3;
            tmax0 = fmaxf(tmax0, fmaxf(x0, x1));
            tmax1 = fmaxf(tmax1, fmaxf(x2, x3));
        }
        tmax0 = fmaxf(tmax0, __shfl_xor_sync(FULL, tmax0, 1));
        tmax0 = fmaxf(tmax0, __shfl_xor_sync(FULL, tmax0, 2));
        tmax1 = fmaxf(tmax1, __shfl_xor_sync(FULL, tmax1, 1));
        tmax1 = fmaxf(tmax1, __shfl_xor_sync(FULL, tmax1, 2));
        float mn0 = fmaxf(m0, tmax0), mn1 = fmaxf(m1, tmax1);
        float sc0 = __expf(m0 - mn0), sc1 = __expf(m1 - mn1);
        float ps0 = 0.f, ps1 = 0.f;
        #pragma unroll
        for (int ni = 0; ni < 8; ni++) {
            s[ni][0] = __expf(s[ni][0] - mn0);
            s[ni][1] = __expf(s[ni][1] - mn0);
            s[ni][2] = __expf(s[ni][2] - mn1);
            s[ni][3] = __expf(s[ni][3] - mn1);
            ps0 += s[ni][0] + s[ni][1];
            ps1 += s[ni][2] + s[ni][3];
        }
        ps0 += __shfl_xor_sync(FULL, ps0, 1);
        ps0 += __shfl_xor_sync(FULL, ps0, 2);
        ps1 += __shfl_xor_sync(FULL, ps1, 1);
        ps1 += __shfl_xor_sync(FULL, ps1, 2);
        l0 = l0 * sc0 + ps0;
        l1 = l1 * sc1 + ps1;
        m0 = mn0; m1 = mn1;
        #pragma unroll
        for (int ni = 0; ni < 8; ni++) {
            o[ni][0] *= sc0; o[ni][1] *= sc0;
            o[ni][2] *= sc1; o[ni][3] *= sc1;
        }

        uint32_t pah[4][4], pal[4][4];
        #pragma unroll
        for (int j = 0; j < 4; j++) {
            packsplit(s[2*j][0],   s[2*j][1],   pah[j][0], pal[j][0]);
            packsplit(s[2*j][2],   s[2*j][3],   pah[j][1], pal[j][1]);
            packsplit(s[2*j+1][0], s[2*j+1][1], pah[j][2], pal[j][2]);
            packsplit(s[2*j+1][2], s[2*j+1][3], pah[j][3], pal[j][3]);
        }

        #pragma unroll
        for (int j = 0; j < 4; j++) {
            uint32_t vbh[8][2], vbl[8][2];
            #pragma unroll
            for (int t = 0; t < 4; t++) {
                uint32_t ad = base + (OVH + (j * 16 + vrow) * QSTR) * 4
                            + (2 * t + vblk) * 16;
                ldsm_x4_t(vbh[2*t][0], vbh[2*t][1], vbh[2*t+1][0], vbh[2*t+1][1], ad);
                ldsm_x4_t(vbl[2*t][0], vbl[2*t][1], vbl[2*t+1][0], vbl[2*t+1][1],
                          ad + (OVL - OVH) * 4);
            }
            #pragma unroll
            for (int ni = 0; ni < 8; ni++)
                mma_bf16(o[ni], pal[j][0], pal[j][1], pal[j][2], pal[j][3],
                         vbh[ni][0], vbh[ni][1]);
            #pragma unroll
            for (int ni = 0; ni < 8; ni++)
                mma_bf16(o[ni], pah[j][0], pah[j][1], pah[j][2], pah[j][3],
                         vbl[ni][0], vbl[ni][1]);
            #pragma unroll
            for (int ni = 0; ni < 8; ni++)
                mma_bf16(o[ni], pah[j][0], pah[j][1], pah[j][2], pah[j][3],
                         vbh[ni][0], vbh[ni][1]);
        }
    }

    float inv0 = 1.f / l0, inv1 = 1.f / l1;
    #pragma unroll
    for (int ni = 0; ni < 8; ni++) {
        int dcol = hh * DH_ + ni * 8 + 2 * tig;
        size_t o0 = (size_t)(b * S_ + qg0) * H_ + dcol;
        size_t o1 = (size_t)(b * S_ + qg1) * H_ + dcol;
        uint32_t ph, pl;
        packsplit(o[ni][0] * inv0, o[ni][1] * inv0, ph, pl);
        *(uint32_t*)(Ohi + o0) = ph;
        *(uint32_t*)(Olo + o0) = pl;
        packsplit(o[ni][2] * inv1, o[ni][3] * inv1, ph, pl);
        *(uint32_t*)(Ohi + o1) = ph;
        *(uint32_t*)(Olo + o1) = pl;
    }
}

// ---------------- pooling head ----------------
__global__ __launch_bounds__(256) void attn_score_kernel(
    const float* __restrict__ h, const float* __restrict__ aw, float* __restrict__ sc)
{
    int t = blockIdx.x;
    int tid = threadIdx.x;
    float acc = 0.f;
    #pragma unroll
    for (int i = 0; i < 3; i++) {
        int c = tid + i * 256;
        acc += h[(size_t)t * H_ + c] * aw[c];
    }
    float s = block_reduce_sum(acc);
    if (tid == 0) sc[t] = s;
}

__global__ __launch_bounds__(256) void softmax_s_kernel(
    const float* __restrict__ sc, float* __restrict__ pr)
{
    int b = blockIdx.x;
    int tid = threadIdx.x;
    float v[4];
    float mx = -1e30f;
    #pragma unroll
    for (int i = 0; i < 4; i++) {
        v[i] = sc[b * S_ + tid + i * 256];
        mx = fmaxf(mx, v[i]);
    }
    mx = block_reduce_max(mx);
    float e[4], ps = 0.f;
    #pragma unroll
    for (int i = 0; i < 4; i++) { e[i] = __expf(v[i] - mx); ps += e[i]; }
    float tot = block_reduce_sum(ps);
    float inv = 1.f / tot;
    #pragma unroll
    for (int i = 0; i < 4; i++) pr[b * S_ + tid + i * 256] = e[i] * inv;
}

__global__ __launch_bounds__(256) void pool_kernel(
    const float* __restrict__ h, const float* __restrict__ pr, float* __restrict__ poolp)
{
    int d = blockIdx.x * 256 + threadIdx.x;
    int b = blockIdx.y;
    int p = blockIdx.z;
    float acc = 0.f;
    int s0 = p * (S_ / 8);
    for (int s = s0; s < s0 + S_ / 8; s++) {
        acc += h[((size_t)(b * S_ + s)) * H_ + d] * pr[b * S_ + s];
    }
    poolp[((size_t)p * B_ + b) * H_ + d] = acc;
}

__global__ __launch_bounds__(256) void final_kernel(
    const float* __restrict__ poolp, const float* __restrict__ Wc,
    const float* __restrict__ bc, float* __restrict__ out)
{
    int b = blockIdx.x;
    int tid = threadIdx.x;
    float acc = 0.f;
    #pragma unroll
    for (int i = 0; i < 3; i++) {
        int c = tid + i * 256;
        float pv = 0.f;
        #pragma unroll
        for (int p = 0; p < 8; p++)
            pv += poolp[((size_t)p * B_ + b) * H_ + c];
        acc += pv * Wc[c];
    }
    float s = block_reduce_sum(acc);
    if (tid == 0) out[b] = s + bc[0];
}

// ---------------- host launcher ----------------
extern "C" void kernel_launch(void* const* d_in, const int* in_sizes, int n_in,
                              void* d_out, int out_size)
{
    (void)in_sizes; (void)n_in; (void)out_size;
    const float* WE   = (const float*)d_in[0];
    const float* PE   = (const float*)d_in[1];
    const float* Eg   = (const float*)d_in[2];
    const float* Eb   = (const float*)d_in[3];
    const float* Wq   = (const float*)d_in[4];
    const float* bq   = (const float*)d_in[5];
    const float* Wk   = (const float*)d_in[6];
    const float* bk   = (const float*)d_in[7];
    const float* Wv   = (const float*)d_in[8];
    const float* bv   = (const float*)d_in[9];
    const float* Wo   = (const float*)d_in[10];
    const float* bo   = (const float*)d_in[11];
    const float* g1   = (const float*)d_in[12];
    const float* beta1= (const float*)d_in[13];
    const float* W1   = (const float*)d_in[14];
    const float* b1   = (const float*)d_in[15];
    const float* W2   = (const float*)d_in[16];
    const float* b2   = (const float*)d_in[17];
    const float* g2   = (const float*)d_in[18];
    const float* beta2= (const float*)d_in[19];
    const float* aw   = (const float*)d_in[20];
    const float* Wc   = (const float*)d_in[21];
    const float* bc   = (const float*)d_in[22];
    const int*   ids  = (const int*)d_in[23];
    const int*   am   = (const int*)d_in[24];
    float* out = (float*)d_out;

    bf16 *wqkv_hi, *wqkv_lo, *wot_hi, *wot_lo, *w1t_hi, *w1t_lo, *w2t_hi, *w2t_lo;
    bf16 *h_hi, *h_lo, *a_hi, *a_lo, *f_hi, *f_lo, *qkvh, *qkvl;
    float *bqkv, *h, *r, *sc, *pr, *poolp;
    cudaGetSymbolAddress((void**)&wqkv_hi, g_wqkv_hi);
    cudaGetSymbolAddress((void**)&wqkv_lo, g_wqkv_lo);
    cudaGetSymbolAddress((void**)&wot_hi,  g_wot_hi);
    cudaGetSymbolAddress((void**)&wot_lo,  g_wot_lo);
    cudaGetSymbolAddress((void**)&w1t_hi,  g_w1t_hi);
    cudaGetSymbolAddress((void**)&w1t_lo,  g_w1t_lo);
    cudaGetSymbolAddress((void**)&w2t_hi,  g_w2t_hi);
    cudaGetSymbolAddress((void**)&w2t_lo,  g_w2t_lo);
    cudaGetSymbolAddress((void**)&bqkv,    g_bqkv);
    cudaGetSymbolAddress((void**)&h,       g_h);
    cudaGetSymbolAddress((void**)&h_hi,    g_h_hi);
    cudaGetSymbolAddress((void**)&h_lo,    g_h_lo);
    cudaGetSymbolAddress((void**)&qkvh,    g_qkvh);
    cudaGetSymbolAddress((void**)&qkvl,    g_qkvl);
    cudaGetSymbolAddress((void**)&a_hi,    g_a_hi);
    cudaGetSymbolAddress((void**)&a_lo,    g_a_lo);
    cudaGetSymbolAddress((void**)&f_hi,    g_f_hi);
    cudaGetSymbolAddress((void**)&f_lo,    g_f_lo);
    cudaGetSymbolAddress((void**)&r,       g_r);
    cudaGetSymbolAddress((void**)&sc,      g_sc);
    cudaGetSymbolAddress((void**)&pr,      g_pr);
    cudaGetSymbolAddress((void**)&poolp,   g_poolp);

    cudaFuncSetAttribute(tgemm_kernel,
                         cudaFuncAttributeMaxDynamicSharedMemorySize, GSMEM);
    cudaFuncSetAttribute(tgemm64_kernel,
                         cudaFuncAttributeMaxDynamicSharedMemorySize, GSMEM64);
    cudaFuncSetAttribute(attn_tc_kernel,
                         cudaFuncAttributeMaxDynamicSharedMemorySize, ATT_SMEM);

    // ---- pre-pass (QKV GEMM at launch idx 3 for ncu) ----
    dim3 wb(256);
    wsplit_qkv_kernel<<<dim3(H_ / 32, H_ / 32, 3 * L_), wb>>>(Wq, Wk, Wv,
                                                              wqkv_hi, wqkv_lo);
    embed_ln_kernel<<<BS_ + L_, 256>>>(WE, PE, Eg, Eb, ids, h, h_hi, h_lo,
                                       bq, bk, bv, bqkv);
    wsplit_kernel<<<dim3(H_ / 32, H_ / 32, L_), wb>>>(Wo, wot_hi, wot_lo, H_, H_,
        (size_t)H_ * H_, (size_t)H_ * H_);

    dim3 gQKV(QKVS / 128, BS_ / 128);   // (18, 32) = 576 CTAs
    dim3 gO64(H_ / 128, BS_ / 64);      // (6, 64)  = 384 CTAs
    dim3 gW1_64(FF_ / 128, BS_ / 64);   // (24, 64) = 1536 CTAs
    dim3 gattn(S_ / 128, NH_, B_);

    // layer 0 QKV GEMM first (launch idx 3), remaining wsplits after it
    tgemm_kernel<<<gQKV, 256, GSMEM>>>(h_hi, h_lo,
        wqkv_hi, wqkv_lo, bqkv, nullptr, qkvh, qkvl, BS_, QKVS, H_, 2);
    wsplit_kernel<<<dim3(FF_ / 32, H_ / 32, L_), wb>>>(W1, w1t_hi, w1t_lo, H_, FF_,
        (size_t)H_ * FF_, (size_t)FF_ * H_);
    wsplit_kernel<<<dim3(H_ / 32, FF_ / 32, L_), wb>>>(W2, w2t_hi, w2t_lo, FF_, H_,
        (size_t)FF_ * H_, (size_t)H_ * FF_);

    for (int l = 0; l < L_; l++) {
        if (l > 0) {
            tgemm_kernel<<<gQKV, 256, GSMEM>>>(h_hi, h_lo,
                wqkv_hi + (size_t)l * QKVS * H_, wqkv_lo + (size_t)l * QKVS * H_,
                bqkv + l * QKVS, nullptr, qkvh, qkvl, BS_, QKVS, H_, 2);
        }

        attn_tc_kernel<<<gattn, 256, ATT_SMEM>>>(qkvh, qkvl, am, a_hi, a_lo);

        tgemm64_kernel<<<gO64, 256, GSMEM64>>>(a_hi, a_lo,
            wot_hi + (size_t)l * H_ * H_, wot_lo + (size_t)l * H_ * H_,
            bo + l * H_, r, nullptr, nullptr, BS_, H_, H_, 0);
        add_ln_kernel<<<BS_, 256>>>(h, r, g1 + l * H_, beta1 + l * H_, h_hi, h_lo);

        tgemm64_kernel<<<gW1_64, 256, GSMEM64>>>(h_hi, h_lo,
            w1t_hi + (size_t)l * FF_ * H_, w1t_lo + (size_t)l * FF_ * H_,
            b1 + l * FF_, nullptr, f_hi, f_lo, BS_, FF_, H_, 1);

        tgemm64_kernel<<<gO64, 256, GSMEM64>>>(f_hi, f_lo,
            w2t_hi + (size_t)l * H_ * FF_, w2t_lo + (size_t)l * H_ * FF_,
            b2 + l * H_, r, nullptr, nullptr, BS_, H_, FF_, 0);
        add_ln_kernel<<<BS_, 256>>>(h, r, g2 + l * H_, beta2 + l * H_, h_hi, h_lo);
    }

    attn_score_kernel<<<BS_, 256>>>(h, aw, sc);
    softmax_s_kernel<<<B_, 256>>>(sc, pr);
    pool_kernel<<<dim3(H_ / 256, B_, 8), 256>>>(h, pr, poolp);
    final_kernel<<<B_, 256>>>(poolp, Wc, bc, out);
}